// round 1
// baseline (speedup 1.0000x reference)
#include <cuda_runtime.h>
#include <cstdint>

// ============================================================================
// Graph_ODE_RNN: 3-level edge-conditioned GCN + pooling + 1x1-conv head
// Layouts are all row-major, matching the JAX reference:
//   x/h      : [B, N, C, T]   (T=200 contiguous)
//   edge_idx : [2, E]  (row0=src, row1=dst)
//   Wk       : [3, Cin, Cout], Wr: [Cin, Cout]
//   P        : [Nout, Nin]
// ============================================================================

#define TT 200

// ---------------- static scratch (no allocation allowed) -------------------
__device__ float g_h1[2 * 2048 * 16 * TT];
__device__ float g_p1[2 * 512 * 16 * TT];
__device__ float g_h2[2 * 512 * 32 * TT];
__device__ float g_p2[2 * 128 * 32 * TT];
__device__ float g_h3[2 * 128 * 64 * TT];
__device__ float g_p3[2 * 64 * 64 * TT];
__device__ float g_hm[2 * 64 * 128 * TT];

__device__ float g_Bw0[16384 * 3];
__device__ float g_We1[16384 * 16];
__device__ float g_Bw1[8192 * 3];
__device__ float g_We2[8192 * 16 * 32];
__device__ float g_Bw2[2048 * 3];
__device__ float g_We3[2048 * 32 * 64];

__device__ int g_deg0[2048], g_off0[2049], g_cur0[2048], g_perm0[16384];
__device__ int g_deg1[512],  g_off1[513],  g_cur1[512],  g_perm1[8192];
__device__ int g_deg2[128],  g_off2[129],  g_cur2[128],  g_perm2[2048];
__device__ float g_inv0[2048], g_inv1[512], g_inv2[128];

// ---------------------------- small utilities ------------------------------
__global__ void zero_int_kernel(int* __restrict__ p, int n) {
    int i = blockIdx.x * blockDim.x + threadIdx.x;
    if (i < n) p[i] = 0;
}

__global__ void count_kernel(const int* __restrict__ dst, int* __restrict__ deg, int E) {
    int e = blockIdx.x * blockDim.x + threadIdx.x;
    if (e < E) atomicAdd(&deg[dst[e]], 1);
}

// Single-block inclusive scan (Hillis-Steele) for N <= 2048.
__global__ void scan_kernel(const int* __restrict__ deg, int* __restrict__ off,
                            int* __restrict__ cursor, float* __restrict__ inv_cnt, int N) {
    __shared__ int sa[2048];
    __shared__ int sb[2048];
    int tid = threadIdx.x;  // 1024 threads
    for (int q = tid; q < 2048; q += 1024) sa[q] = (q < N) ? deg[q] : 0;
    __syncthreads();
    int* cur = sa;
    int* nxt = sb;
    for (int d = 1; d < 2048; d <<= 1) {
        for (int q = tid; q < 2048; q += 1024) {
            int v = cur[q];
            if (q >= d) v += cur[q - d];
            nxt[q] = v;
        }
        __syncthreads();
        int* tmp = cur; cur = nxt; nxt = tmp;
    }
    for (int q = tid; q < 2048; q += 1024) {
        if (q < N) {
            int o = (q == 0) ? 0 : cur[q - 1];
            off[q] = o;
            cursor[q] = o;
            int dg = deg[q];
            inv_cnt[q] = 1.0f / (float)(dg > 0 ? dg : 1);
        }
    }
    if (tid == 0) off[N] = cur[N - 1];
}

__global__ void fill_kernel(const int* __restrict__ dst, int* __restrict__ cursor,
                            int* __restrict__ perm, int E) {
    int e = blockIdx.x * blockDim.x + threadIdx.x;
    if (e < E) {
        int p = atomicAdd(&cursor[dst[e]], 1);
        perm[p] = e;
    }
}

// Deterministic edge order per node: insertion-sort each node's edge list.
__global__ void sort_kernel(const int* __restrict__ off, int* __restrict__ perm, int N) {
    int n = blockIdx.x * blockDim.x + threadIdx.x;
    if (n >= N) return;
    int a = off[n], b = off[n + 1];
    for (int i = a + 1; i < b; i++) {
        int v = perm[i];
        int j = i - 1;
        while (j >= a && perm[j] > v) { perm[j + 1] = perm[j]; j--; }
        perm[j + 1] = v;
    }
}

// Bw = softmax(ea @ A) per edge, ea: [E,3], A: [3,3]
__global__ void bw_kernel(const float* __restrict__ ea, const float* __restrict__ A,
                          float* __restrict__ Bw, int E) {
    int e = blockIdx.x * blockDim.x + threadIdx.x;
    if (e >= E) return;
    float a0 = ea[e * 3 + 0], a1 = ea[e * 3 + 1], a2 = ea[e * 3 + 2];
    float v[3];
#pragma unroll
    for (int j = 0; j < 3; j++)
        v[j] = a0 * A[0 * 3 + j] + a1 * A[1 * 3 + j] + a2 * A[2 * 3 + j];
    float m = fmaxf(v[0], fmaxf(v[1], v[2]));
    float e0 = expf(v[0] - m), e1 = expf(v[1] - m), e2 = expf(v[2] - m);
    float inv = 1.0f / (e0 + e1 + e2);
    Bw[e * 3 + 0] = e0 * inv;
    Bw[e * 3 + 1] = e1 * inv;
    Bw[e * 3 + 2] = e2 * inv;
}

// We[e, q] = sum_k Bw[e,k] * Wk[k, q], q in [0, Cin*Cout)
__global__ void we_kernel(const float* __restrict__ Bw, const float* __restrict__ Wk,
                          float* __restrict__ We, int E, int CC) {
    long idx = (long)blockIdx.x * blockDim.x + threadIdx.x;
    long tot = (long)E * CC;
    if (idx >= tot) return;
    int e = (int)(idx / CC);
    int q = (int)(idx - (long)e * CC);
    float b0 = Bw[e * 3 + 0], b1 = Bw[e * 3 + 1], b2 = Bw[e * 3 + 2];
    We[idx] = b0 * Wk[q] + b1 * Wk[CC + q] + b2 * Wk[2 * CC + q];
}

// ---------------------------- level-1 GCN (Cin=1) --------------------------
// out[b,n,o,t] = elu( mean_e( x[b,src_e,t] * We1[e,o] ) + x[b,n,t]*Wr[o] + bias[o] )
__global__ __launch_bounds__(256)
void gcn1_kernel(const float* __restrict__ x, const float* __restrict__ We1,
                 const float* __restrict__ Wr, const float* __restrict__ bias,
                 const int* __restrict__ srcArr, const int* __restrict__ off,
                 const int* __restrict__ perm, const float* __restrict__ inv_cnt,
                 float* __restrict__ out) {
    __shared__ float xs[2 * TT];
    __shared__ float wes[16];
    __shared__ float wrs[16];
    __shared__ float bbs[16];
    const int N0 = 2048;
    int n = blockIdx.x;
    int tid = threadIdx.x;
    int tx = tid & 31, ty = tid >> 5;  // ty in [0,8)
    if (tid < 16) { wrs[tid] = Wr[tid]; bbs[tid] = bias[tid]; }

    float acc[2][2][7];
#pragma unroll
    for (int b = 0; b < 2; b++)
#pragma unroll
        for (int u = 0; u < 2; u++)
#pragma unroll
            for (int s = 0; s < 7; s++) acc[b][u][s] = 0.0f;

    int e0 = off[n], e1 = off[n + 1];
    for (int ei = e0; ei < e1; ++ei) {
        int e = perm[ei];
        int src = srcArr[e];
        __syncthreads();
        if (tid < 16) wes[tid] = We1[e * 16 + tid];
        for (int q = tid; q < 2 * TT; q += 256) {
            int b = q / TT, t = q - b * TT;
            xs[q] = x[(b * N0 + src) * TT + t];
        }
        __syncthreads();
#pragma unroll
        for (int b = 0; b < 2; b++) {
            float xr[7];
#pragma unroll
            for (int s = 0; s < 7; s++) {
                int t = tx + 32 * s;
                xr[s] = (s < 6 || tx < 8) ? xs[b * TT + (t < TT ? t : 0)] : 0.0f;
            }
#pragma unroll
            for (int u = 0; u < 2; u++) {
                float w = wes[ty + 8 * u];
#pragma unroll
                for (int s = 0; s < 7; s++) acc[b][u][s] += w * xr[s];
            }
        }
    }
    float inv = inv_cnt[n];
    __syncthreads();
    for (int q = tid; q < 2 * TT; q += 256) {
        int b = q / TT, t = q - b * TT;
        xs[q] = x[(b * N0 + n) * TT + t];
    }
    __syncthreads();
#pragma unroll
    for (int b = 0; b < 2; b++) {
#pragma unroll
        for (int u = 0; u < 2; u++) {
            int o = ty + 8 * u;
            float w = wrs[o], bb = bbs[o];
#pragma unroll
            for (int s = 0; s < 7; s++) {
                int t = tx + 32 * s;
                if (t < TT) {
                    float v = acc[b][u][s] * inv + xs[b * TT + t] * w + bb;
                    v = v > 0.0f ? v : expm1f(v);
                    out[((long)(b * N0 + n) * 16 + o) * TT + t] = v;
                }
            }
        }
    }
}

// ------------------------- generic GCN (levels 2,3) ------------------------
template <int CIN, int COUT>
__global__ __launch_bounds__(256)
void gcn_kernel(const float* __restrict__ xin, const float* __restrict__ We,
                const float* __restrict__ Wr, const float* __restrict__ bias,
                const int* __restrict__ srcArr, const int* __restrict__ off,
                const int* __restrict__ perm, const float* __restrict__ inv_cnt,
                float* __restrict__ out, int Nn) {
    __shared__ float xs[CIN * TT];
    __shared__ float we[CIN * COUT];
    __shared__ float wr[CIN * COUT];
    __shared__ float bs[COUT];
    int n = blockIdx.x, b = blockIdx.y;
    int tid = threadIdx.x, tx = tid & 31, ty = tid >> 5;
    constexpr int U = COUT / 8;
    constexpr int S = 7;

    for (int q = tid; q < CIN * COUT; q += 256) wr[q] = Wr[q];
    if (tid < COUT) bs[tid] = bias[tid];

    float acc[U][S];
#pragma unroll
    for (int u = 0; u < U; u++)
#pragma unroll
        for (int s = 0; s < S; s++) acc[u][s] = 0.0f;

    int e0 = off[n], e1 = off[n + 1];
    for (int ei = e0; ei < e1; ++ei) {
        int e = perm[ei];
        int src = srcArr[e];
        __syncthreads();
        const float4* xp = (const float4*)(xin + (long)(b * Nn + src) * (CIN * TT));
        for (int q = tid; q < CIN * TT / 4; q += 256) ((float4*)xs)[q] = xp[q];
        const float4* wp = (const float4*)(We + (long)e * (CIN * COUT));
        for (int q = tid; q < CIN * COUT / 4; q += 256) ((float4*)we)[q] = wp[q];
        __syncthreads();
#pragma unroll 4
        for (int i = 0; i < CIN; i++) {
            float xr[S];
#pragma unroll
            for (int s = 0; s < S; s++) {
                int t = tx + 32 * s;
                xr[s] = (s < 6 || tx < 8) ? xs[i * TT + (t < TT ? t : 0)] : 0.0f;
            }
#pragma unroll
            for (int u = 0; u < U; u++) {
                float w = we[i * COUT + ty + 8 * u];
#pragma unroll
                for (int s = 0; s < S; s++) acc[u][s] += w * xr[s];
            }
        }
    }

    float inv = inv_cnt[n];
#pragma unroll
    for (int u = 0; u < U; u++)
#pragma unroll
        for (int s = 0; s < S; s++) acc[u][s] *= inv;

    // root term: own node's features
    __syncthreads();
    const float4* xp = (const float4*)(xin + (long)(b * Nn + n) * (CIN * TT));
    for (int q = tid; q < CIN * TT / 4; q += 256) ((float4*)xs)[q] = xp[q];
    __syncthreads();
#pragma unroll 4
    for (int i = 0; i < CIN; i++) {
        float xr[S];
#pragma unroll
        for (int s = 0; s < S; s++) {
            int t = tx + 32 * s;
            xr[s] = (s < 6 || tx < 8) ? xs[i * TT + (t < TT ? t : 0)] : 0.0f;
        }
#pragma unroll
        for (int u = 0; u < U; u++) {
            float w = wr[i * COUT + ty + 8 * u];
#pragma unroll
            for (int s = 0; s < S; s++) acc[u][s] += w * xr[s];
        }
    }

    float* op = out + (long)(b * Nn + n) * (COUT * TT);
#pragma unroll
    for (int u = 0; u < U; u++) {
        int o = ty + 8 * u;
        float bb = bs[o];
#pragma unroll
        for (int s = 0; s < S; s++) {
            int t = tx + 32 * s;
            if (t < TT) {
                float v = acc[u][s] + bb;
                v = v > 0.0f ? v : expm1f(v);
                op[o * TT + t] = v;
            }
        }
    }
}

// ------------------------------ pool SGEMM ---------------------------------
// C[z,m,f] = sum_k A[m,k] * B[z,k,f];  A:[M,K], B:[batch,K,N], C:[batch,M,N]
// N must be a multiple of 128, K a multiple of 8 (true for all 3 pools).
__global__ __launch_bounds__(256)
void sgemm_kernel(const float* __restrict__ A, const float* __restrict__ B,
                  float* __restrict__ C, int M, int N, int K) {
    __shared__ float As[8][128];
    __shared__ float Bs[8][128];
    const float* Bp = B + (long)blockIdx.z * K * N;
    float* Cp = C + (long)blockIdx.z * M * N;
    int tid = threadIdx.x;
    int tx = tid % 16, ty = tid / 16;
    int row0 = blockIdx.y * 128, col0 = blockIdx.x * 128;

    float acc[8][8];
#pragma unroll
    for (int i = 0; i < 8; i++)
#pragma unroll
        for (int j = 0; j < 8; j++) acc[i][j] = 0.0f;

    int a_m = tid >> 1;
    int a_k4 = (tid & 1) * 4;
    int b_k = tid >> 5;
    int b_n = (tid & 31) * 4;

    for (int k0 = 0; k0 < K; k0 += 8) {
        float4 av = make_float4(0.f, 0.f, 0.f, 0.f);
        if (row0 + a_m < M) av = *(const float4*)&A[(long)(row0 + a_m) * K + k0 + a_k4];
        float4 bv = *(const float4*)&Bp[(long)(k0 + b_k) * N + col0 + b_n];
        __syncthreads();
        As[a_k4 + 0][a_m] = av.x;
        As[a_k4 + 1][a_m] = av.y;
        As[a_k4 + 2][a_m] = av.z;
        As[a_k4 + 3][a_m] = av.w;
        *(float4*)&Bs[b_k][b_n] = bv;
        __syncthreads();
#pragma unroll
        for (int kk = 0; kk < 8; kk++) {
            float ar[8], br[8];
#pragma unroll
            for (int i = 0; i < 8; i++) ar[i] = As[kk][ty * 8 + i];
#pragma unroll
            for (int j = 0; j < 8; j++) br[j] = Bs[kk][tx * 8 + j];
#pragma unroll
            for (int i = 0; i < 8; i++)
#pragma unroll
                for (int j = 0; j < 8; j++) acc[i][j] += ar[i] * br[j];
        }
    }

#pragma unroll
    for (int i = 0; i < 8; i++) {
        int r = row0 + ty * 8 + i;
        if (r < M) {
#pragma unroll
            for (int j = 0; j < 8; j += 4) {
                float4 v = make_float4(acc[i][j], acc[i][j + 1], acc[i][j + 2], acc[i][j + 3]);
                *(float4*)&Cp[(long)r * N + col0 + tx * 8 + j] = v;
            }
        }
    }
}

// ------------------------- per-node linear (head) ---------------------------
// out[b,n,o,t] = act( sum_c in[b,n,c,t] * W[c, ob+o] + bias[ob+o] )
template <int CIN, int COUT, int ACT>
__global__ __launch_bounds__(256)
void node_linear_kernel(const float* __restrict__ in, const float* __restrict__ W,
                        const float* __restrict__ bias, float* __restrict__ out,
                        int Nn, int totalCout) {
    __shared__ float ws[CIN * COUT];
    __shared__ float bs[COUT];
    int n = blockIdx.x, b = blockIdx.y;
    int ob = blockIdx.z * COUT;
    int tid = threadIdx.x, tx = tid & 31, ty = tid >> 5;
    for (int q = tid; q < CIN * COUT; q += 256) {
        int c = q / COUT, o = q - c * COUT;
        ws[q] = W[c * totalCout + ob + o];
    }
    if (tid < COUT) bs[tid] = bias[ob + tid];
    __syncthreads();

    constexpr int U = COUT / 8;
    constexpr int S = 7;
    float acc[U][S];
#pragma unroll
    for (int u = 0; u < U; u++)
#pragma unroll
        for (int s = 0; s < S; s++) acc[u][s] = 0.0f;

    const float* xp = in + (long)(b * Nn + n) * (CIN * TT);
#pragma unroll 4
    for (int i = 0; i < CIN; i++) {
        float xr[S];
#pragma unroll
        for (int s = 0; s < S; s++) {
            int t = tx + 32 * s;
            xr[s] = (s < 6 || tx < 8) ? xp[i * TT + (t < TT ? t : 0)] : 0.0f;
        }
#pragma unroll
        for (int u = 0; u < U; u++) {
            float w = ws[i * COUT + ty + 8 * u];
#pragma unroll
            for (int s = 0; s < S; s++) acc[u][s] += w * xr[s];
        }
    }

    float* op = out + (long)(b * Nn + n) * ((long)totalCout * TT);
#pragma unroll
    for (int u = 0; u < U; u++) {
        int o = ty + 8 * u;
        float bb = bs[o];
#pragma unroll
        for (int s = 0; s < S; s++) {
            int t = tx + 32 * s;
            if (t < TT) {
                float v = acc[u][s] + bb;
                if (ACT == 0)
                    v = v > 0.0f ? v : expm1f(v);
                else
                    v = tanhf(v);
                op[(long)(ob + o) * TT + t] = v;
            }
        }
    }
}

// -------------------------------- launch ------------------------------------
#define GETSYM(var, sym)                                       \
    do {                                                       \
        void* _p = nullptr;                                    \
        cudaGetSymbolAddress(&_p, sym);                        \
        var = (decltype(var))_p;                               \
    } while (0)

extern "C" void kernel_launch(void* const* d_in, const int* in_sizes, int n_in,
                              void* d_out, int out_size) {
    (void)in_sizes; (void)n_in; (void)out_size;
    const float* x   = (const float*)d_in[0];
    const int*   ei0 = (const int*)d_in[1];
    const float* ea0 = (const float*)d_in[2];
    const int*   ei1 = (const int*)d_in[3];
    const float* ea1 = (const float*)d_in[4];
    const int*   ei2 = (const int*)d_in[5];
    const float* ea2 = (const float*)d_in[6];
    const float* A1  = (const float*)d_in[7];
    const float* Wk1 = (const float*)d_in[8];
    const float* Wr1 = (const float*)d_in[9];
    const float* b1  = (const float*)d_in[10];
    const float* A2  = (const float*)d_in[11];
    const float* Wk2 = (const float*)d_in[12];
    const float* Wr2 = (const float*)d_in[13];
    const float* b2  = (const float*)d_in[14];
    const float* A3  = (const float*)d_in[15];
    const float* Wk3 = (const float*)d_in[16];
    const float* Wr3 = (const float*)d_in[17];
    const float* b3  = (const float*)d_in[18];
    const float* P01 = (const float*)d_in[19];
    const float* P12 = (const float*)d_in[20];
    const float* P23 = (const float*)d_in[21];
    const float* f1w = (const float*)d_in[22];
    const float* f1b = (const float*)d_in[23];
    const float* f2w = (const float*)d_in[24];
    const float* f2b = (const float*)d_in[25];

    const int N0 = 2048, N1 = 512, N2 = 128, N3 = 64;
    const int E0 = 16384, E1 = 8192, E2 = 2048;

    float *h1, *p1, *h2, *p2, *h3, *p3, *hm;
    float *Bw0, *We1, *Bw1, *We2, *Bw2, *We3;
    int *deg0, *off0, *cur0, *perm0;
    int *deg1, *off1, *cur1, *perm1;
    int *deg2, *off2, *cur2, *perm2;
    float *inv0, *inv1, *inv2;
    GETSYM(h1, g_h1); GETSYM(p1, g_p1); GETSYM(h2, g_h2); GETSYM(p2, g_p2);
    GETSYM(h3, g_h3); GETSYM(p3, g_p3); GETSYM(hm, g_hm);
    GETSYM(Bw0, g_Bw0); GETSYM(We1, g_We1);
    GETSYM(Bw1, g_Bw1); GETSYM(We2, g_We2);
    GETSYM(Bw2, g_Bw2); GETSYM(We3, g_We3);
    GETSYM(deg0, g_deg0); GETSYM(off0, g_off0); GETSYM(cur0, g_cur0); GETSYM(perm0, g_perm0);
    GETSYM(deg1, g_deg1); GETSYM(off1, g_off1); GETSYM(cur1, g_cur1); GETSYM(perm1, g_perm1);
    GETSYM(deg2, g_deg2); GETSYM(off2, g_off2); GETSYM(cur2, g_cur2); GETSYM(perm2, g_perm2);
    GETSYM(inv0, g_inv0); GETSYM(inv1, g_inv1); GETSYM(inv2, g_inv2);

    // ---- CSR + edge weights, level 0 ----
    zero_int_kernel<<<(N0 + 255) / 256, 256>>>(deg0, N0);
    count_kernel<<<(E0 + 255) / 256, 256>>>(ei0 + E0, deg0, E0);
    scan_kernel<<<1, 1024>>>(deg0, off0, cur0, inv0, N0);
    fill_kernel<<<(E0 + 255) / 256, 256>>>(ei0 + E0, cur0, perm0, E0);
    sort_kernel<<<(N0 + 127) / 128, 128>>>(off0, perm0, N0);
    bw_kernel<<<(E0 + 255) / 256, 256>>>(ea0, A1, Bw0, E0);
    we_kernel<<<(E0 * 16 + 255) / 256, 256>>>(Bw0, Wk1, We1, E0, 16);

    // ---- level 1 ----
    zero_int_kernel<<<(N1 + 255) / 256, 256>>>(deg1, N1);
    count_kernel<<<(E1 + 255) / 256, 256>>>(ei1 + E1, deg1, E1);
    scan_kernel<<<1, 1024>>>(deg1, off1, cur1, inv1, N1);
    fill_kernel<<<(E1 + 255) / 256, 256>>>(ei1 + E1, cur1, perm1, E1);
    sort_kernel<<<(N1 + 127) / 128, 128>>>(off1, perm1, N1);
    bw_kernel<<<(E1 + 255) / 256, 256>>>(ea1, A2, Bw1, E1);
    we_kernel<<<(E1 * 512 + 255) / 256, 256>>>(Bw1, Wk2, We2, E1, 16 * 32);

    // ---- level 2 ----
    zero_int_kernel<<<(N2 + 255) / 256, 256>>>(deg2, N2);
    count_kernel<<<(E2 + 255) / 256, 256>>>(ei2 + E2, deg2, E2);
    scan_kernel<<<1, 1024>>>(deg2, off2, cur2, inv2, N2);
    fill_kernel<<<(E2 + 255) / 256, 256>>>(ei2 + E2, cur2, perm2, E2);
    sort_kernel<<<(N2 + 127) / 128, 128>>>(off2, perm2, N2);
    bw_kernel<<<(E2 + 255) / 256, 256>>>(ea2, A3, Bw2, E2);
    we_kernel<<<(E2 * 2048 + 255) / 256, 256>>>(Bw2, Wk3, We3, E2, 32 * 64);

    // ---- GCN level 0->1 : x[2,2048,1,200] -> h1[2,2048,16,200] ----
    gcn1_kernel<<<N0, 256>>>(x, We1, Wr1, b1, ei0, off0, perm0, inv0, h1);

    // ---- pool1: p1[b,m,f] = P01 @ h1 ;  M=512, K=2048, F=3200 ----
    sgemm_kernel<<<dim3(3200 / 128, 512 / 128, 2), 256>>>(P01, h1, p1, 512, 3200, 2048);

    // ---- GCN level 1->2 : p1[2,512,16,200] -> h2[2,512,32,200] ----
    gcn_kernel<16, 32><<<dim3(N1, 2), 256>>>(p1, We2, Wr2, b2, ei1, off1, perm1, inv1, h2, N1);

    // ---- pool2: M=128, K=512, F=6400 ----
    sgemm_kernel<<<dim3(6400 / 128, 1, 2), 256>>>(P12, h2, p2, 128, 6400, 512);

    // ---- GCN level 2->3 : p2[2,128,32,200] -> h3[2,128,64,200] ----
    gcn_kernel<32, 64><<<dim3(N2, 2), 256>>>(p2, We3, Wr3, b3, ei2, off2, perm2, inv2, h3, N2);

    // ---- pool3: M=64, K=128, F=12800 ----
    sgemm_kernel<<<dim3(12800 / 128, 1, 2), 256>>>(P23, h3, p3, 64, 12800, 128);

    // ---- head: elu(p3 @ f1w + f1b) -> hm ; tanh(hm @ f2w + f2b) -> out ----
    node_linear_kernel<64, 64, 0><<<dim3(N3, 2, 2), 256>>>(p3, f1w, f1b, hm, N3, 128);
    node_linear_kernel<128, 64, 1><<<dim3(N3, 2, 1), 256>>>(hm, f2w, f2b, (float*)d_out, N3, 64);
}

// round 2
// speedup vs baseline: 1.1372x; 1.1372x over previous
#include <cuda_runtime.h>
#include <cstdint>

// ============================================================================
// Graph_ODE_RNN — gather-first edge-conditioned GCN + pooled SGEMM + head
//   x/h  : [B, N, C, T] row-major (T=200 contiguous)
//   Gl   : [B, N, 3, Cin, T]  (per-basis weighted gather of neighbor features)
//   GCN: out = elu( [G | x] @ [Wk0;Wk1;Wk2;Wr] + bias )  (K = 4*Cin)
// ============================================================================

#define TT 200

// ---------------- static scratch (no allocation allowed) -------------------
__device__ float g_h1[2 * 2048 * 16 * TT];
__device__ float g_p1[2 * 512 * 16 * TT];
__device__ float g_h2[2 * 512 * 32 * TT];
__device__ float g_p2[2 * 128 * 32 * TT];
__device__ float g_h3[2 * 128 * 64 * TT];
__device__ float g_p3[2 * 64 * 64 * TT];
__device__ float g_hm[2 * 64 * 128 * TT];

__device__ float g_G1[2 * 512 * 3 * 16 * TT];
__device__ float g_G2[2 * 128 * 3 * 32 * TT];

__device__ float g_Bw0[16384 * 3];
__device__ float g_Bw1[8192 * 3];
__device__ float g_Bw2[2048 * 3];

__device__ int g_deg0[2048], g_off0[2049], g_cur0[2048], g_perm0[16384];
__device__ int g_deg1[512],  g_off1[513],  g_cur1[512],  g_perm1[8192];
__device__ int g_deg2[128],  g_off2[129],  g_cur2[128],  g_perm2[2048];
__device__ float g_inv0[2048], g_inv1[512], g_inv2[128];

// ---------------------------- CSR build ------------------------------------
__global__ void zero_int_kernel(int* __restrict__ p, int n) {
    int i = blockIdx.x * blockDim.x + threadIdx.x;
    if (i < n) p[i] = 0;
}

__global__ void count_kernel(const int* __restrict__ dst, int* __restrict__ deg, int E) {
    int e = blockIdx.x * blockDim.x + threadIdx.x;
    if (e < E) atomicAdd(&deg[dst[e]], 1);
}

__global__ void scan_kernel(const int* __restrict__ deg, int* __restrict__ off,
                            int* __restrict__ cursor, float* __restrict__ inv_cnt, int N) {
    __shared__ int sa[2048];
    __shared__ int sb[2048];
    int tid = threadIdx.x;  // 1024 threads
    for (int q = tid; q < 2048; q += 1024) sa[q] = (q < N) ? deg[q] : 0;
    __syncthreads();
    int* cur = sa;
    int* nxt = sb;
    for (int d = 1; d < 2048; d <<= 1) {
        for (int q = tid; q < 2048; q += 1024) {
            int v = cur[q];
            if (q >= d) v += cur[q - d];
            nxt[q] = v;
        }
        __syncthreads();
        int* tmp = cur; cur = nxt; nxt = tmp;
    }
    for (int q = tid; q < 2048; q += 1024) {
        if (q < N) {
            int o = (q == 0) ? 0 : cur[q - 1];
            off[q] = o;
            cursor[q] = o;
            int dg = deg[q];
            inv_cnt[q] = 1.0f / (float)(dg > 0 ? dg : 1);
        }
    }
    if (tid == 0) off[N] = cur[N - 1];
}

__global__ void fill_kernel(const int* __restrict__ dst, int* __restrict__ cursor,
                            int* __restrict__ perm, int E) {
    int e = blockIdx.x * blockDim.x + threadIdx.x;
    if (e < E) {
        int p = atomicAdd(&cursor[dst[e]], 1);
        perm[p] = e;
    }
}

// Deterministic edge order per node.
__global__ void sort_kernel(const int* __restrict__ off, int* __restrict__ perm, int N) {
    int n = blockIdx.x * blockDim.x + threadIdx.x;
    if (n >= N) return;
    int a = off[n], b = off[n + 1];
    for (int i = a + 1; i < b; i++) {
        int v = perm[i];
        int j = i - 1;
        while (j >= a && perm[j] > v) { perm[j + 1] = perm[j]; j--; }
        perm[j + 1] = v;
    }
}

// Bw = softmax(ea @ A) per edge
__global__ void bw_kernel(const float* __restrict__ ea, const float* __restrict__ A,
                          float* __restrict__ Bw, int E) {
    int e = blockIdx.x * blockDim.x + threadIdx.x;
    if (e >= E) return;
    float a0 = ea[e * 3 + 0], a1 = ea[e * 3 + 1], a2 = ea[e * 3 + 2];
    float v[3];
#pragma unroll
    for (int j = 0; j < 3; j++)
        v[j] = a0 * A[0 * 3 + j] + a1 * A[1 * 3 + j] + a2 * A[2 * 3 + j];
    float m = fmaxf(v[0], fmaxf(v[1], v[2]));
    float e0 = expf(v[0] - m), e1 = expf(v[1] - m), e2 = expf(v[2] - m);
    float inv = 1.0f / (e0 + e1 + e2);
    Bw[e * 3 + 0] = e0 * inv;
    Bw[e * 3 + 1] = e1 * inv;
    Bw[e * 3 + 2] = e2 * inv;
}

// ---------------------- level-1 GCN fully fused (Cin=1) --------------------
__global__ __launch_bounds__(256)
void gcn1_kernel(const float* __restrict__ x, const float* __restrict__ Bw,
                 const float* __restrict__ Wk, const float* __restrict__ Wr,
                 const float* __restrict__ bias,
                 const int* __restrict__ srcArr, const int* __restrict__ off,
                 const int* __restrict__ perm, const float* __restrict__ inv_cnt,
                 float* __restrict__ out) {
    __shared__ float sW[80];  // Wk[3*16] | Wr[16] | bias[16]
    const int N0 = 2048;
    int n = blockIdx.x, b = blockIdx.y;
    int t = threadIdx.x;
    if (t < 48) sW[t] = Wk[t];
    else if (t < 64) sW[t] = Wr[t - 48];
    else if (t < 80) sW[t] = bias[t - 64];
    __syncthreads();
    if (t >= TT) return;

    float a0 = 0.f, a1 = 0.f, a2 = 0.f;
    int e0 = off[n], e1 = off[n + 1];
    for (int ei = e0; ei < e1; ++ei) {
        int e = perm[ei];
        int src = srcArr[e];
        float v = x[(b * N0 + src) * TT + t];
        a0 += Bw[e * 3 + 0] * v;
        a1 += Bw[e * 3 + 1] * v;
        a2 += Bw[e * 3 + 2] * v;
    }
    float inv = inv_cnt[n];
    a0 *= inv; a1 *= inv; a2 *= inv;
    float xo = x[(b * N0 + n) * TT + t];
    float* op = out + ((long)(b * N0 + n) * 16) * TT + t;
#pragma unroll
    for (int o = 0; o < 16; o++) {
        float v = a0 * sW[o] + a1 * sW[16 + o] + a2 * sW[32 + o] + xo * sW[48 + o] + sW[64 + o];
        v = v > 0.0f ? v : expm1f(v);
        op[(long)o * TT] = v;
    }
}

// ------------------ weighted neighbor gather (levels 2,3) ------------------
// G[b,n,k,c,t] = inv_cnt[n] * sum_{e in in(n)} Bw[e,k] * x[b,src_e,c,t]
template <int CIN>
__global__ __launch_bounds__(256)
void gather_kernel(const float* __restrict__ xin, const float* __restrict__ Bw,
                   const int* __restrict__ srcArr, const int* __restrict__ off,
                   const int* __restrict__ perm, const float* __restrict__ inv_cnt,
                   float* __restrict__ G, int Nn) {
    int n = blockIdx.x, b = blockIdx.y, k = blockIdx.z;
    int tid = threadIdx.x, tx = tid & 31, ty = tid >> 5;
    constexpr int U = CIN / 8;
    float acc[U][7];
#pragma unroll
    for (int u = 0; u < U; u++)
#pragma unroll
        for (int s = 0; s < 7; s++) acc[u][s] = 0.0f;

    int e0 = off[n], e1 = off[n + 1];
    for (int ei = e0; ei < e1; ++ei) {
        int e = perm[ei];
        int src = srcArr[e];
        float w = Bw[e * 3 + k];
        const float* xp = xin + (long)(b * Nn + src) * (CIN * TT);
#pragma unroll
        for (int u = 0; u < U; u++) {
#pragma unroll
            for (int s = 0; s < 7; s++) {
                int t = tx + 32 * s;
                acc[u][s] += w * xp[(ty + 8 * u) * TT + (t < TT ? t : 0)];
            }
        }
    }
    float inv = inv_cnt[n];
    float* gp = G + ((long)(b * Nn + n) * 3 + k) * (CIN * TT);
#pragma unroll
    for (int u = 0; u < U; u++) {
#pragma unroll
        for (int s = 0; s < 7; s++) {
            int t = tx + 32 * s;
            if (t < TT) gp[(ty + 8 * u) * TT + t] = acc[u][s] * inv;
        }
    }
}

// -------- combine: out = elu([G|x] @ [Wk;Wr] + bias), per node, T-split -----
template <int CIN, int COUT>
__global__ __launch_bounds__(256)
void combine_kernel(const float* __restrict__ G, const float* __restrict__ xin,
                    const float* __restrict__ Wk, const float* __restrict__ Wr,
                    const float* __restrict__ bias, float* __restrict__ out, int Nn) {
    constexpr int CC = CIN * COUT;
    __shared__ float sW[4 * CC];
    __shared__ float sb[COUT];
    int n = blockIdx.x, b = blockIdx.y, tz = blockIdx.z;  // tz: T half (100 each)
    int tid = threadIdx.x, tx = tid & 31, ty = tid >> 5;
    for (int q = tid; q < 3 * CC; q += 256) sW[q] = Wk[q];
    for (int q = tid; q < CC; q += 256) sW[3 * CC + q] = Wr[q];
    if (tid < COUT) sb[tid] = bias[tid];
    __syncthreads();

    constexpr int U = COUT / 8;
    float acc[U][4];
#pragma unroll
    for (int u = 0; u < U; u++)
#pragma unroll
        for (int s = 0; s < 4; s++) acc[u][s] = 0.0f;

    const float* gp = G + (long)(b * Nn + n) * (3 * CIN * TT) + tz * 100;
#pragma unroll 4
    for (int j = 0; j < 3 * CIN; j++) {
        float xr[4];
#pragma unroll
        for (int s = 0; s < 4; s++) {
            int t = tx + 32 * s;
            xr[s] = gp[j * TT + (t < 100 ? t : 0)];
        }
#pragma unroll
        for (int u = 0; u < U; u++) {
            float w = sW[j * COUT + ty + 8 * u];
#pragma unroll
            for (int s = 0; s < 4; s++) acc[u][s] += w * xr[s];
        }
    }
    const float* xp = xin + (long)(b * Nn + n) * (CIN * TT) + tz * 100;
#pragma unroll 4
    for (int j = 0; j < CIN; j++) {
        float xr[4];
#pragma unroll
        for (int s = 0; s < 4; s++) {
            int t = tx + 32 * s;
            xr[s] = xp[j * TT + (t < 100 ? t : 0)];
        }
#pragma unroll
        for (int u = 0; u < U; u++) {
            float w = sW[(3 * CIN + j) * COUT + ty + 8 * u];
#pragma unroll
            for (int s = 0; s < 4; s++) acc[u][s] += w * xr[s];
        }
    }

    float* op = out + (long)(b * Nn + n) * (COUT * TT) + tz * 100;
#pragma unroll
    for (int u = 0; u < U; u++) {
        int o = ty + 8 * u;
        float bb = sb[o];
#pragma unroll
        for (int s = 0; s < 4; s++) {
            int t = tx + 32 * s;
            if (t < 100) {
                float v = acc[u][s] + bb;
                v = v > 0.0f ? v : expm1f(v);
                op[o * TT + t] = v;
            }
        }
    }
}

// -------------------- pool SGEMM: 64x128 tile, double-buffered --------------
// C[z,m,f] = sum_k A[m,k]*B[z,k,f]; A:[M,K], B:[batch,K,N], C:[batch,M,N]
// N % 128 == 0, K % 16 == 0.
__global__ __launch_bounds__(256)
void sgemm64_kernel(const float* __restrict__ A, const float* __restrict__ B,
                    float* __restrict__ C, int M, int N, int K) {
    __shared__ float As[2][16][64];
    __shared__ float Bs[2][16][128];
    const float* Bp = B + (long)blockIdx.z * K * N;
    float* Cp = C + (long)blockIdx.z * M * N;
    int tid = threadIdx.x;
    int tx = tid & 15, ty = tid >> 4;      // compute: rows ty*4..+3, cols tx*8..+7
    int row0 = blockIdx.y * 64, col0 = blockIdx.x * 128;

    int a_m = tid >> 2;            // 0..63
    int a_k = (tid & 3) * 4;       // 0,4,8,12
    int b_k = tid >> 4;            // 0..15
    int b_n = (tid & 15) * 8;      // 0..120

    float acc[4][8];
#pragma unroll
    for (int i = 0; i < 4; i++)
#pragma unroll
        for (int j = 0; j < 8; j++) acc[i][j] = 0.0f;

    // prologue: tile 0
    float4 av = make_float4(0.f, 0.f, 0.f, 0.f);
    if (row0 + a_m < M) av = *(const float4*)&A[(long)(row0 + a_m) * K + a_k];
    float4 bv0 = *(const float4*)&Bp[(long)b_k * N + col0 + b_n];
    float4 bv1 = *(const float4*)&Bp[(long)b_k * N + col0 + b_n + 4];
    As[0][a_k + 0][a_m] = av.x;
    As[0][a_k + 1][a_m] = av.y;
    As[0][a_k + 2][a_m] = av.z;
    As[0][a_k + 3][a_m] = av.w;
    *(float4*)&Bs[0][b_k][b_n] = bv0;
    *(float4*)&Bs[0][b_k][b_n + 4] = bv1;
    __syncthreads();

    int buf = 0;
    for (int k0 = 0; k0 < K; k0 += 16) {
        bool hasNext = (k0 + 16) < K;
        float4 nav = make_float4(0.f, 0.f, 0.f, 0.f), nbv0, nbv1;
        if (hasNext) {
            if (row0 + a_m < M)
                nav = *(const float4*)&A[(long)(row0 + a_m) * K + k0 + 16 + a_k];
            nbv0 = *(const float4*)&Bp[(long)(k0 + 16 + b_k) * N + col0 + b_n];
            nbv1 = *(const float4*)&Bp[(long)(k0 + 16 + b_k) * N + col0 + b_n + 4];
        }
#pragma unroll
        for (int kk = 0; kk < 16; kk++) {
            float4 a4 = *(const float4*)&As[buf][kk][ty * 4];
            float4 b4a = *(const float4*)&Bs[buf][kk][tx * 8];
            float4 b4b = *(const float4*)&Bs[buf][kk][tx * 8 + 4];
            float ar[4] = {a4.x, a4.y, a4.z, a4.w};
            float br[8] = {b4a.x, b4a.y, b4a.z, b4a.w, b4b.x, b4b.y, b4b.z, b4b.w};
#pragma unroll
            for (int i = 0; i < 4; i++)
#pragma unroll
                for (int j = 0; j < 8; j++) acc[i][j] += ar[i] * br[j];
        }
        if (hasNext) {
            int nb = buf ^ 1;
            As[nb][a_k + 0][a_m] = nav.x;
            As[nb][a_k + 1][a_m] = nav.y;
            As[nb][a_k + 2][a_m] = nav.z;
            As[nb][a_k + 3][a_m] = nav.w;
            *(float4*)&Bs[nb][b_k][b_n] = nbv0;
            *(float4*)&Bs[nb][b_k][b_n + 4] = nbv1;
            __syncthreads();
            buf = nb;
        }
    }

#pragma unroll
    for (int i = 0; i < 4; i++) {
        int r = row0 + ty * 4 + i;
        if (r < M) {
            *(float4*)&Cp[(long)r * N + col0 + tx * 8] =
                make_float4(acc[i][0], acc[i][1], acc[i][2], acc[i][3]);
            *(float4*)&Cp[(long)r * N + col0 + tx * 8 + 4] =
                make_float4(acc[i][4], acc[i][5], acc[i][6], acc[i][7]);
        }
    }
}

// ----------------------- per-node linear head (T-split) ---------------------
template <int CIN, int COUT, int ACT>
__global__ __launch_bounds__(256)
void linear_kernel(const float* __restrict__ in, const float* __restrict__ W,
                   const float* __restrict__ bias, float* __restrict__ out, int Nn) {
    __shared__ float sW[CIN * COUT];
    __shared__ float sb[COUT];
    int n = blockIdx.x, b = blockIdx.y, tz = blockIdx.z;
    int tid = threadIdx.x, tx = tid & 31, ty = tid >> 5;
    for (int q = tid; q < CIN * COUT; q += 256) sW[q] = W[q];
    if (tid < COUT) sb[tid] = bias[tid];
    __syncthreads();

    constexpr int U = COUT / 8;
    float acc[U][4];
#pragma unroll
    for (int u = 0; u < U; u++)
#pragma unroll
        for (int s = 0; s < 4; s++) acc[u][s] = 0.0f;

    const float* xp = in + (long)(b * Nn + n) * (CIN * TT) + tz * 100;
#pragma unroll 4
    for (int j = 0; j < CIN; j++) {
        float xr[4];
#pragma unroll
        for (int s = 0; s < 4; s++) {
            int t = tx + 32 * s;
            xr[s] = xp[j * TT + (t < 100 ? t : 0)];
        }
#pragma unroll
        for (int u = 0; u < U; u++) {
            float w = sW[j * COUT + ty + 8 * u];
#pragma unroll
            for (int s = 0; s < 4; s++) acc[u][s] += w * xr[s];
        }
    }

    float* op = out + (long)(b * Nn + n) * (COUT * TT) + tz * 100;
#pragma unroll
    for (int u = 0; u < U; u++) {
        int o = ty + 8 * u;
        float bb = sb[o];
#pragma unroll
        for (int s = 0; s < 4; s++) {
            int t = tx + 32 * s;
            if (t < 100) {
                float v = acc[u][s] + bb;
                if (ACT == 0)
                    v = v > 0.0f ? v : expm1f(v);
                else
                    v = tanhf(v);
                op[o * TT + t] = v;
            }
        }
    }
}

// -------------------------------- launch ------------------------------------
#define GETSYM(var, sym)                                       \
    do {                                                       \
        void* _p = nullptr;                                    \
        cudaGetSymbolAddress(&_p, sym);                        \
        var = (decltype(var))_p;                               \
    } while (0)

extern "C" void kernel_launch(void* const* d_in, const int* in_sizes, int n_in,
                              void* d_out, int out_size) {
    (void)in_sizes; (void)n_in; (void)out_size;
    const float* x   = (const float*)d_in[0];
    const int*   ei0 = (const int*)d_in[1];
    const float* ea0 = (const float*)d_in[2];
    const int*   ei1 = (const int*)d_in[3];
    const float* ea1 = (const float*)d_in[4];
    const int*   ei2 = (const int*)d_in[5];
    const float* ea2 = (const float*)d_in[6];
    const float* A1  = (const float*)d_in[7];
    const float* Wk1 = (const float*)d_in[8];
    const float* Wr1 = (const float*)d_in[9];
    const float* b1  = (const float*)d_in[10];
    const float* A2  = (const float*)d_in[11];
    const float* Wk2 = (const float*)d_in[12];
    const float* Wr2 = (const float*)d_in[13];
    const float* b2  = (const float*)d_in[14];
    const float* A3  = (const float*)d_in[15];
    const float* Wk3 = (const float*)d_in[16];
    const float* Wr3 = (const float*)d_in[17];
    const float* b3  = (const float*)d_in[18];
    const float* P01 = (const float*)d_in[19];
    const float* P12 = (const float*)d_in[20];
    const float* P23 = (const float*)d_in[21];
    const float* f1w = (const float*)d_in[22];
    const float* f1b = (const float*)d_in[23];
    const float* f2w = (const float*)d_in[24];
    const float* f2b = (const float*)d_in[25];

    const int N0 = 2048, N1 = 512, N2 = 128, N3 = 64;
    const int E0 = 16384, E1 = 8192, E2 = 2048;

    float *h1, *p1, *h2, *p2, *h3, *p3, *hm, *G1, *G2;
    float *Bw0, *Bw1, *Bw2;
    int *deg0, *off0, *cur0, *perm0;
    int *deg1, *off1, *cur1, *perm1;
    int *deg2, *off2, *cur2, *perm2;
    float *inv0, *inv1, *inv2;
    GETSYM(h1, g_h1); GETSYM(p1, g_p1); GETSYM(h2, g_h2); GETSYM(p2, g_p2);
    GETSYM(h3, g_h3); GETSYM(p3, g_p3); GETSYM(hm, g_hm);
    GETSYM(G1, g_G1); GETSYM(G2, g_G2);
    GETSYM(Bw0, g_Bw0); GETSYM(Bw1, g_Bw1); GETSYM(Bw2, g_Bw2);
    GETSYM(deg0, g_deg0); GETSYM(off0, g_off0); GETSYM(cur0, g_cur0); GETSYM(perm0, g_perm0);
    GETSYM(deg1, g_deg1); GETSYM(off1, g_off1); GETSYM(cur1, g_cur1); GETSYM(perm1, g_perm1);
    GETSYM(deg2, g_deg2); GETSYM(off2, g_off2); GETSYM(cur2, g_cur2); GETSYM(perm2, g_perm2);
    GETSYM(inv0, g_inv0); GETSYM(inv1, g_inv1); GETSYM(inv2, g_inv2);

    // ---- CSR + basis weights (all levels) ----
    zero_int_kernel<<<(N0 + 255) / 256, 256>>>(deg0, N0);
    count_kernel<<<(E0 + 255) / 256, 256>>>(ei0 + E0, deg0, E0);
    scan_kernel<<<1, 1024>>>(deg0, off0, cur0, inv0, N0);
    fill_kernel<<<(E0 + 255) / 256, 256>>>(ei0 + E0, cur0, perm0, E0);
    sort_kernel<<<(N0 + 127) / 128, 128>>>(off0, perm0, N0);
    bw_kernel<<<(E0 + 255) / 256, 256>>>(ea0, A1, Bw0, E0);

    zero_int_kernel<<<(N1 + 255) / 256, 256>>>(deg1, N1);
    count_kernel<<<(E1 + 255) / 256, 256>>>(ei1 + E1, deg1, E1);
    scan_kernel<<<1, 1024>>>(deg1, off1, cur1, inv1, N1);
    fill_kernel<<<(E1 + 255) / 256, 256>>>(ei1 + E1, cur1, perm1, E1);
    sort_kernel<<<(N1 + 127) / 128, 128>>>(off1, perm1, N1);
    bw_kernel<<<(E1 + 255) / 256, 256>>>(ea1, A2, Bw1, E1);

    zero_int_kernel<<<(N2 + 255) / 256, 256>>>(deg2, N2);
    count_kernel<<<(E2 + 255) / 256, 256>>>(ei2 + E2, deg2, E2);
    scan_kernel<<<1, 1024>>>(deg2, off2, cur2, inv2, N2);
    fill_kernel<<<(E2 + 255) / 256, 256>>>(ei2 + E2, cur2, perm2, E2);
    sort_kernel<<<(N2 + 127) / 128, 128>>>(off2, perm2, N2);
    bw_kernel<<<(E2 + 255) / 256, 256>>>(ea2, A3, Bw2, E2);

    // ---- level 0->1 GCN (fused) : x -> h1[2,2048,16,200] ----
    gcn1_kernel<<<dim3(N0, 2), 256>>>(x, Bw0, Wk1, Wr1, b1, ei0, off0, perm0, inv0, h1);

    // ---- pool1: p1 = P01 @ h1 ; M=512, K=2048, F=3200 ----
    sgemm64_kernel<<<dim3(3200 / 128, 512 / 64, 2), 256>>>(P01, h1, p1, 512, 3200, 2048);

    // ---- level 1->2 GCN : gather + combine -> h2[2,512,32,200] ----
    gather_kernel<16><<<dim3(N1, 2, 3), 256>>>(p1, Bw1, ei1, off1, perm1, inv1, G1, N1);
    combine_kernel<16, 32><<<dim3(N1, 2, 2), 256>>>(G1, p1, Wk2, Wr2, b2, h2, N1);

    // ---- pool2: M=128, K=512, F=6400 ----
    sgemm64_kernel<<<dim3(6400 / 128, 2, 2), 256>>>(P12, h2, p2, 128, 6400, 512);

    // ---- level 2->3 GCN : gather + combine -> h3[2,128,64,200] ----
    gather_kernel<32><<<dim3(N2, 2, 3), 256>>>(p2, Bw2, ei2, off2, perm2, inv2, G2, N2);
    combine_kernel<32, 64><<<dim3(N2, 2, 2), 256>>>(G2, p2, Wk3, Wr3, b3, h3, N2);

    // ---- pool3: M=64, K=128, F=12800 ----
    sgemm64_kernel<<<dim3(12800 / 128, 1, 2), 256>>>(P23, h3, p3, 64, 12800, 128);

    // ---- head ----
    linear_kernel<64, 128, 0><<<dim3(N3, 2, 2), 256>>>(p3, f1w, f1b, hm, N3);
    linear_kernel<128, 64, 1><<<dim3(N3, 2, 2), 256>>>(hm, f2w, f2b, (float*)d_out, N3);
}

// round 4
// speedup vs baseline: 2.0257x; 1.7813x over previous
#include <cuda_runtime.h>
#include <cuda_bf16.h>
#include <cstdint>

// ============================================================================
// Graph_ODE_RNN — gather-first GCN + bf16x3 mma.sync pooled GEMM + head
// (tcgen05 unavailable: harness compiles via compute_103 virtual arch)
// ============================================================================

#define TT 200

// ---------------- static scratch (no allocation allowed) -------------------
__device__ float g_h1[2 * 2048 * 16 * TT];
__device__ float g_p1[2 * 512 * 16 * TT];
__device__ float g_h2[2 * 512 * 32 * TT];
__device__ float g_p2[2 * 128 * 32 * TT];
__device__ float g_h3[2 * 128 * 64 * TT];
__device__ float g_p3[2 * 64 * 64 * TT];
__device__ float g_hm[2 * 64 * 128 * TT];

__device__ float g_G1[2 * 512 * 3 * 16 * TT];
__device__ float g_G2[2 * 128 * 3 * 32 * TT];

// bf16 hi/lo operands for tensor-core pools
__device__ __nv_bfloat16 g_A1h[512 * 2048], g_A1l[512 * 2048];
__device__ __nv_bfloat16 g_A2h[128 * 512],  g_A2l[128 * 512];
__device__ __nv_bfloat16 g_A3h[128 * 128],  g_A3l[128 * 128];  // M padded 64->128
__device__ __nv_bfloat16 g_Bh[2 * 3200 * 2048], g_Bl[2 * 3200 * 2048];

__device__ int g_deg0[2048], g_off0[2049], g_cur0[2048], g_perm0[16384];
__device__ int g_deg1[512],  g_off1[513],  g_cur1[512],  g_perm1[8192];
__device__ int g_deg2[128],  g_off2[129],  g_cur2[128],  g_perm2[2048];
__device__ float g_inv0[2048], g_inv1[512], g_inv2[128];

// ---------------------------- helpers ---------------------------------------
__device__ __forceinline__ uint32_t smem_u32(const void* p) {
    uint32_t a;
    asm("{ .reg .u64 t; cvta.to.shared.u64 t, %1; cvt.u32.u64 %0, t; }"
        : "=r"(a) : "l"(p));
    return a;
}

#define SW128(x) ((x) ^ (((x) >> 3) & 0x70))

#define LDM4(r, addr)                                                           \
    asm volatile("ldmatrix.sync.aligned.m8n8.x4.shared.b16 {%0,%1,%2,%3}, [%4];" \
                 : "=r"((r)[0]), "=r"((r)[1]), "=r"((r)[2]), "=r"((r)[3])        \
                 : "r"(addr))

#define LDM2(r, addr)                                                           \
    asm volatile("ldmatrix.sync.aligned.m8n8.x2.shared.b16 {%0,%1}, [%2];"       \
                 : "=r"((r)[0]), "=r"((r)[1]) : "r"(addr))

#define MMA_BF16(c, a, bb)                                                      \
    asm volatile("mma.sync.aligned.m16n8k16.row.col.f32.bf16.bf16.f32 "          \
                 "{%0,%1,%2,%3}, {%4,%5,%6,%7}, {%8,%9}, {%0,%1,%2,%3};"         \
                 : "+f"((c)[0]), "+f"((c)[1]), "+f"((c)[2]), "+f"((c)[3])        \
                 : "r"((a)[0]), "r"((a)[1]), "r"((a)[2]), "r"((a)[3]),           \
                   "r"((bb)[0]), "r"((bb)[1]))

// ---------------------------- CSR build (merged) ----------------------------
__global__ void zero_all_kernel(int* d0, int* d1, int* d2) {
    int i = blockIdx.x * blockDim.x + threadIdx.x;
    if (i < 2048) d0[i] = 0;
    else if (i < 2560) d1[i - 2048] = 0;
    else if (i < 2688) d2[i - 2560] = 0;
}

__global__ void count_all_kernel(const int* e0, const int* e1, const int* e2,
                                 int* d0, int* d1, int* d2) {
    int i = blockIdx.x * blockDim.x + threadIdx.x;
    if (i < 16384) atomicAdd(&d0[e0[16384 + i]], 1);
    else if (i < 24576) atomicAdd(&d1[e1[8192 + (i - 16384)]], 1);
    else if (i < 26624) atomicAdd(&d2[e2[2048 + (i - 24576)]], 1);
}

__global__ void scan_all_kernel(int* d0, int* o0, int* c0, float* v0,
                                int* d1, int* o1, int* c1, float* v1,
                                int* d2, int* o2, int* c2, float* v2) {
    __shared__ int sa[2048];
    __shared__ int sb[2048];
    int lvl = blockIdx.x;
    int* deg = lvl == 0 ? d0 : (lvl == 1 ? d1 : d2);
    int* off = lvl == 0 ? o0 : (lvl == 1 ? o1 : o2);
    int* cur = lvl == 0 ? c0 : (lvl == 1 ? c1 : c2);
    float* inv = lvl == 0 ? v0 : (lvl == 1 ? v1 : v2);
    int N = lvl == 0 ? 2048 : (lvl == 1 ? 512 : 128);
    int tid = threadIdx.x;  // 1024
    for (int q = tid; q < 2048; q += 1024) sa[q] = (q < N) ? deg[q] : 0;
    __syncthreads();
    int *pc = sa, *pn = sb;
    for (int d = 1; d < 2048; d <<= 1) {
        for (int q = tid; q < 2048; q += 1024) {
            int v = pc[q];
            if (q >= d) v += pc[q - d];
            pn[q] = v;
        }
        __syncthreads();
        int* t = pc; pc = pn; pn = t;
    }
    for (int q = tid; q < 2048; q += 1024) {
        if (q < N) {
            int o = (q == 0) ? 0 : pc[q - 1];
            off[q] = o;
            cur[q] = o;
            int dg = deg[q];
            inv[q] = 1.0f / (float)(dg > 0 ? dg : 1);
        }
    }
    if (tid == 0) off[N] = pc[N - 1];
}

__global__ void fill_all_kernel(const int* e0, const int* e1, const int* e2,
                                int* c0, int* c1, int* c2,
                                int* p0, int* p1, int* p2) {
    int i = blockIdx.x * blockDim.x + threadIdx.x;
    if (i < 16384) { int p = atomicAdd(&c0[e0[16384 + i]], 1); p0[p] = i; }
    else if (i < 24576) { int q = i - 16384; int p = atomicAdd(&c1[e1[8192 + q]], 1); p1[p] = q; }
    else if (i < 26624) { int q = i - 24576; int p = atomicAdd(&c2[e2[2048 + q]], 1); p2[p] = q; }
}

__global__ void sort_all_kernel(const int* o0, int* p0, const int* o1, int* p1,
                                const int* o2, int* p2) {
    int i = blockIdx.x * blockDim.x + threadIdx.x;
    const int* off; int* perm; int n;
    if (i < 2048) { off = o0; perm = p0; n = i; }
    else if (i < 2560) { off = o1; perm = p1; n = i - 2048; }
    else if (i < 2688) { off = o2; perm = p2; n = i - 2560; }
    else return;
    int a = off[n], b = off[n + 1];
    for (int k = a + 1; k < b; k++) {
        int v = perm[k];
        int j = k - 1;
        while (j >= a && perm[j] > v) { perm[j + 1] = perm[j]; j--; }
        perm[j + 1] = v;
    }
}

// --------------------- level-1 GCN fused (inline softmax) -------------------
__global__ __launch_bounds__(256)
void gcn1_kernel(const float* __restrict__ x, const float* __restrict__ ea,
                 const float* __restrict__ Amat,
                 const float* __restrict__ Wk, const float* __restrict__ Wr,
                 const float* __restrict__ bias,
                 const int* __restrict__ srcArr, const int* __restrict__ off,
                 const int* __restrict__ perm, const float* __restrict__ inv_cnt,
                 float* __restrict__ out) {
    __shared__ float sA[9];
    __shared__ float sW[80];  // Wk[48] | Wr[16] | bias[16]
    const int N0 = 2048;
    int n = blockIdx.x, b = blockIdx.y;
    int t = threadIdx.x;
    if (t < 9) sA[t] = Amat[t];
    if (t < 48) sW[t] = Wk[t];
    else if (t < 64) sW[t] = Wr[t - 48];
    else if (t < 80) sW[t] = bias[t - 64];
    __syncthreads();
    if (t >= TT) return;

    float a0 = 0.f, a1 = 0.f, a2 = 0.f;
    int e0 = off[n], e1 = off[n + 1];
    for (int ei = e0; ei < e1; ++ei) {
        int e = perm[ei];
        int src = srcArr[e];
        float u0 = ea[e * 3 + 0], u1 = ea[e * 3 + 1], u2 = ea[e * 3 + 2];
        float w0 = u0 * sA[0] + u1 * sA[3] + u2 * sA[6];
        float w1 = u0 * sA[1] + u1 * sA[4] + u2 * sA[7];
        float w2 = u0 * sA[2] + u1 * sA[5] + u2 * sA[8];
        float m = fmaxf(w0, fmaxf(w1, w2));
        float q0 = __expf(w0 - m), q1 = __expf(w1 - m), q2 = __expf(w2 - m);
        float qi = 1.0f / (q0 + q1 + q2);
        float v = x[(b * N0 + src) * TT + t];
        a0 += q0 * qi * v;
        a1 += q1 * qi * v;
        a2 += q2 * qi * v;
    }
    float inv = inv_cnt[n];
    a0 *= inv; a1 *= inv; a2 *= inv;
    float xo = x[(b * N0 + n) * TT + t];
    float* op = out + ((long)(b * N0 + n) * 16) * TT + t;
#pragma unroll
    for (int o = 0; o < 16; o++) {
        float v = a0 * sW[o] + a1 * sW[16 + o] + a2 * sW[32 + o] + xo * sW[48 + o] + sW[64 + o];
        v = v > 0.0f ? v : expm1f(v);
        op[(long)o * TT] = v;
    }
}

// --------- fused neighbor gather (all 3 bases, 16-channel slice) -----------
__global__ __launch_bounds__(256)
void gather_kernel(const float* __restrict__ xin, const float* __restrict__ ea,
                   const float* __restrict__ Amat,
                   const int* __restrict__ srcArr, const int* __restrict__ off,
                   const int* __restrict__ perm, const float* __restrict__ inv_cnt,
                   float* __restrict__ G, int Nn, int CIN) {
    __shared__ float sA[9];
    int n = blockIdx.x, b = blockIdx.y, cz = blockIdx.z;
    int tid = threadIdx.x, tx = tid & 31, ty = tid >> 5;
    if (tid < 9) sA[tid] = Amat[tid];
    __syncthreads();
    int cbase = cz * 16;

    float acc[3][2][7];
#pragma unroll
    for (int k = 0; k < 3; k++)
#pragma unroll
        for (int u = 0; u < 2; u++)
#pragma unroll
            for (int s = 0; s < 7; s++) acc[k][u][s] = 0.0f;

    int e0 = off[n], e1 = off[n + 1];
    for (int ei = e0; ei < e1; ++ei) {
        int e = perm[ei];
        int src = srcArr[e];
        float u0 = ea[e * 3 + 0], u1 = ea[e * 3 + 1], u2 = ea[e * 3 + 2];
        float w0 = u0 * sA[0] + u1 * sA[3] + u2 * sA[6];
        float w1 = u0 * sA[1] + u1 * sA[4] + u2 * sA[7];
        float w2 = u0 * sA[2] + u1 * sA[5] + u2 * sA[8];
        float m = fmaxf(w0, fmaxf(w1, w2));
        float q0 = __expf(w0 - m), q1 = __expf(w1 - m), q2 = __expf(w2 - m);
        float qi = 1.0f / (q0 + q1 + q2);
        q0 *= qi; q1 *= qi; q2 *= qi;
        const float* xp = xin + ((long)(b * Nn + src) * CIN + cbase) * TT;
#pragma unroll
        for (int u = 0; u < 2; u++) {
#pragma unroll
            for (int s = 0; s < 7; s++) {
                int t = tx + 32 * s;
                float v = xp[(ty + 8 * u) * TT + (t < TT ? t : 0)];
                acc[0][u][s] += q0 * v;
                acc[1][u][s] += q1 * v;
                acc[2][u][s] += q2 * v;
            }
        }
    }
    float inv = inv_cnt[n];
#pragma unroll
    for (int k = 0; k < 3; k++) {
        float* gp = G + ((long)(b * Nn + n) * 3 + k) * ((long)CIN * TT);
#pragma unroll
        for (int u = 0; u < 2; u++) {
#pragma unroll
            for (int s = 0; s < 7; s++) {
                int t = tx + 32 * s;
                if (t < TT) gp[(cbase + ty + 8 * u) * TT + t] = acc[k][u][s] * inv;
            }
        }
    }
}

// -------- combine: out = elu([G|x] @ [Wk;Wr] + bias), per node, T-half ------
template <int CIN, int COUT>
__global__ __launch_bounds__(256)
void combine_kernel(const float* __restrict__ G, const float* __restrict__ xin,
                    const float* __restrict__ Wk, const float* __restrict__ Wr,
                    const float* __restrict__ bias, float* __restrict__ out, int Nn) {
    constexpr int CC = CIN * COUT;
    __shared__ float sW[4 * CC];
    __shared__ float sb[COUT];
    int n = blockIdx.x, b = blockIdx.y, tz = blockIdx.z;
    int tid = threadIdx.x, tx = tid & 31, ty = tid >> 5;
    for (int q = tid; q < 3 * CC; q += 256) sW[q] = Wk[q];
    for (int q = tid; q < CC; q += 256) sW[3 * CC + q] = Wr[q];
    if (tid < COUT) sb[tid] = bias[tid];
    __syncthreads();

    constexpr int U = COUT / 8;
    float acc[U][4];
#pragma unroll
    for (int u = 0; u < U; u++)
#pragma unroll
        for (int s = 0; s < 4; s++) acc[u][s] = 0.0f;

    const float* gp = G + (long)(b * Nn + n) * (3 * CIN * TT) + tz * 100;
#pragma unroll 4
    for (int j = 0; j < 3 * CIN; j++) {
        float xr[4];
#pragma unroll
        for (int s = 0; s < 4; s++) {
            int t = tx + 32 * s;
            xr[s] = gp[j * TT + (t < 100 ? t : 0)];
        }
#pragma unroll
        for (int u = 0; u < U; u++) {
            float w = sW[j * COUT + ty + 8 * u];
#pragma unroll
            for (int s = 0; s < 4; s++) acc[u][s] += w * xr[s];
        }
    }
    const float* xp = xin + (long)(b * Nn + n) * (CIN * TT) + tz * 100;
#pragma unroll 4
    for (int j = 0; j < CIN; j++) {
        float xr[4];
#pragma unroll
        for (int s = 0; s < 4; s++) {
            int t = tx + 32 * s;
            xr[s] = xp[j * TT + (t < 100 ? t : 0)];
        }
#pragma unroll
        for (int u = 0; u < U; u++) {
            float w = sW[(3 * CIN + j) * COUT + ty + 8 * u];
#pragma unroll
            for (int s = 0; s < 4; s++) acc[u][s] += w * xr[s];
        }
    }

    float* op = out + (long)(b * Nn + n) * (COUT * TT) + tz * 100;
#pragma unroll
    for (int u = 0; u < U; u++) {
        int o = ty + 8 * u;
        float bb = sb[o];
#pragma unroll
        for (int s = 0; s < 4; s++) {
            int t = tx + 32 * s;
            if (t < 100) {
                float v = acc[u][s] + bb;
                v = v > 0.0f ? v : expm1f(v);
                op[o * TT + t] = v;
            }
        }
    }
}

// ------------- transpose + bf16 hi/lo split: h[b,K,F] -> B[b,F,K] -----------
__global__ __launch_bounds__(256)
void tsplit_kernel(const float* __restrict__ h, __nv_bfloat16* __restrict__ Bh,
                   __nv_bfloat16* __restrict__ Bl, int K, int F) {
    __shared__ float tile[32][33];
    int b = blockIdx.z;
    int k0 = blockIdx.y * 32, f0 = blockIdx.x * 32;
    const float* hp = h + (long)b * K * F;
    int tx = threadIdx.x & 31, ty = threadIdx.x >> 5;  // ty 0..7
#pragma unroll
    for (int i = ty; i < 32; i += 8)
        tile[i][tx] = hp[(long)(k0 + i) * F + f0 + tx];
    __syncthreads();
    __nv_bfloat16* Hp = Bh + (long)b * F * K;
    __nv_bfloat16* Lp = Bl + (long)b * F * K;
#pragma unroll
    for (int i = ty; i < 32; i += 8) {
        float v = tile[tx][i];
        __nv_bfloat16 hi = __float2bfloat16(v);
        float lo = v - __bfloat162float(hi);
        Hp[(long)(f0 + i) * K + k0 + tx] = hi;
        Lp[(long)(f0 + i) * K + k0 + tx] = __float2bfloat16(lo);
    }
}

// ---------------- split all three P matrices into bf16 hi/lo ----------------
__global__ void splitA_kernel(const float* __restrict__ P01, const float* __restrict__ P12,
                              const float* __restrict__ P23,
                              __nv_bfloat16* A1h, __nv_bfloat16* A1l,
                              __nv_bfloat16* A2h, __nv_bfloat16* A2l,
                              __nv_bfloat16* A3h, __nv_bfloat16* A3l) {
    const int S1 = 512 * 2048, S2 = 128 * 512, S3 = 128 * 128;
    int i = blockIdx.x * blockDim.x + threadIdx.x;
    float v; __nv_bfloat16 *H, *L; int o;
    if (i < S1) { o = i; v = P01[o]; H = A1h; L = A1l; }
    else if (i < S1 + S2) { o = i - S1; v = P12[o]; H = A2h; L = A2l; }
    else if (i < S1 + S2 + S3) {
        o = i - S1 - S2;
        int m = o / 128;
        v = (m < 64) ? P23[o] : 0.0f;
        H = A3h; L = A3l;
    } else return;
    __nv_bfloat16 hi = __float2bfloat16(v);
    H[o] = hi;
    L[o] = __float2bfloat16(v - __bfloat162float(hi));
}

// ----------------- bf16x3 GEMM via mma.sync (tensor pipe) -------------------
// C[b,m,f] = sum_k A[m,k] * B[b,f,k]; A:[Mpad,K], B:[batch,F,K], C:[batch,Mout,F]
// Block: 128(M) x 64(F); 8 warps, warp = 64x16 (4x2 m16n8k16 tiles); K chunk 64.
__global__ __launch_bounds__(256)
void mma_gemm_kernel(const __nv_bfloat16* __restrict__ Ahi, const __nv_bfloat16* __restrict__ Alo,
                     const __nv_bfloat16* __restrict__ Bhi, const __nv_bfloat16* __restrict__ Blo,
                     float* __restrict__ C, int Mout, int K, int F) {
    extern __shared__ char smem[];
    const int OFF_AH = 0, OFF_AL = 16384, OFF_BH = 32768, OFF_BL = 40960;
    uint32_t sbase = smem_u32(smem);
    int tid = threadIdx.x, lane = tid & 31, w = tid >> 5;
    int mw = w & 1, fw = w >> 1;  // mw: 64-row half; fw: 16-col group
    int f0 = blockIdx.x * 64, row0 = blockIdx.y * 128, b = blockIdx.z;

    const __nv_bfloat16* Bhp = Bhi + ((long)b * F + f0) * K;
    const __nv_bfloat16* Blp = Blo + ((long)b * F + f0) * K;

    float acc[4][2][4];
#pragma unroll
    for (int mt = 0; mt < 4; mt++)
#pragma unroll
        for (int nt = 0; nt < 2; nt++)
#pragma unroll
            for (int q = 0; q < 4; q++) acc[mt][nt][q] = 0.0f;

    int r = tid >> 3, cb = (tid & 7) * 16;          // staging: row, byte-col
    int aRow = lane & 15, aKb = (lane >> 4) * 16;   // ldmatrix A addressing
    int bRow = lane & 7, bKb = ((lane >> 3) & 1) * 16;

    for (int k0 = 0; k0 < K; k0 += 64) {
#pragma unroll
        for (int i = 0; i < 4; i++) {
            int rr = r + i * 32;
            uint32_t so = SW128(rr * 128 + cb);
            long gi = (long)(row0 + rr) * K + k0 + (cb >> 1);
            *(uint4*)(smem + OFF_AH + so) = *(const uint4*)&Ahi[gi];
            *(uint4*)(smem + OFF_AL + so) = *(const uint4*)&Alo[gi];
        }
#pragma unroll
        for (int i = 0; i < 2; i++) {
            int rr = r + i * 32;
            uint32_t so = SW128(rr * 128 + cb);
            long gi = (long)rr * K + k0 + (cb >> 1);
            *(uint4*)(smem + OFF_BH + so) = *(const uint4*)&Bhp[gi];
            *(uint4*)(smem + OFF_BL + so) = *(const uint4*)&Blp[gi];
        }
        __syncthreads();
#pragma unroll
        for (int ks = 0; ks < 4; ks++) {
            uint32_t ah[4][4], al[4][4], bh[2][2], bl[2][2];
#pragma unroll
            for (int mt = 0; mt < 4; mt++) {
                uint32_t off = SW128((mw * 64 + mt * 16 + aRow) * 128 + ks * 32 + aKb);
                LDM4(ah[mt], sbase + OFF_AH + off);
                LDM4(al[mt], sbase + OFF_AL + off);
            }
#pragma unroll
            for (int nt = 0; nt < 2; nt++) {
                uint32_t off = SW128((fw * 16 + nt * 8 + bRow) * 128 + ks * 32 + bKb);
                LDM2(bh[nt], sbase + OFF_BH + off);
                LDM2(bl[nt], sbase + OFF_BL + off);
            }
#pragma unroll
            for (int mt = 0; mt < 4; mt++) {
#pragma unroll
                for (int nt = 0; nt < 2; nt++) {
                    MMA_BF16(acc[mt][nt], ah[mt], bh[nt]);
                    MMA_BF16(acc[mt][nt], ah[mt], bl[nt]);
                    MMA_BF16(acc[mt][nt], al[mt], bh[nt]);
                }
            }
        }
        __syncthreads();
    }

#pragma unroll
    for (int mt = 0; mt < 4; mt++) {
        int gr = row0 + mw * 64 + mt * 16 + (lane >> 2);
#pragma unroll
        for (int nt = 0; nt < 2; nt++) {
            int gc = f0 + fw * 16 + nt * 8 + (lane & 3) * 2;
            if (gr < Mout)
                *(float2*)&C[((long)b * Mout + gr) * F + gc] =
                    make_float2(acc[mt][nt][0], acc[mt][nt][1]);
            if (gr + 8 < Mout)
                *(float2*)&C[((long)b * Mout + gr + 8) * F + gc] =
                    make_float2(acc[mt][nt][2], acc[mt][nt][3]);
        }
    }
}

// ----------------------- per-node linear head (T-half) ----------------------
template <int CIN, int COUT, int ACT>
__global__ __launch_bounds__(256)
void linear_kernel(const float* __restrict__ in, const float* __restrict__ W,
                   const float* __restrict__ bias, float* __restrict__ out, int Nn) {
    __shared__ float sW[CIN * COUT];
    __shared__ float sb[COUT];
    int n = blockIdx.x, b = blockIdx.y, tz = blockIdx.z;
    int tid = threadIdx.x, tx = tid & 31, ty = tid >> 5;
    for (int q = tid; q < CIN * COUT; q += 256) sW[q] = W[q];
    if (tid < COUT) sb[tid] = bias[tid];
    __syncthreads();

    constexpr int U = COUT / 8;
    float acc[U][4];
#pragma unroll
    for (int u = 0; u < U; u++)
#pragma unroll
        for (int s = 0; s < 4; s++) acc[u][s] = 0.0f;

    const float* xp = in + (long)(b * Nn + n) * (CIN * TT) + tz * 100;
#pragma unroll 4
    for (int j = 0; j < CIN; j++) {
        float xr[4];
#pragma unroll
        for (int s = 0; s < 4; s++) {
            int t = tx + 32 * s;
            xr[s] = xp[j * TT + (t < 100 ? t : 0)];
        }
#pragma unroll
        for (int u = 0; u < U; u++) {
            float w = sW[j * COUT + ty + 8 * u];
#pragma unroll
            for (int s = 0; s < 4; s++) acc[u][s] += w * xr[s];
        }
    }

    float* op = out + (long)(b * Nn + n) * (COUT * TT) + tz * 100;
#pragma unroll
    for (int u = 0; u < U; u++) {
        int o = ty + 8 * u;
        float bb = sb[o];
#pragma unroll
        for (int s = 0; s < 4; s++) {
            int t = tx + 32 * s;
            if (t < 100) {
                float v = acc[u][s] + bb;
                if (ACT == 0)
                    v = v > 0.0f ? v : expm1f(v);
                else
                    v = tanhf(v);
                op[o * TT + t] = v;
            }
        }
    }
}

// -------------------------------- launch ------------------------------------
#define GETSYM(var, sym)                                       \
    do {                                                       \
        void* _p = nullptr;                                    \
        cudaGetSymbolAddress(&_p, sym);                        \
        var = (decltype(var))_p;                               \
    } while (0)

extern "C" void kernel_launch(void* const* d_in, const int* in_sizes, int n_in,
                              void* d_out, int out_size) {
    (void)in_sizes; (void)n_in; (void)out_size;
    const float* x   = (const float*)d_in[0];
    const int*   ei0 = (const int*)d_in[1];
    const float* ea0 = (const float*)d_in[2];
    const int*   ei1 = (const int*)d_in[3];
    const float* ea1 = (const float*)d_in[4];
    const int*   ei2 = (const int*)d_in[5];
    const float* ea2 = (const float*)d_in[6];
    const float* A1  = (const float*)d_in[7];
    const float* Wk1 = (const float*)d_in[8];
    const float* Wr1 = (const float*)d_in[9];
    const float* b1  = (const float*)d_in[10];
    const float* A2  = (const float*)d_in[11];
    const float* Wk2 = (const float*)d_in[12];
    const float* Wr2 = (const float*)d_in[13];
    const float* b2  = (const float*)d_in[14];
    const float* A3  = (const float*)d_in[15];
    const float* Wk3 = (const float*)d_in[16];
    const float* Wr3 = (const float*)d_in[17];
    const float* b3  = (const float*)d_in[18];
    const float* P01 = (const float*)d_in[19];
    const float* P12 = (const float*)d_in[20];
    const float* P23 = (const float*)d_in[21];
    const float* f1w = (const float*)d_in[22];
    const float* f1b = (const float*)d_in[23];
    const float* f2w = (const float*)d_in[24];
    const float* f2b = (const float*)d_in[25];

    const int N0 = 2048, N1 = 512, N2 = 128, N3 = 64;

    float *h1, *p1, *h2, *p2, *h3, *p3, *hm, *G1, *G2;
    __nv_bfloat16 *A1h, *A1l, *A2h, *A2l, *A3h, *A3l, *Bh, *Bl;
    int *deg0, *off0, *cur0, *perm0;
    int *deg1, *off1, *cur1, *perm1;
    int *deg2, *off2, *cur2, *perm2;
    float *inv0, *inv1, *inv2;
    GETSYM(h1, g_h1); GETSYM(p1, g_p1); GETSYM(h2, g_h2); GETSYM(p2, g_p2);
    GETSYM(h3, g_h3); GETSYM(p3, g_p3); GETSYM(hm, g_hm);
    GETSYM(G1, g_G1); GETSYM(G2, g_G2);
    GETSYM(A1h, g_A1h); GETSYM(A1l, g_A1l);
    GETSYM(A2h, g_A2h); GETSYM(A2l, g_A2l);
    GETSYM(A3h, g_A3h); GETSYM(A3l, g_A3l);
    GETSYM(Bh, g_Bh); GETSYM(Bl, g_Bl);
    GETSYM(deg0, g_deg0); GETSYM(off0, g_off0); GETSYM(cur0, g_cur0); GETSYM(perm0, g_perm0);
    GETSYM(deg1, g_deg1); GETSYM(off1, g_off1); GETSYM(cur1, g_cur1); GETSYM(perm1, g_perm1);
    GETSYM(deg2, g_deg2); GETSYM(off2, g_off2); GETSYM(cur2, g_cur2); GETSYM(perm2, g_perm2);
    GETSYM(inv0, g_inv0); GETSYM(inv1, g_inv1); GETSYM(inv2, g_inv2);

    const int SMEM_GEMM = 49152;  // 48KB: within default dynamic smem limit

    // ---- CSR (all 3 levels, merged launches) ----
    zero_all_kernel<<<(2688 + 255) / 256, 256>>>(deg0, deg1, deg2);
    count_all_kernel<<<(26624 + 255) / 256, 256>>>(ei0, ei1, ei2, deg0, deg1, deg2);
    scan_all_kernel<<<3, 1024>>>(deg0, off0, cur0, inv0, deg1, off1, cur1, inv1,
                                 deg2, off2, cur2, inv2);
    fill_all_kernel<<<(26624 + 255) / 256, 256>>>(ei0, ei1, ei2, cur0, cur1, cur2,
                                                  perm0, perm1, perm2);
    sort_all_kernel<<<(2688 + 127) / 128, 128>>>(off0, perm0, off1, perm1, off2, perm2);

    // ---- level 0->1 GCN : x -> h1[2,2048,16,200] ----
    gcn1_kernel<<<dim3(N0, 2), 256>>>(x, ea0, A1, Wk1, Wr1, b1, ei0, off0, perm0, inv0, h1);

    // ---- pool1 (tensor): p1 = P01 @ h1 ; M=512, K=2048, F=3200 ----
    tsplit_kernel<<<dim3(3200 / 32, 2048 / 32, 2), 256>>>(h1, Bh, Bl, 2048, 3200);
    splitA_kernel<<<(512 * 2048 + 128 * 512 + 128 * 128 + 255) / 256, 256>>>(
        P01, P12, P23, A1h, A1l, A2h, A2l, A3h, A3l);
    mma_gemm_kernel<<<dim3(3200 / 64, 512 / 128, 2), 256, SMEM_GEMM>>>(
        A1h, A1l, Bh, Bl, p1, 512, 2048, 3200);

    // ---- level 1->2 GCN ----
    gather_kernel<<<dim3(N1, 2, 1), 256>>>(p1, ea1, A2, ei1, off1, perm1, inv1, G1, N1, 16);
    combine_kernel<16, 32><<<dim3(N1, 2, 2), 256>>>(G1, p1, Wk2, Wr2, b2, h2, N1);

    // ---- pool2 (tensor): M=128, K=512, F=6400 ----
    tsplit_kernel<<<dim3(6400 / 32, 512 / 32, 2), 256>>>(h2, Bh, Bl, 512, 6400);
    mma_gemm_kernel<<<dim3(6400 / 64, 1, 2), 256, SMEM_GEMM>>>(
        A2h, A2l, Bh, Bl, p2, 128, 512, 6400);

    // ---- level 2->3 GCN ----
    gather_kernel<<<dim3(N2, 2, 2), 256>>>(p2, ea2, A3, ei2, off2, perm2, inv2, G2, N2, 32);
    combine_kernel<32, 64><<<dim3(N2, 2, 2), 256>>>(G2, p2, Wk3, Wr3, b3, h3, N2);

    // ---- pool3 (tensor): M=64 (padded 128), K=128, F=12800 ----
    tsplit_kernel<<<dim3(12800 / 32, 128 / 32, 2), 256>>>(h3, Bh, Bl, 128, 12800);
    mma_gemm_kernel<<<dim3(12800 / 64, 1, 2), 256, SMEM_GEMM>>>(
        A3h, A3l, Bh, Bl, p3, 64, 128, 12800);

    // ---- head ----
    linear_kernel<64, 128, 0><<<dim3(N3, 2, 2), 256>>>(p3, f1w, f1b, hm, N3);
    linear_kernel<128, 64, 1><<<dim3(N3, 2, 2), 256>>>(hm, f2w, f2b, (float*)d_out, N3);
}

// round 5
// speedup vs baseline: 2.3599x; 1.1650x over previous
#include <cuda_runtime.h>
#include <cuda_bf16.h>
#include <cstdint>

// ============================================================================
// Graph_ODE_RNN — GCN writes bf16 hi/lo GEMM operands directly;
// pools = cp.async double-buffered bf16x3 mma.sync GEMM (trans-ldmatrix B).
// ============================================================================

#define TT 200

// ---------------- static scratch (no allocation allowed) -------------------
__device__ float g_p1[2 * 512 * 16 * TT];
__device__ float g_p2[2 * 128 * 32 * TT];
__device__ float g_p3[2 * 64 * 64 * TT];
__device__ float g_hm[2 * 64 * 128 * TT];

__device__ float g_G1[2 * 512 * 3 * 16 * TT];
__device__ float g_G2[2 * 128 * 3 * 32 * TT];

// bf16 hi/lo operands for tensor-core pools
__device__ __nv_bfloat16 g_A1h[512 * 2048], g_A1l[512 * 2048];
__device__ __nv_bfloat16 g_A2h[128 * 512],  g_A2l[128 * 512];
__device__ __nv_bfloat16 g_A3h[128 * 128],  g_A3l[128 * 128];  // M padded 64->128
__device__ __nv_bfloat16 g_Bh[2 * 2048 * 3200], g_Bl[2 * 2048 * 3200];

__device__ int g_deg0[2048], g_off0[2049], g_cur0[2048], g_perm0[16384];
__device__ int g_deg1[512],  g_off1[513],  g_cur1[512],  g_perm1[8192];
__device__ int g_deg2[128],  g_off2[129],  g_cur2[128],  g_perm2[2048];
__device__ float g_inv0[2048], g_inv1[512], g_inv2[128];

// ---------------------------- helpers ---------------------------------------
__device__ __forceinline__ uint32_t smem_u32(const void* p) {
    uint32_t a;
    asm("{ .reg .u64 t; cvta.to.shared.u64 t, %1; cvt.u32.u64 %0, t; }"
        : "=r"(a) : "l"(p));
    return a;
}

#define SW128(x) ((x) ^ (((x) >> 3) & 0x70))

#define LDM4(r, addr)                                                            \
    asm volatile("ldmatrix.sync.aligned.m8n8.x4.shared.b16 {%0,%1,%2,%3}, [%4];" \
                 : "=r"((r)[0]), "=r"((r)[1]), "=r"((r)[2]), "=r"((r)[3])        \
                 : "r"(addr))

#define LDM2T(r, addr)                                                           \
    asm volatile("ldmatrix.sync.aligned.m8n8.x2.trans.shared.b16 {%0,%1}, [%2];" \
                 : "=r"((r)[0]), "=r"((r)[1]) : "r"(addr))

#define MMA_BF16(c, a, bb)                                                       \
    asm volatile("mma.sync.aligned.m16n8k16.row.col.f32.bf16.bf16.f32 "          \
                 "{%0,%1,%2,%3}, {%4,%5,%6,%7}, {%8,%9}, {%0,%1,%2,%3};"         \
                 : "+f"((c)[0]), "+f"((c)[1]), "+f"((c)[2]), "+f"((c)[3])        \
                 : "r"((a)[0]), "r"((a)[1]), "r"((a)[2]), "r"((a)[3]),           \
                   "r"((bb)[0]), "r"((bb)[1]))

#define CP16(dst, src)                                                           \
    asm volatile("cp.async.cg.shared.global [%0], [%1], 16;" :: "r"(dst), "l"(src))
#define CP_COMMIT asm volatile("cp.async.commit_group;" ::: "memory")
#define CP_WAIT0  asm volatile("cp.async.wait_group 0;" ::: "memory")

// ---------------------------- CSR build (merged) ----------------------------
__global__ void zero_all_kernel(int* d0, int* d1, int* d2) {
    int i = blockIdx.x * blockDim.x + threadIdx.x;
    if (i < 2048) d0[i] = 0;
    else if (i < 2560) d1[i - 2048] = 0;
    else if (i < 2688) d2[i - 2560] = 0;
}

__global__ void count_all_kernel(const int* e0, const int* e1, const int* e2,
                                 int* d0, int* d1, int* d2) {
    int i = blockIdx.x * blockDim.x + threadIdx.x;
    if (i < 16384) atomicAdd(&d0[e0[16384 + i]], 1);
    else if (i < 24576) atomicAdd(&d1[e1[8192 + (i - 16384)]], 1);
    else if (i < 26624) atomicAdd(&d2[e2[2048 + (i - 24576)]], 1);
}

__global__ void scan_all_kernel(int* d0, int* o0, int* c0, float* v0,
                                int* d1, int* o1, int* c1, float* v1,
                                int* d2, int* o2, int* c2, float* v2) {
    __shared__ int sa[2048];
    __shared__ int sb[2048];
    int lvl = blockIdx.x;
    int* deg = lvl == 0 ? d0 : (lvl == 1 ? d1 : d2);
    int* off = lvl == 0 ? o0 : (lvl == 1 ? o1 : o2);
    int* cur = lvl == 0 ? c0 : (lvl == 1 ? c1 : c2);
    float* inv = lvl == 0 ? v0 : (lvl == 1 ? v1 : v2);
    int N = lvl == 0 ? 2048 : (lvl == 1 ? 512 : 128);
    int tid = threadIdx.x;  // 1024
    for (int q = tid; q < 2048; q += 1024) sa[q] = (q < N) ? deg[q] : 0;
    __syncthreads();
    int *pc = sa, *pn = sb;
    for (int d = 1; d < 2048; d <<= 1) {
        for (int q = tid; q < 2048; q += 1024) {
            int v = pc[q];
            if (q >= d) v += pc[q - d];
            pn[q] = v;
        }
        __syncthreads();
        int* t = pc; pc = pn; pn = t;
    }
    for (int q = tid; q < 2048; q += 1024) {
        if (q < N) {
            int o = (q == 0) ? 0 : pc[q - 1];
            off[q] = o;
            cur[q] = o;
            int dg = deg[q];
            inv[q] = 1.0f / (float)(dg > 0 ? dg : 1);
        }
    }
    if (tid == 0) off[N] = pc[N - 1];
}

__global__ void fill_all_kernel(const int* e0, const int* e1, const int* e2,
                                int* c0, int* c1, int* c2,
                                int* p0, int* p1, int* p2) {
    int i = blockIdx.x * blockDim.x + threadIdx.x;
    if (i < 16384) { int p = atomicAdd(&c0[e0[16384 + i]], 1); p0[p] = i; }
    else if (i < 24576) { int q = i - 16384; int p = atomicAdd(&c1[e1[8192 + q]], 1); p1[p] = q; }
    else if (i < 26624) { int q = i - 24576; int p = atomicAdd(&c2[e2[2048 + q]], 1); p2[p] = q; }
}

__global__ void sort_all_kernel(const int* o0, int* p0, const int* o1, int* p1,
                                const int* o2, int* p2) {
    int i = blockIdx.x * blockDim.x + threadIdx.x;
    const int* off; int* perm; int n;
    if (i < 2048) { off = o0; perm = p0; n = i; }
    else if (i < 2560) { off = o1; perm = p1; n = i - 2048; }
    else if (i < 2688) { off = o2; perm = p2; n = i - 2560; }
    else return;
    int a = off[n], b = off[n + 1];
    for (int k = a + 1; k < b; k++) {
        int v = perm[k];
        int j = k - 1;
        while (j >= a && perm[j] > v) { perm[j + 1] = perm[j]; j--; }
        perm[j + 1] = v;
    }
}

// ------------- level-1 GCN fused; writes bf16 hi/lo GEMM operand -------------
__global__ __launch_bounds__(256)
void gcn1_kernel(const float* __restrict__ x, const float* __restrict__ ea,
                 const float* __restrict__ Amat,
                 const float* __restrict__ Wk, const float* __restrict__ Wr,
                 const float* __restrict__ bias,
                 const int* __restrict__ srcArr, const int* __restrict__ off,
                 const int* __restrict__ perm, const float* __restrict__ inv_cnt,
                 __nv_bfloat16* __restrict__ Bh, __nv_bfloat16* __restrict__ Bl) {
    __shared__ float sA[9];
    __shared__ float sW[80];  // Wk[48] | Wr[16] | bias[16]
    const int N0 = 2048;
    int n = blockIdx.x, b = blockIdx.y;
    int t = threadIdx.x;
    if (t < 9) sA[t] = Amat[t];
    if (t < 48) sW[t] = Wk[t];
    else if (t < 64) sW[t] = Wr[t - 48];
    else if (t < 80) sW[t] = bias[t - 64];
    __syncthreads();
    if (t >= TT) return;

    float a0 = 0.f, a1 = 0.f, a2 = 0.f;
    int e0 = off[n], e1 = off[n + 1];
    for (int ei = e0; ei < e1; ++ei) {
        int e = perm[ei];
        int src = srcArr[e];
        float u0 = ea[e * 3 + 0], u1 = ea[e * 3 + 1], u2 = ea[e * 3 + 2];
        float w0 = u0 * sA[0] + u1 * sA[3] + u2 * sA[6];
        float w1 = u0 * sA[1] + u1 * sA[4] + u2 * sA[7];
        float w2 = u0 * sA[2] + u1 * sA[5] + u2 * sA[8];
        float m = fmaxf(w0, fmaxf(w1, w2));
        float q0 = __expf(w0 - m), q1 = __expf(w1 - m), q2 = __expf(w2 - m);
        float qi = 1.0f / (q0 + q1 + q2);
        float v = x[(b * N0 + src) * TT + t];
        a0 += q0 * qi * v;
        a1 += q1 * qi * v;
        a2 += q2 * qi * v;
    }
    float inv = inv_cnt[n];
    a0 *= inv; a1 *= inv; a2 *= inv;
    float xo = x[(b * N0 + n) * TT + t];
    long base = ((long)(b * N0 + n) * 16) * TT + t;
#pragma unroll
    for (int o = 0; o < 16; o++) {
        float v = a0 * sW[o] + a1 * sW[16 + o] + a2 * sW[32 + o] + xo * sW[48 + o] + sW[64 + o];
        v = v > 0.0f ? v : expm1f(v);
        __nv_bfloat16 hi = __float2bfloat16(v);
        Bh[base + (long)o * TT] = hi;
        Bl[base + (long)o * TT] = __float2bfloat16(v - __bfloat162float(hi));
    }
}

// --------- fused neighbor gather (all 3 bases, 16-channel slice) -----------
__global__ __launch_bounds__(256)
void gather_kernel(const float* __restrict__ xin, const float* __restrict__ ea,
                   const float* __restrict__ Amat,
                   const int* __restrict__ srcArr, const int* __restrict__ off,
                   const int* __restrict__ perm, const float* __restrict__ inv_cnt,
                   float* __restrict__ G, int Nn, int CIN) {
    __shared__ float sA[9];
    int n = blockIdx.x, b = blockIdx.y, cz = blockIdx.z;
    int tid = threadIdx.x, tx = tid & 31, ty = tid >> 5;
    if (tid < 9) sA[tid] = Amat[tid];
    __syncthreads();
    int cbase = cz * 16;

    float acc[3][2][7];
#pragma unroll
    for (int k = 0; k < 3; k++)
#pragma unroll
        for (int u = 0; u < 2; u++)
#pragma unroll
            for (int s = 0; s < 7; s++) acc[k][u][s] = 0.0f;

    int e0 = off[n], e1 = off[n + 1];
    for (int ei = e0; ei < e1; ++ei) {
        int e = perm[ei];
        int src = srcArr[e];
        float u0 = ea[e * 3 + 0], u1 = ea[e * 3 + 1], u2 = ea[e * 3 + 2];
        float w0 = u0 * sA[0] + u1 * sA[3] + u2 * sA[6];
        float w1 = u0 * sA[1] + u1 * sA[4] + u2 * sA[7];
        float w2 = u0 * sA[2] + u1 * sA[5] + u2 * sA[8];
        float m = fmaxf(w0, fmaxf(w1, w2));
        float q0 = __expf(w0 - m), q1 = __expf(w1 - m), q2 = __expf(w2 - m);
        float qi = 1.0f / (q0 + q1 + q2);
        q0 *= qi; q1 *= qi; q2 *= qi;
        const float* xp = xin + ((long)(b * Nn + src) * CIN + cbase) * TT;
#pragma unroll
        for (int u = 0; u < 2; u++) {
#pragma unroll
            for (int s = 0; s < 7; s++) {
                int t = tx + 32 * s;
                float v = xp[(ty + 8 * u) * TT + (t < TT ? t : 0)];
                acc[0][u][s] += q0 * v;
                acc[1][u][s] += q1 * v;
                acc[2][u][s] += q2 * v;
            }
        }
    }
    float inv = inv_cnt[n];
#pragma unroll
    for (int k = 0; k < 3; k++) {
        float* gp = G + ((long)(b * Nn + n) * 3 + k) * ((long)CIN * TT);
#pragma unroll
        for (int u = 0; u < 2; u++) {
#pragma unroll
            for (int s = 0; s < 7; s++) {
                int t = tx + 32 * s;
                if (t < TT) gp[(cbase + ty + 8 * u) * TT + t] = acc[k][u][s] * inv;
            }
        }
    }
}

// ---- combine: out = elu([G|x]@[Wk;Wr]+bias); writes bf16 hi/lo operand -----
template <int CIN, int COUT>
__global__ __launch_bounds__(256)
void combine_kernel(const float* __restrict__ G, const float* __restrict__ xin,
                    const float* __restrict__ Wk, const float* __restrict__ Wr,
                    const float* __restrict__ bias,
                    __nv_bfloat16* __restrict__ Bh, __nv_bfloat16* __restrict__ Bl, int Nn) {
    constexpr int CC = CIN * COUT;
    __shared__ float sW[4 * CC];
    __shared__ float sb[COUT];
    int n = blockIdx.x, b = blockIdx.y, tz = blockIdx.z;
    int tid = threadIdx.x, tx = tid & 31, ty = tid >> 5;
    for (int q = tid; q < 3 * CC; q += 256) sW[q] = Wk[q];
    for (int q = tid; q < CC; q += 256) sW[3 * CC + q] = Wr[q];
    if (tid < COUT) sb[tid] = bias[tid];
    __syncthreads();

    constexpr int U = COUT / 8;
    float acc[U][4];
#pragma unroll
    for (int u = 0; u < U; u++)
#pragma unroll
        for (int s = 0; s < 4; s++) acc[u][s] = 0.0f;

    const float* gp = G + (long)(b * Nn + n) * (3 * CIN * TT) + tz * 100;
#pragma unroll 4
    for (int j = 0; j < 3 * CIN; j++) {
        float xr[4];
#pragma unroll
        for (int s = 0; s < 4; s++) {
            int t = tx + 32 * s;
            xr[s] = gp[j * TT + (t < 100 ? t : 0)];
        }
#pragma unroll
        for (int u = 0; u < U; u++) {
            float w = sW[j * COUT + ty + 8 * u];
#pragma unroll
            for (int s = 0; s < 4; s++) acc[u][s] += w * xr[s];
        }
    }
    const float* xp = xin + (long)(b * Nn + n) * (CIN * TT) + tz * 100;
#pragma unroll 4
    for (int j = 0; j < CIN; j++) {
        float xr[4];
#pragma unroll
        for (int s = 0; s < 4; s++) {
            int t = tx + 32 * s;
            xr[s] = xp[j * TT + (t < 100 ? t : 0)];
        }
#pragma unroll
        for (int u = 0; u < U; u++) {
            float w = sW[(3 * CIN + j) * COUT + ty + 8 * u];
#pragma unroll
            for (int s = 0; s < 4; s++) acc[u][s] += w * xr[s];
        }
    }

    long obase = (long)(b * Nn + n) * (COUT * TT) + tz * 100;
#pragma unroll
    for (int u = 0; u < U; u++) {
        int o = ty + 8 * u;
        float bb = sb[o];
#pragma unroll
        for (int s = 0; s < 4; s++) {
            int t = tx + 32 * s;
            if (t < 100) {
                float v = acc[u][s] + bb;
                v = v > 0.0f ? v : expm1f(v);
                __nv_bfloat16 hi = __float2bfloat16(v);
                Bh[obase + o * TT + t] = hi;
                Bl[obase + o * TT + t] = __float2bfloat16(v - __bfloat162float(hi));
            }
        }
    }
}

// ---------------- split all three P matrices into bf16 hi/lo ----------------
__global__ void splitA_kernel(const float* __restrict__ P01, const float* __restrict__ P12,
                              const float* __restrict__ P23,
                              __nv_bfloat16* A1h, __nv_bfloat16* A1l,
                              __nv_bfloat16* A2h, __nv_bfloat16* A2l,
                              __nv_bfloat16* A3h, __nv_bfloat16* A3l) {
    const int S1 = 512 * 2048, S2 = 128 * 512, S3 = 128 * 128;
    int i = blockIdx.x * blockDim.x + threadIdx.x;
    float v; __nv_bfloat16 *H, *L; int o;
    if (i < S1) { o = i; v = P01[o]; H = A1h; L = A1l; }
    else if (i < S1 + S2) { o = i - S1; v = P12[o]; H = A2h; L = A2l; }
    else if (i < S1 + S2 + S3) {
        o = i - S1 - S2;
        int m = o / 128;
        v = (m < 64) ? P23[o] : 0.0f;
        H = A3h; L = A3l;
    } else return;
    __nv_bfloat16 hi = __float2bfloat16(v);
    H[o] = hi;
    L[o] = __float2bfloat16(v - __bfloat162float(hi));
}

// ------- bf16x3 GEMM, cp.async double-buffered, B read via trans-ldmatrix ----
// C[b,m,f] = sum_k A[m,k] * B[b,k,f]; A:[Mpad,K], B:[batch,K,F], C:[batch,Mout,F]
// Block: 128(M) x 64(F); 8 warps; K chunk 64. K % 64 == 0, F % 64 == 0.
__global__ __launch_bounds__(256)
void mma_gemm_kernel(const __nv_bfloat16* __restrict__ Ahi, const __nv_bfloat16* __restrict__ Alo,
                     const __nv_bfloat16* __restrict__ Bhi, const __nv_bfloat16* __restrict__ Blo,
                     float* __restrict__ C, int Mout, int K, int F) {
    extern __shared__ char smem[];
    const int BUF = 49152;
    const int OFF_AH = 0, OFF_AL = 16384, OFF_BH = 32768, OFF_BL = 40960;
    uint32_t sbase = smem_u32(smem);
    int tid = threadIdx.x, lane = tid & 31, w = tid >> 5;
    int mw = w & 1, fw = w >> 1;  // mw: 64-row half; fw: 16-col group
    int f0 = blockIdx.x * 64, row0 = blockIdx.y * 128, b = blockIdx.z;

    const __nv_bfloat16* BhB = Bhi + (long)b * K * F;
    const __nv_bfloat16* BlB = Blo + (long)b * K * F;

    float acc[4][2][4];
#pragma unroll
    for (int mt = 0; mt < 4; mt++)
#pragma unroll
        for (int nt = 0; nt < 2; nt++)
#pragma unroll
            for (int q = 0; q < 4; q++) acc[mt][nt][q] = 0.0f;

    int r = tid >> 3, cb = (tid & 7) * 16;  // staging: row, byte offset in 128B row
    int nchunk = K >> 6;

#define STAGE(bo, k0)                                                              \
    do {                                                                           \
        _Pragma("unroll")                                                          \
        for (int i = 0; i < 4; i++) {                                              \
            int rr = r + i * 32;                                                   \
            uint32_t so = SW128(rr * 128 + cb);                                    \
            CP16(sbase + (bo) + OFF_AH + so,                                       \
                 (const char*)&Ahi[(long)(row0 + rr) * K + (k0) + (cb >> 1)]);     \
            CP16(sbase + (bo) + OFF_AL + so,                                       \
                 (const char*)&Alo[(long)(row0 + rr) * K + (k0) + (cb >> 1)]);     \
        }                                                                          \
        _Pragma("unroll")                                                          \
        for (int i = 0; i < 2; i++) {                                              \
            int rr = r + i * 32;                                                   \
            uint32_t so = SW128(rr * 128 + cb);                                    \
            long gi = (long)((k0) + rr) * F + f0 + (cb >> 1);                      \
            CP16(sbase + (bo) + OFF_BH + so, (const char*)&BhB[gi]);               \
            CP16(sbase + (bo) + OFF_BL + so, (const char*)&BlB[gi]);               \
        }                                                                          \
    } while (0)

    STAGE(0, 0);
    CP_COMMIT;

    int buf = 0;
    for (int kc = 0; kc < nchunk; kc++) {
        CP_WAIT0;
        __syncthreads();
        if (kc + 1 < nchunk) {
            STAGE((buf ^ 1) * BUF, (kc + 1) << 6);
            CP_COMMIT;
        }
        int bo = buf * BUF;
#pragma unroll
        for (int ks = 0; ks < 4; ks++) {
            uint32_t ah[4][4], al[4][4], bh[2][2], bl[2][2];
#pragma unroll
            for (int mt = 0; mt < 4; mt++) {
                uint32_t off = SW128((mw * 64 + mt * 16 + (lane & 15)) * 128 +
                                     ks * 32 + (lane >> 4) * 16);
                LDM4(ah[mt], sbase + bo + OFF_AH + off);
                LDM4(al[mt], sbase + bo + OFF_AL + off);
            }
#pragma unroll
            for (int nt = 0; nt < 2; nt++) {
                uint32_t off = SW128((ks * 16 + (lane & 15)) * 128 + fw * 32 + nt * 16);
                LDM2T(bh[nt], sbase + bo + OFF_BH + off);
                LDM2T(bl[nt], sbase + bo + OFF_BL + off);
            }
#pragma unroll
            for (int mt = 0; mt < 4; mt++) {
#pragma unroll
                for (int nt = 0; nt < 2; nt++) {
                    MMA_BF16(acc[mt][nt], ah[mt], bh[nt]);
                    MMA_BF16(acc[mt][nt], ah[mt], bl[nt]);
                    MMA_BF16(acc[mt][nt], al[mt], bh[nt]);
                }
            }
        }
        __syncthreads();
        buf ^= 1;
    }
#undef STAGE

#pragma unroll
    for (int mt = 0; mt < 4; mt++) {
        int gr = row0 + mw * 64 + mt * 16 + (lane >> 2);
#pragma unroll
        for (int nt = 0; nt < 2; nt++) {
            int gc = f0 + fw * 16 + nt * 8 + (lane & 3) * 2;
            if (gr < Mout)
                *(float2*)&C[((long)b * Mout + gr) * F + gc] =
                    make_float2(acc[mt][nt][0], acc[mt][nt][1]);
            if (gr + 8 < Mout)
                *(float2*)&C[((long)b * Mout + gr + 8) * F + gc] =
                    make_float2(acc[mt][nt][2], acc[mt][nt][3]);
        }
    }
}

// ----------------------- per-node linear head (T-half) ----------------------
template <int CIN, int COUT, int ACT>
__global__ __launch_bounds__(256)
void linear_kernel(const float* __restrict__ in, const float* __restrict__ W,
                   const float* __restrict__ bias, float* __restrict__ out, int Nn) {
    __shared__ float sW[CIN * COUT];
    __shared__ float sb[COUT];
    int n = blockIdx.x, b = blockIdx.y, tz = blockIdx.z;
    int tid = threadIdx.x, tx = tid & 31, ty = tid >> 5;
    for (int q = tid; q < CIN * COUT; q += 256) sW[q] = W[q];
    if (tid < COUT) sb[tid] = bias[tid];
    __syncthreads();

    constexpr int U = COUT / 8;
    float acc[U][4];
#pragma unroll
    for (int u = 0; u < U; u++)
#pragma unroll
        for (int s = 0; s < 4; s++) acc[u][s] = 0.0f;

    const float* xp = in + (long)(b * Nn + n) * (CIN * TT) + tz * 100;
#pragma unroll 4
    for (int j = 0; j < CIN; j++) {
        float xr[4];
#pragma unroll
        for (int s = 0; s < 4; s++) {
            int t = tx + 32 * s;
            xr[s] = xp[j * TT + (t < 100 ? t : 0)];
        }
#pragma unroll
        for (int u = 0; u < U; u++) {
            float w = sW[j * COUT + ty + 8 * u];
#pragma unroll
            for (int s = 0; s < 4; s++) acc[u][s] += w * xr[s];
        }
    }

    float* op = out + (long)(b * Nn + n) * (COUT * TT) + tz * 100;
#pragma unroll
    for (int u = 0; u < U; u++) {
        int o = ty + 8 * u;
        float bb = sb[o];
#pragma unroll
        for (int s = 0; s < 4; s++) {
            int t = tx + 32 * s;
            if (t < 100) {
                float v = acc[u][s] + bb;
                if (ACT == 0)
                    v = v > 0.0f ? v : expm1f(v);
                else
                    v = tanhf(v);
                op[o * TT + t] = v;
            }
        }
    }
}

// -------------------------------- launch ------------------------------------
#define GETSYM(var, sym)                                       \
    do {                                                       \
        void* _p = nullptr;                                    \
        cudaGetSymbolAddress(&_p, sym);                        \
        var = (decltype(var))_p;                               \
    } while (0)

extern "C" void kernel_launch(void* const* d_in, const int* in_sizes, int n_in,
                              void* d_out, int out_size) {
    (void)in_sizes; (void)n_in; (void)out_size;
    const float* x   = (const float*)d_in[0];
    const int*   ei0 = (const int*)d_in[1];
    const float* ea0 = (const float*)d_in[2];
    const int*   ei1 = (const int*)d_in[3];
    const float* ea1 = (const float*)d_in[4];
    const int*   ei2 = (const int*)d_in[5];
    const float* ea2 = (const float*)d_in[6];
    const float* A1  = (const float*)d_in[7];
    const float* Wk1 = (const float*)d_in[8];
    const float* Wr1 = (const float*)d_in[9];
    const float* b1  = (const float*)d_in[10];
    const float* A2  = (const float*)d_in[11];
    const float* Wk2 = (const float*)d_in[12];
    const float* Wr2 = (const float*)d_in[13];
    const float* b2  = (const float*)d_in[14];
    const float* A3  = (const float*)d_in[15];
    const float* Wk3 = (const float*)d_in[16];
    const float* Wr3 = (const float*)d_in[17];
    const float* b3  = (const float*)d_in[18];
    const float* P01 = (const float*)d_in[19];
    const float* P12 = (const float*)d_in[20];
    const float* P23 = (const float*)d_in[21];
    const float* f1w = (const float*)d_in[22];
    const float* f1b = (const float*)d_in[23];
    const float* f2w = (const float*)d_in[24];
    const float* f2b = (const float*)d_in[25];

    const int N0 = 2048, N1 = 512, N2 = 128, N3 = 64;

    float *p1, *p2, *p3, *hm, *G1, *G2;
    __nv_bfloat16 *A1h, *A1l, *A2h, *A2l, *A3h, *A3l, *Bh, *Bl;
    int *deg0, *off0, *cur0, *perm0;
    int *deg1, *off1, *cur1, *perm1;
    int *deg2, *off2, *cur2, *perm2;
    float *inv0, *inv1, *inv2;
    GETSYM(p1, g_p1); GETSYM(p2, g_p2); GETSYM(p3, g_p3); GETSYM(hm, g_hm);
    GETSYM(G1, g_G1); GETSYM(G2, g_G2);
    GETSYM(A1h, g_A1h); GETSYM(A1l, g_A1l);
    GETSYM(A2h, g_A2h); GETSYM(A2l, g_A2l);
    GETSYM(A3h, g_A3h); GETSYM(A3l, g_A3l);
    GETSYM(Bh, g_Bh); GETSYM(Bl, g_Bl);
    GETSYM(deg0, g_deg0); GETSYM(off0, g_off0); GETSYM(cur0, g_cur0); GETSYM(perm0, g_perm0);
    GETSYM(deg1, g_deg1); GETSYM(off1, g_off1); GETSYM(cur1, g_cur1); GETSYM(perm1, g_perm1);
    GETSYM(deg2, g_deg2); GETSYM(off2, g_off2); GETSYM(cur2, g_cur2); GETSYM(perm2, g_perm2);
    GETSYM(inv0, g_inv0); GETSYM(inv1, g_inv1); GETSYM(inv2, g_inv2);

    const int SMEM_GEMM = 98304;  // 2 x 48KB double buffer
    cudaFuncSetAttribute(mma_gemm_kernel, cudaFuncAttributeMaxDynamicSharedMemorySize,
                         SMEM_GEMM);

    // ---- CSR (all 3 levels, merged launches) ----
    zero_all_kernel<<<(2688 + 255) / 256, 256>>>(deg0, deg1, deg2);
    count_all_kernel<<<(26624 + 255) / 256, 256>>>(ei0, ei1, ei2, deg0, deg1, deg2);
    scan_all_kernel<<<3, 1024>>>(deg0, off0, cur0, inv0, deg1, off1, cur1, inv1,
                                 deg2, off2, cur2, inv2);
    fill_all_kernel<<<(26624 + 255) / 256, 256>>>(ei0, ei1, ei2, cur0, cur1, cur2,
                                                  perm0, perm1, perm2);
    sort_all_kernel<<<(2688 + 127) / 128, 128>>>(off0, perm0, off1, perm1, off2, perm2);

    // ---- P matrices -> bf16 hi/lo (A operands) ----
    splitA_kernel<<<(512 * 2048 + 128 * 512 + 128 * 128 + 255) / 256, 256>>>(
        P01, P12, P23, A1h, A1l, A2h, A2l, A3h, A3l);

    // ---- level 0->1 GCN : x -> B operand (bf16 hi/lo, [b,n,16*200]) ----
    gcn1_kernel<<<dim3(N0, 2), 256>>>(x, ea0, A1, Wk1, Wr1, b1, ei0, off0, perm0, inv0,
                                      Bh, Bl);

    // ---- pool1: p1 = P01 @ h1 ; M=512, K=2048, F=3200 ----
    mma_gemm_kernel<<<dim3(3200 / 64, 512 / 128, 2), 256, SMEM_GEMM>>>(
        A1h, A1l, Bh, Bl, p1, 512, 2048, 3200);

    // ---- level 1->2 GCN ----
    gather_kernel<<<dim3(N1, 2, 1), 256>>>(p1, ea1, A2, ei1, off1, perm1, inv1, G1, N1, 16);
    combine_kernel<16, 32><<<dim3(N1, 2, 2), 256>>>(G1, p1, Wk2, Wr2, b2, Bh, Bl, N1);

    // ---- pool2: M=128, K=512, F=6400 ----
    mma_gemm_kernel<<<dim3(6400 / 64, 1, 2), 256, SMEM_GEMM>>>(
        A2h, A2l, Bh, Bl, p2, 128, 512, 6400);

    // ---- level 2->3 GCN ----
    gather_kernel<<<dim3(N2, 2, 2), 256>>>(p2, ea2, A3, ei2, off2, perm2, inv2, G2, N2, 32);
    combine_kernel<32, 64><<<dim3(N2, 2, 2), 256>>>(G2, p2, Wk3, Wr3, b3, Bh, Bl, N2);

    // ---- pool3: M=64 (padded 128), K=128, F=12800 ----
    mma_gemm_kernel<<<dim3(12800 / 64, 1, 2), 256, SMEM_GEMM>>>(
        A3h, A3l, Bh, Bl, p3, 64, 128, 12800);

    // ---- head ----
    linear_kernel<64, 128, 0><<<dim3(N3, 2, 2), 256>>>(p3, f1w, f1b, hm, N3);
    linear_kernel<128, 64, 1><<<dim3(N3, 2, 2), 256>>>(hm, f2w, f2b, (float*)d_out, N3);
}

// round 6
// speedup vs baseline: 2.9813x; 1.2633x over previous
#include <cuda_runtime.h>
#include <cuda_bf16.h>
#include <cstdint>

// ============================================================================
// Graph_ODE_RNN — fused GCN (smem-staged gather+combine, bf16 hi/lo output)
// + cp.async double-buffered bf16x3 mma.sync pooled GEMM + head.
// ============================================================================

#define TT 200

// ---------------- static scratch (no allocation allowed) -------------------
__device__ float g_p1[2 * 512 * 16 * TT];
__device__ float g_p2[2 * 128 * 32 * TT];
__device__ float g_p3[2 * 64 * 64 * TT];
__device__ float g_hm[2 * 64 * 128 * TT];

// bf16 hi/lo operands for tensor-core pools
__device__ __nv_bfloat16 g_A1h[512 * 2048], g_A1l[512 * 2048];
__device__ __nv_bfloat16 g_A2h[128 * 512],  g_A2l[128 * 512];
__device__ __nv_bfloat16 g_A3h[128 * 128],  g_A3l[128 * 128];  // M padded 64->128
__device__ __nv_bfloat16 g_Bh[2 * 2048 * 3200], g_Bl[2 * 2048 * 3200];

__device__ int g_deg0[2048], g_off0[2049], g_cur0[2048], g_perm0[16384];
__device__ int g_deg1[512],  g_off1[513],  g_cur1[512],  g_perm1[8192];
__device__ int g_deg2[128],  g_off2[129],  g_cur2[128],  g_perm2[2048];
__device__ float g_inv0[2048], g_inv1[512], g_inv2[128];

// ---------------------------- helpers ---------------------------------------
__device__ __forceinline__ uint32_t smem_u32(const void* p) {
    uint32_t a;
    asm("{ .reg .u64 t; cvta.to.shared.u64 t, %1; cvt.u32.u64 %0, t; }"
        : "=r"(a) : "l"(p));
    return a;
}

#define SW128(x) ((x) ^ (((x) >> 3) & 0x70))

#define LDM4(r, addr)                                                            \
    asm volatile("ldmatrix.sync.aligned.m8n8.x4.shared.b16 {%0,%1,%2,%3}, [%4];" \
                 : "=r"((r)[0]), "=r"((r)[1]), "=r"((r)[2]), "=r"((r)[3])        \
                 : "r"(addr))

#define LDM2T(r, addr)                                                           \
    asm volatile("ldmatrix.sync.aligned.m8n8.x2.trans.shared.b16 {%0,%1}, [%2];" \
                 : "=r"((r)[0]), "=r"((r)[1]) : "r"(addr))

#define MMA_BF16(c, a, bb)                                                       \
    asm volatile("mma.sync.aligned.m16n8k16.row.col.f32.bf16.bf16.f32 "          \
                 "{%0,%1,%2,%3}, {%4,%5,%6,%7}, {%8,%9}, {%0,%1,%2,%3};"         \
                 : "+f"((c)[0]), "+f"((c)[1]), "+f"((c)[2]), "+f"((c)[3])        \
                 : "r"((a)[0]), "r"((a)[1]), "r"((a)[2]), "r"((a)[3]),           \
                   "r"((bb)[0]), "r"((bb)[1]))

#define CP16(dst, src)                                                           \
    asm volatile("cp.async.cg.shared.global [%0], [%1], 16;" :: "r"(dst), "l"(src))
#define CP_COMMIT asm volatile("cp.async.commit_group;" ::: "memory")
#define CP_WAIT0  asm volatile("cp.async.wait_group 0;" ::: "memory")

// ---------------------------- CSR build (merged) ----------------------------
__global__ void zero_all_kernel(int* d0, int* d1, int* d2) {
    int i = blockIdx.x * blockDim.x + threadIdx.x;
    if (i < 2048) d0[i] = 0;
    else if (i < 2560) d1[i - 2048] = 0;
    else if (i < 2688) d2[i - 2560] = 0;
}

__global__ void count_all_kernel(const int* e0, const int* e1, const int* e2,
                                 int* d0, int* d1, int* d2) {
    int i = blockIdx.x * blockDim.x + threadIdx.x;
    if (i < 16384) atomicAdd(&d0[e0[16384 + i]], 1);
    else if (i < 24576) atomicAdd(&d1[e1[8192 + (i - 16384)]], 1);
    else if (i < 26624) atomicAdd(&d2[e2[2048 + (i - 24576)]], 1);
}

__global__ void scan_all_kernel(int* d0, int* o0, int* c0, float* v0,
                                int* d1, int* o1, int* c1, float* v1,
                                int* d2, int* o2, int* c2, float* v2) {
    __shared__ int sa[2048];
    __shared__ int sb[2048];
    int lvl = blockIdx.x;
    int* deg = lvl == 0 ? d0 : (lvl == 1 ? d1 : d2);
    int* off = lvl == 0 ? o0 : (lvl == 1 ? o1 : o2);
    int* cur = lvl == 0 ? c0 : (lvl == 1 ? c1 : c2);
    float* inv = lvl == 0 ? v0 : (lvl == 1 ? v1 : v2);
    int N = lvl == 0 ? 2048 : (lvl == 1 ? 512 : 128);
    int tid = threadIdx.x;  // 1024
    for (int q = tid; q < 2048; q += 1024) sa[q] = (q < N) ? deg[q] : 0;
    __syncthreads();
    int *pc = sa, *pn = sb;
    for (int d = 1; d < 2048; d <<= 1) {
        for (int q = tid; q < 2048; q += 1024) {
            int v = pc[q];
            if (q >= d) v += pc[q - d];
            pn[q] = v;
        }
        __syncthreads();
        int* t = pc; pc = pn; pn = t;
    }
    for (int q = tid; q < 2048; q += 1024) {
        if (q < N) {
            int o = (q == 0) ? 0 : pc[q - 1];
            off[q] = o;
            cur[q] = o;
            int dg = deg[q];
            inv[q] = 1.0f / (float)(dg > 0 ? dg : 1);
        }
    }
    if (tid == 0) off[N] = pc[N - 1];
}

__global__ void fill_all_kernel(const int* e0, const int* e1, const int* e2,
                                int* c0, int* c1, int* c2,
                                int* p0, int* p1, int* p2) {
    int i = blockIdx.x * blockDim.x + threadIdx.x;
    if (i < 16384) { int p = atomicAdd(&c0[e0[16384 + i]], 1); p0[p] = i; }
    else if (i < 24576) { int q = i - 16384; int p = atomicAdd(&c1[e1[8192 + q]], 1); p1[p] = q; }
    else if (i < 26624) { int q = i - 24576; int p = atomicAdd(&c2[e2[2048 + q]], 1); p2[p] = q; }
}

__global__ void sort_all_kernel(const int* o0, int* p0, const int* o1, int* p1,
                                const int* o2, int* p2) {
    int i = blockIdx.x * blockDim.x + threadIdx.x;
    const int* off; int* perm; int n;
    if (i < 2048) { off = o0; perm = p0; n = i; }
    else if (i < 2560) { off = o1; perm = p1; n = i - 2048; }
    else if (i < 2688) { off = o2; perm = p2; n = i - 2560; }
    else return;
    int a = off[n], b = off[n + 1];
    for (int k = a + 1; k < b; k++) {
        int v = perm[k];
        int j = k - 1;
        while (j >= a && perm[j] > v) { perm[j + 1] = perm[j]; j--; }
        perm[j + 1] = v;
    }
}

// ------------- level-1 GCN (staged edge weights, bf16 hi/lo out) ------------
__global__ __launch_bounds__(256)
void gcn1_kernel(const float* __restrict__ x, const float* __restrict__ ea,
                 const float* __restrict__ Amat,
                 const float* __restrict__ Wk, const float* __restrict__ Wr,
                 const float* __restrict__ bias,
                 const int* __restrict__ srcArr, const int* __restrict__ off,
                 const int* __restrict__ perm, const float* __restrict__ inv_cnt,
                 __nv_bfloat16* __restrict__ Bh, __nv_bfloat16* __restrict__ Bl) {
    __shared__ float sA[9];
    __shared__ float sW[80];  // Wk[48] | Wr[16] | bias[16]
    __shared__ int sSrc[64];
    __shared__ float sEw[64 * 3];
    const int N0 = 2048;
    int n = blockIdx.x, b = blockIdx.y;
    int t = threadIdx.x;
    if (t < 9) sA[t] = Amat[t];
    if (t < 48) sW[t] = Wk[t];
    else if (t < 64) sW[t] = Wr[t - 48];
    else if (t < 80) sW[t] = bias[t - 64];
    __syncthreads();

    float a0 = 0.f, a1 = 0.f, a2 = 0.f;
    int e0 = off[n], e1 = off[n + 1];
    for (int base = e0; base < e1; base += 64) {
        int cnt = min(64, e1 - base);
        __syncthreads();
        if (t < cnt) {
            int e = perm[base + t];
            sSrc[t] = srcArr[e];
            float u0 = ea[e * 3 + 0], u1 = ea[e * 3 + 1], u2 = ea[e * 3 + 2];
            float w0 = u0 * sA[0] + u1 * sA[3] + u2 * sA[6];
            float w1 = u0 * sA[1] + u1 * sA[4] + u2 * sA[7];
            float w2 = u0 * sA[2] + u1 * sA[5] + u2 * sA[8];
            float m = fmaxf(w0, fmaxf(w1, w2));
            float q0 = __expf(w0 - m), q1 = __expf(w1 - m), q2 = __expf(w2 - m);
            float qi = 1.0f / (q0 + q1 + q2);
            sEw[t * 3 + 0] = q0 * qi;
            sEw[t * 3 + 1] = q1 * qi;
            sEw[t * 3 + 2] = q2 * qi;
        }
        __syncthreads();
        if (t < TT) {
            for (int j = 0; j < cnt; j++) {
                float v = x[(b * N0 + sSrc[j]) * TT + t];
                a0 += sEw[j * 3 + 0] * v;
                a1 += sEw[j * 3 + 1] * v;
                a2 += sEw[j * 3 + 2] * v;
            }
        }
    }
    if (t >= TT) return;
    float inv = inv_cnt[n];
    a0 *= inv; a1 *= inv; a2 *= inv;
    float xo = x[(b * N0 + n) * TT + t];
    long base = ((long)(b * N0 + n) * 16) * TT + t;
#pragma unroll
    for (int o = 0; o < 16; o++) {
        float v = a0 * sW[o] + a1 * sW[16 + o] + a2 * sW[32 + o] + xo * sW[48 + o] + sW[64 + o];
        v = v > 0.0f ? v : expm1f(v);
        __nv_bfloat16 hi = __float2bfloat16(v);
        Bh[base + (long)o * TT] = hi;
        Bl[base + (long)o * TT] = __float2bfloat16(v - __bfloat162float(hi));
    }
}

// -------- fused GCN level (gather in smem + combine), bf16 hi/lo out --------
// dyn smem layout: sW[4*CIN*COUT] | sb[COUT] | sG[3*CIN*TT]
template <int CIN, int COUT>
__global__ __launch_bounds__(256)
void gcnf_kernel(const float* __restrict__ xin, const float* __restrict__ ea,
                 const float* __restrict__ Amat,
                 const float* __restrict__ Wk, const float* __restrict__ Wr,
                 const float* __restrict__ bias,
                 const int* __restrict__ srcArr, const int* __restrict__ off,
                 const int* __restrict__ perm, const float* __restrict__ inv_cnt,
                 __nv_bfloat16* __restrict__ Bh, __nv_bfloat16* __restrict__ Bl, int Nn) {
    constexpr int CC = CIN * COUT;
    extern __shared__ float dsm[];
    float* sW = dsm;                 // 4*CC
    float* sb = sW + 4 * CC;         // COUT
    float* sG = sb + COUT;           // 3*CIN*TT
    __shared__ float sA[9];
    __shared__ int sSrc[64];
    __shared__ float sEw[64 * 3];

    int n = blockIdx.x, b = blockIdx.y;
    int tid = threadIdx.x, tx = tid & 31, ty = tid >> 5;
    if (tid < 9) sA[tid] = Amat[tid];
    for (int q = tid; q < 3 * CC; q += 256) sW[q] = Wk[q];
    for (int q = tid; q < CC; q += 256) sW[3 * CC + q] = Wr[q];
    if (tid < COUT) sb[tid] = bias[tid];
    __syncthreads();

    // ---- gather phase: acc[k][u][s] covers 3 bases x CIN channels x T ----
    constexpr int U = CIN / 8;
    float acc[3][U][7];
#pragma unroll
    for (int k = 0; k < 3; k++)
#pragma unroll
        for (int u = 0; u < U; u++)
#pragma unroll
            for (int s = 0; s < 7; s++) acc[k][u][s] = 0.0f;

    int e0 = off[n], e1 = off[n + 1];
    for (int base = e0; base < e1; base += 64) {
        int cnt = min(64, e1 - base);
        __syncthreads();
        if (tid < cnt) {
            int e = perm[base + tid];
            sSrc[tid] = srcArr[e];
            float u0 = ea[e * 3 + 0], u1 = ea[e * 3 + 1], u2 = ea[e * 3 + 2];
            float w0 = u0 * sA[0] + u1 * sA[3] + u2 * sA[6];
            float w1 = u0 * sA[1] + u1 * sA[4] + u2 * sA[7];
            float w2 = u0 * sA[2] + u1 * sA[5] + u2 * sA[8];
            float m = fmaxf(w0, fmaxf(w1, w2));
            float q0 = __expf(w0 - m), q1 = __expf(w1 - m), q2 = __expf(w2 - m);
            float qi = 1.0f / (q0 + q1 + q2);
            sEw[tid * 3 + 0] = q0 * qi;
            sEw[tid * 3 + 1] = q1 * qi;
            sEw[tid * 3 + 2] = q2 * qi;
        }
        __syncthreads();
        for (int j = 0; j < cnt; j++) {
            float q0 = sEw[j * 3 + 0], q1 = sEw[j * 3 + 1], q2 = sEw[j * 3 + 2];
            const float* xp = xin + (long)(b * Nn + sSrc[j]) * (CIN * TT);
#pragma unroll
            for (int u = 0; u < U; u++) {
#pragma unroll
                for (int s = 0; s < 7; s++) {
                    int t = tx + 32 * s;
                    float v = xp[(ty + 8 * u) * TT + (t < TT ? t : 0)];
                    acc[0][u][s] += q0 * v;
                    acc[1][u][s] += q1 * v;
                    acc[2][u][s] += q2 * v;
                }
            }
        }
    }
    float inv = inv_cnt[n];
    __syncthreads();
#pragma unroll
    for (int k = 0; k < 3; k++)
#pragma unroll
        for (int u = 0; u < U; u++)
#pragma unroll
            for (int s = 0; s < 7; s++) {
                int t = tx + 32 * s;
                if (t < TT) sG[(k * CIN + ty + 8 * u) * TT + t] = acc[k][u][s] * inv;
            }
    __syncthreads();

    // ---- combine phase: out = elu([sG | x] @ [Wk;Wr] + bias) ----
    constexpr int U2 = COUT / 8;
    float a2r[U2][7];
#pragma unroll
    for (int u = 0; u < U2; u++)
#pragma unroll
        for (int s = 0; s < 7; s++) a2r[u][s] = 0.0f;

#pragma unroll 4
    for (int j = 0; j < 3 * CIN; j++) {
        float xr[7];
#pragma unroll
        for (int s = 0; s < 7; s++) {
            int t = tx + 32 * s;
            xr[s] = sG[j * TT + (t < TT ? t : 0)];
        }
#pragma unroll
        for (int u = 0; u < U2; u++) {
            float w = sW[j * COUT + ty + 8 * u];
#pragma unroll
            for (int s = 0; s < 7; s++) a2r[u][s] += w * xr[s];
        }
    }
    const float* xp = xin + (long)(b * Nn + n) * (CIN * TT);
#pragma unroll 4
    for (int j = 0; j < CIN; j++) {
        float xr[7];
#pragma unroll
        for (int s = 0; s < 7; s++) {
            int t = tx + 32 * s;
            xr[s] = xp[j * TT + (t < TT ? t : 0)];
        }
#pragma unroll
        for (int u = 0; u < U2; u++) {
            float w = sW[(3 * CIN + j) * COUT + ty + 8 * u];
#pragma unroll
            for (int s = 0; s < 7; s++) a2r[u][s] += w * xr[s];
        }
    }

    long obase = (long)(b * Nn + n) * (COUT * TT);
#pragma unroll
    for (int u = 0; u < U2; u++) {
        int o = ty + 8 * u;
        float bb = sb[o];
#pragma unroll
        for (int s = 0; s < 7; s++) {
            int t = tx + 32 * s;
            if (t < TT) {
                float v = a2r[u][s] + bb;
                v = v > 0.0f ? v : expm1f(v);
                __nv_bfloat16 hi = __float2bfloat16(v);
                Bh[obase + o * TT + t] = hi;
                Bl[obase + o * TT + t] = __float2bfloat16(v - __bfloat162float(hi));
            }
        }
    }
}

// ---------------- split all three P matrices into bf16 hi/lo ----------------
__global__ void splitA_kernel(const float* __restrict__ P01, const float* __restrict__ P12,
                              const float* __restrict__ P23,
                              __nv_bfloat16* A1h, __nv_bfloat16* A1l,
                              __nv_bfloat16* A2h, __nv_bfloat16* A2l,
                              __nv_bfloat16* A3h, __nv_bfloat16* A3l) {
    const int S1 = 512 * 2048, S2 = 128 * 512, S3 = 128 * 128;
    int i = blockIdx.x * blockDim.x + threadIdx.x;
    float v; __nv_bfloat16 *H, *L; int o;
    if (i < S1) { o = i; v = P01[o]; H = A1h; L = A1l; }
    else if (i < S1 + S2) { o = i - S1; v = P12[o]; H = A2h; L = A2l; }
    else if (i < S1 + S2 + S3) {
        o = i - S1 - S2;
        int m = o / 128;
        v = (m < 64) ? P23[o] : 0.0f;
        H = A3h; L = A3l;
    } else return;
    __nv_bfloat16 hi = __float2bfloat16(v);
    H[o] = hi;
    L[o] = __float2bfloat16(v - __bfloat162float(hi));
}

// ------- bf16x3 GEMM, cp.async double-buffered, B read via trans-ldmatrix ----
__global__ __launch_bounds__(256)
void mma_gemm_kernel(const __nv_bfloat16* __restrict__ Ahi, const __nv_bfloat16* __restrict__ Alo,
                     const __nv_bfloat16* __restrict__ Bhi, const __nv_bfloat16* __restrict__ Blo,
                     float* __restrict__ C, int Mout, int K, int F) {
    extern __shared__ char smem[];
    const int BUF = 49152;
    const int OFF_AH = 0, OFF_AL = 16384, OFF_BH = 32768, OFF_BL = 40960;
    uint32_t sbase = smem_u32(smem);
    int tid = threadIdx.x, lane = tid & 31, w = tid >> 5;
    int mw = w & 1, fw = w >> 1;
    int f0 = blockIdx.x * 64, row0 = blockIdx.y * 128, b = blockIdx.z;

    const __nv_bfloat16* BhB = Bhi + (long)b * K * F;
    const __nv_bfloat16* BlB = Blo + (long)b * K * F;

    float acc[4][2][4];
#pragma unroll
    for (int mt = 0; mt < 4; mt++)
#pragma unroll
        for (int nt = 0; nt < 2; nt++)
#pragma unroll
            for (int q = 0; q < 4; q++) acc[mt][nt][q] = 0.0f;

    int r = tid >> 3, cb = (tid & 7) * 16;
    int nchunk = K >> 6;

#define STAGE(bo, k0)                                                              \
    do {                                                                           \
        _Pragma("unroll")                                                          \
        for (int i = 0; i < 4; i++) {                                              \
            int rr = r + i * 32;                                                   \
            uint32_t so = SW128(rr * 128 + cb);                                    \
            CP16(sbase + (bo) + OFF_AH + so,                                       \
                 (const char*)&Ahi[(long)(row0 + rr) * K + (k0) + (cb >> 1)]);     \
            CP16(sbase + (bo) + OFF_AL + so,                                       \
                 (const char*)&Alo[(long)(row0 + rr) * K + (k0) + (cb >> 1)]);     \
        }                                                                          \
        _Pragma("unroll")                                                          \
        for (int i = 0; i < 2; i++) {                                              \
            int rr = r + i * 32;                                                   \
            uint32_t so = SW128(rr * 128 + cb);                                    \
            long gi = (long)((k0) + rr) * F + f0 + (cb >> 1);                      \
            CP16(sbase + (bo) + OFF_BH + so, (const char*)&BhB[gi]);               \
            CP16(sbase + (bo) + OFF_BL + so, (const char*)&BlB[gi]);               \
        }                                                                          \
    } while (0)

    STAGE(0, 0);
    CP_COMMIT;

    int buf = 0;
    for (int kc = 0; kc < nchunk; kc++) {
        CP_WAIT0;
        __syncthreads();
        if (kc + 1 < nchunk) {
            STAGE((buf ^ 1) * BUF, (kc + 1) << 6);
            CP_COMMIT;
        }
        int bo = buf * BUF;
#pragma unroll
        for (int ks = 0; ks < 4; ks++) {
            uint32_t ah[4][4], al[4][4], bh[2][2], bl[2][2];
#pragma unroll
            for (int mt = 0; mt < 4; mt++) {
                uint32_t off = SW128((mw * 64 + mt * 16 + (lane & 15)) * 128 +
                                     ks * 32 + (lane >> 4) * 16);
                LDM4(ah[mt], sbase + bo + OFF_AH + off);
                LDM4(al[mt], sbase + bo + OFF_AL + off);
            }
#pragma unroll
            for (int nt = 0; nt < 2; nt++) {
                uint32_t off = SW128((ks * 16 + (lane & 15)) * 128 + fw * 32 + nt * 16);
                LDM2T(bh[nt], sbase + bo + OFF_BH + off);
                LDM2T(bl[nt], sbase + bo + OFF_BL + off);
            }
#pragma unroll
            for (int mt = 0; mt < 4; mt++) {
#pragma unroll
                for (int nt = 0; nt < 2; nt++) {
                    MMA_BF16(acc[mt][nt], ah[mt], bh[nt]);
                    MMA_BF16(acc[mt][nt], ah[mt], bl[nt]);
                    MMA_BF16(acc[mt][nt], al[mt], bh[nt]);
                }
            }
        }
        __syncthreads();
        buf ^= 1;
    }
#undef STAGE

#pragma unroll
    for (int mt = 0; mt < 4; mt++) {
        int gr = row0 + mw * 64 + mt * 16 + (lane >> 2);
#pragma unroll
        for (int nt = 0; nt < 2; nt++) {
            int gc = f0 + fw * 16 + nt * 8 + (lane & 3) * 2;
            if (gr < Mout)
                *(float2*)&C[((long)b * Mout + gr) * F + gc] =
                    make_float2(acc[mt][nt][0], acc[mt][nt][1]);
            if (gr + 8 < Mout)
                *(float2*)&C[((long)b * Mout + gr + 8) * F + gc] =
                    make_float2(acc[mt][nt][2], acc[mt][nt][3]);
        }
    }
}

// ----------------------- per-node linear head (T-half) ----------------------
template <int CIN, int COUT, int ACT>
__global__ __launch_bounds__(256)
void linear_kernel(const float* __restrict__ in, const float* __restrict__ W,
                   const float* __restrict__ bias, float* __restrict__ out, int Nn) {
    __shared__ float sW[CIN * COUT];
    __shared__ float sb[COUT];
    int n = blockIdx.x, b = blockIdx.y, tz = blockIdx.z;
    int tid = threadIdx.x, tx = tid & 31, ty = tid >> 5;
    for (int q = tid; q < CIN * COUT; q += 256) sW[q] = W[q];
    if (tid < COUT) sb[tid] = bias[tid];
    __syncthreads();

    constexpr int U = COUT / 8;
    float acc[U][4];
#pragma unroll
    for (int u = 0; u < U; u++)
#pragma unroll
        for (int s = 0; s < 4; s++) acc[u][s] = 0.0f;

    const float* xp = in + (long)(b * Nn + n) * (CIN * TT) + tz * 100;
#pragma unroll 4
    for (int j = 0; j < CIN; j++) {
        float xr[4];
#pragma unroll
        for (int s = 0; s < 4; s++) {
            int t = tx + 32 * s;
            xr[s] = xp[j * TT + (t < 100 ? t : 0)];
        }
#pragma unroll
        for (int u = 0; u < U; u++) {
            float w = sW[j * COUT + ty + 8 * u];
#pragma unroll
            for (int s = 0; s < 4; s++) acc[u][s] += w * xr[s];
        }
    }

    float* op = out + (long)(b * Nn + n) * (COUT * TT) + tz * 100;
#pragma unroll
    for (int u = 0; u < U; u++) {
        int o = ty + 8 * u;
        float bb = sb[o];
#pragma unroll
        for (int s = 0; s < 4; s++) {
            int t = tx + 32 * s;
            if (t < 100) {
                float v = acc[u][s] + bb;
                if (ACT == 0)
                    v = v > 0.0f ? v : expm1f(v);
                else
                    v = tanhf(v);
                op[o * TT + t] = v;
            }
        }
    }
}

// -------------------------------- launch ------------------------------------
#define GETSYM(var, sym)                                       \
    do {                                                       \
        void* _p = nullptr;                                    \
        cudaGetSymbolAddress(&_p, sym);                        \
        var = (decltype(var))_p;                               \
    } while (0)

extern "C" void kernel_launch(void* const* d_in, const int* in_sizes, int n_in,
                              void* d_out, int out_size) {
    (void)in_sizes; (void)n_in; (void)out_size;
    const float* x   = (const float*)d_in[0];
    const int*   ei0 = (const int*)d_in[1];
    const float* ea0 = (const float*)d_in[2];
    const int*   ei1 = (const int*)d_in[3];
    const float* ea1 = (const float*)d_in[4];
    const int*   ei2 = (const int*)d_in[5];
    const float* ea2 = (const float*)d_in[6];
    const float* A1  = (const float*)d_in[7];
    const float* Wk1 = (const float*)d_in[8];
    const float* Wr1 = (const float*)d_in[9];
    const float* b1  = (const float*)d_in[10];
    const float* A2  = (const float*)d_in[11];
    const float* Wk2 = (const float*)d_in[12];
    const float* Wr2 = (const float*)d_in[13];
    const float* b2  = (const float*)d_in[14];
    const float* A3  = (const float*)d_in[15];
    const float* Wk3 = (const float*)d_in[16];
    const float* Wr3 = (const float*)d_in[17];
    const float* b3  = (const float*)d_in[18];
    const float* P01 = (const float*)d_in[19];
    const float* P12 = (const float*)d_in[20];
    const float* P23 = (const float*)d_in[21];
    const float* f1w = (const float*)d_in[22];
    const float* f1b = (const float*)d_in[23];
    const float* f2w = (const float*)d_in[24];
    const float* f2b = (const float*)d_in[25];

    const int N0 = 2048, N1 = 512, N2 = 128, N3 = 64;

    float *p1, *p2, *p3, *hm;
    __nv_bfloat16 *A1h, *A1l, *A2h, *A2l, *A3h, *A3l, *Bh, *Bl;
    int *deg0, *off0, *cur0, *perm0;
    int *deg1, *off1, *cur1, *perm1;
    int *deg2, *off2, *cur2, *perm2;
    float *inv0, *inv1, *inv2;
    GETSYM(p1, g_p1); GETSYM(p2, g_p2); GETSYM(p3, g_p3); GETSYM(hm, g_hm);
    GETSYM(A1h, g_A1h); GETSYM(A1l, g_A1l);
    GETSYM(A2h, g_A2h); GETSYM(A2l, g_A2l);
    GETSYM(A3h, g_A3h); GETSYM(A3l, g_A3l);
    GETSYM(Bh, g_Bh); GETSYM(Bl, g_Bl);
    GETSYM(deg0, g_deg0); GETSYM(off0, g_off0); GETSYM(cur0, g_cur0); GETSYM(perm0, g_perm0);
    GETSYM(deg1, g_deg1); GETSYM(off1, g_off1); GETSYM(cur1, g_cur1); GETSYM(perm1, g_perm1);
    GETSYM(deg2, g_deg2); GETSYM(off2, g_off2); GETSYM(cur2, g_cur2); GETSYM(perm2, g_perm2);
    GETSYM(inv0, g_inv0); GETSYM(inv1, g_inv1); GETSYM(inv2, g_inv2);

    const int SMEM_GEMM = 98304;  // 2 x 48KB double buffer
    cudaFuncSetAttribute(mma_gemm_kernel, cudaFuncAttributeMaxDynamicSharedMemorySize,
                         SMEM_GEMM);
    const int SMEM_F1 = (4 * 16 * 32 + 32 + 3 * 16 * TT) * 4;    // ~47KB
    const int SMEM_F2 = (4 * 32 * 64 + 64 + 3 * 32 * TT) * 4;    // ~108KB
    cudaFuncSetAttribute((const void*)gcnf_kernel<16, 32>,
                         cudaFuncAttributeMaxDynamicSharedMemorySize, SMEM_F1);
    cudaFuncSetAttribute((const void*)gcnf_kernel<32, 64>,
                         cudaFuncAttributeMaxDynamicSharedMemorySize, SMEM_F2);

    // ---- CSR (all 3 levels, merged launches) ----
    zero_all_kernel<<<(2688 + 255) / 256, 256>>>(deg0, deg1, deg2);
    count_all_kernel<<<(26624 + 255) / 256, 256>>>(ei0, ei1, ei2, deg0, deg1, deg2);
    scan_all_kernel<<<3, 1024>>>(deg0, off0, cur0, inv0, deg1, off1, cur1, inv1,
                                 deg2, off2, cur2, inv2);
    fill_all_kernel<<<(26624 + 255) / 256, 256>>>(ei0, ei1, ei2, cur0, cur1, cur2,
                                                  perm0, perm1, perm2);
    sort_all_kernel<<<(2688 + 127) / 128, 128>>>(off0, perm0, off1, perm1, off2, perm2);

    // ---- P matrices -> bf16 hi/lo (A operands) ----
    splitA_kernel<<<(512 * 2048 + 128 * 512 + 128 * 128 + 255) / 256, 256>>>(
        P01, P12, P23, A1h, A1l, A2h, A2l, A3h, A3l);

    // ---- level 0->1 GCN : x -> B operand (bf16 hi/lo) ----
    gcn1_kernel<<<dim3(N0, 2), 256>>>(x, ea0, A1, Wk1, Wr1, b1, ei0, off0, perm0, inv0,
                                      Bh, Bl);

    // ---- pool1: p1 = P01 @ h1 ; M=512, K=2048, F=3200 ----
    mma_gemm_kernel<<<dim3(3200 / 64, 512 / 128, 2), 256, SMEM_GEMM>>>(
        A1h, A1l, Bh, Bl, p1, 512, 2048, 3200);

    // ---- level 1->2 GCN (fused gather+combine) ----
    gcnf_kernel<16, 32><<<dim3(N1, 2), 256, SMEM_F1>>>(
        p1, ea1, A2, Wk2, Wr2, b2, ei1, off1, perm1, inv1, Bh, Bl, N1);

    // ---- pool2: M=128, K=512, F=6400 ----
    mma_gemm_kernel<<<dim3(6400 / 64, 1, 2), 256, SMEM_GEMM>>>(
        A2h, A2l, Bh, Bl, p2, 128, 512, 6400);

    // ---- level 2->3 GCN (fused gather+combine) ----
    gcnf_kernel<32, 64><<<dim3(N2, 2), 256, SMEM_F2>>>(
        p2, ea2, A3, Wk3, Wr3, b3, ei2, off2, perm2, inv2, Bh, Bl, N2);

    // ---- pool3: M=64 (padded 128), K=128, F=12800 ----
    mma_gemm_kernel<<<dim3(12800 / 64, 1, 2), 256, SMEM_GEMM>>>(
        A3h, A3l, Bh, Bl, p3, 64, 128, 12800);

    // ---- head ----
    linear_kernel<64, 128, 0><<<dim3(N3, 2, 2), 256>>>(p3, f1w, f1b, hm, N3);
    linear_kernel<128, 64, 1><<<dim3(N3, 2, 2), 256>>>(hm, f2w, f2b, (float*)d_out, N3);
}

// round 7
// speedup vs baseline: 3.2069x; 1.0757x over previous
#include <cuda_runtime.h>
#include <cuda_bf16.h>
#include <cstdint>

// ============================================================================
// Graph_ODE_RNN — 8-launch pipeline:
//  [csr+splitA] -> gcn1 -> pool1 -> gcnf1 -> pool2 -> gcnf2 -> pool3 -> head
// ============================================================================

#define TT 200

// ---------------- static scratch (no allocation allowed) -------------------
__device__ float g_p1[2 * 512 * 16 * TT];
__device__ float g_p2[2 * 128 * 32 * TT];
__device__ float g_p3[2 * 64 * 64 * TT];

__device__ __nv_bfloat16 g_A1h[512 * 2048], g_A1l[512 * 2048];
__device__ __nv_bfloat16 g_A2h[128 * 512],  g_A2l[128 * 512];
__device__ __nv_bfloat16 g_A3h[128 * 128],  g_A3l[128 * 128];  // M padded 64->128
__device__ __nv_bfloat16 g_Bh[2 * 2048 * 3200], g_Bl[2 * 2048 * 3200];

__device__ int g_off0[2049], g_perm0[16384];
__device__ int g_off1[513],  g_perm1[8192];
__device__ int g_off2[129],  g_perm2[2048];
__device__ float g_inv0[2048], g_inv1[512], g_inv2[128];

// ---------------------------- helpers ---------------------------------------
__device__ __forceinline__ uint32_t smem_u32(const void* p) {
    uint32_t a;
    asm("{ .reg .u64 t; cvta.to.shared.u64 t, %1; cvt.u32.u64 %0, t; }"
        : "=r"(a) : "l"(p));
    return a;
}

#define SW128(x) ((x) ^ (((x) >> 3) & 0x70))

#define LDM4(r, addr)                                                            \
    asm volatile("ldmatrix.sync.aligned.m8n8.x4.shared.b16 {%0,%1,%2,%3}, [%4];" \
                 : "=r"((r)[0]), "=r"((r)[1]), "=r"((r)[2]), "=r"((r)[3])        \
                 : "r"(addr))

#define LDM2T(r, addr)                                                           \
    asm volatile("ldmatrix.sync.aligned.m8n8.x2.trans.shared.b16 {%0,%1}, [%2];" \
                 : "=r"((r)[0]), "=r"((r)[1]) : "r"(addr))

#define MMA_BF16(c, a, bb)                                                       \
    asm volatile("mma.sync.aligned.m16n8k16.row.col.f32.bf16.bf16.f32 "          \
                 "{%0,%1,%2,%3}, {%4,%5,%6,%7}, {%8,%9}, {%0,%1,%2,%3};"         \
                 : "+f"((c)[0]), "+f"((c)[1]), "+f"((c)[2]), "+f"((c)[3])        \
                 : "r"((a)[0]), "r"((a)[1]), "r"((a)[2]), "r"((a)[3]),           \
                   "r"((bb)[0]), "r"((bb)[1]))

#define CP16(dst, src)                                                           \
    asm volatile("cp.async.cg.shared.global [%0], [%1], 16;" :: "r"(dst), "l"(src))
#define CP_COMMIT asm volatile("cp.async.commit_group;" ::: "memory")
#define CP_WAIT0  asm volatile("cp.async.wait_group 0;" ::: "memory")

// -------------- merged setup: 3 CSR blocks + splitA blocks ------------------
// blockIdx.x < 3  : build CSR for level (count/scan/fill/sort, in-block)
// blockIdx.x >= 3 : split P matrices into bf16 hi/lo
__global__ __launch_bounds__(1024)
void setup_kernel(const int* e0, const int* e1, const int* e2,
                  int* o0, int* p0, float* v0,
                  int* o1, int* p1, float* v1,
                  int* o2, int* p2, float* v2,
                  const float* __restrict__ P01, const float* __restrict__ P12,
                  const float* __restrict__ P23,
                  __nv_bfloat16* A1h, __nv_bfloat16* A1l,
                  __nv_bfloat16* A2h, __nv_bfloat16* A2l,
                  __nv_bfloat16* A3h, __nv_bfloat16* A3l) {
    int tid = threadIdx.x;
    if (blockIdx.x >= 3) {
        // ---- splitA part ----
        const int S1 = 512 * 2048, S2 = 128 * 512, S3 = 128 * 128;
        long i = (long)(blockIdx.x - 3) * 1024 + tid;
        float v; __nv_bfloat16 *H, *L; long o;
        if (i < S1) { o = i; v = P01[o]; H = A1h; L = A1l; }
        else if (i < S1 + S2) { o = i - S1; v = P12[o]; H = A2h; L = A2l; }
        else if (i < S1 + S2 + S3) {
            o = i - S1 - S2;
            v = ((o >> 7) < 64) ? P23[o] : 0.0f;
            H = A3h; L = A3l;
        } else return;
        __nv_bfloat16 hi = __float2bfloat16(v);
        H[o] = hi;
        L[o] = __float2bfloat16(v - __bfloat162float(hi));
        return;
    }
    // ---- CSR part: one block per level ----
    __shared__ int sa[2048];
    __shared__ int sb[2048];
    __shared__ int scur[2048];
    int lvl = blockIdx.x;
    const int* dst = lvl == 0 ? e0 + 16384 : (lvl == 1 ? e1 + 8192 : e2 + 2048);
    int E = lvl == 0 ? 16384 : (lvl == 1 ? 8192 : 2048);
    int N = lvl == 0 ? 2048 : (lvl == 1 ? 512 : 128);
    int* off = lvl == 0 ? o0 : (lvl == 1 ? o1 : o2);
    int* perm = lvl == 0 ? p0 : (lvl == 1 ? p1 : p2);
    float* inv = lvl == 0 ? v0 : (lvl == 1 ? v1 : v2);

    // count (deg in sa)
    for (int q = tid; q < 2048; q += 1024) sa[q] = 0;
    __syncthreads();
    for (int i = tid; i < E; i += 1024) atomicAdd(&sa[dst[i]], 1);
    __syncthreads();
    for (int q = tid; q < 2048; q += 1024) {
        int dg = sa[q];
        sb[q] = dg;  // keep deg in sb
        if (q < N) inv[q] = 1.0f / (float)(dg > 0 ? dg : 1);
    }
    __syncthreads();
    // inclusive scan of sa (Hillis-Steele, ping-pong sa<->scur)
    int* pc = sa;
    int* pn = scur;
    for (int d = 1; d < 2048; d <<= 1) {
        for (int q = tid; q < 2048; q += 1024) {
            int v = pc[q];
            if (q >= d) v += pc[q - d];
            pn[q] = v;
        }
        __syncthreads();
        int* t = pc; pc = pn; pn = t;
    }
    // offsets -> gmem + cursors (reuse pn buffer as cursor)
    for (int q = tid; q < N; q += 1024) {
        int o = (q == 0) ? 0 : pc[q - 1];
        off[q] = o;
        pn[q] = o;
    }
    if (tid == 0) off[N] = pc[N - 1];
    __syncthreads();
    // fill
    for (int i = tid; i < E; i += 1024) {
        int p = atomicAdd(&pn[dst[i]], 1);
        perm[p] = i;
    }
    __syncthreads();
    // deterministic order: insertion sort per node
    for (int n = tid; n < N; n += 1024) {
        int a = (n == 0) ? 0 : pc[n - 1];
        int b = pc[n];
        for (int k = a + 1; k < b; k++) {
            int v = perm[k];
            int j = k - 1;
            while (j >= a && perm[j] > v) { perm[j + 1] = perm[j]; j--; }
            perm[j + 1] = v;
        }
    }
}

// ------- level-1 GCN (both batches per block, staged edge weights) ----------
__global__ __launch_bounds__(256)
void gcn1_kernel(const float* __restrict__ x, const float* __restrict__ ea,
                 const float* __restrict__ Amat,
                 const float* __restrict__ Wk, const float* __restrict__ Wr,
                 const float* __restrict__ bias,
                 const int* __restrict__ srcArr, const int* __restrict__ off,
                 const int* __restrict__ perm, const float* __restrict__ inv_cnt,
                 __nv_bfloat16* __restrict__ Bh, __nv_bfloat16* __restrict__ Bl) {
    __shared__ float sA[9];
    __shared__ float sW[80];  // Wk[48] | Wr[16] | bias[16]
    __shared__ int sSrc[64];
    __shared__ float sEw[64 * 3];
    const int N0 = 2048;
    int n = blockIdx.x;
    int t = threadIdx.x;
    if (t < 9) sA[t] = Amat[t];
    if (t < 48) sW[t] = Wk[t];
    else if (t < 64) sW[t] = Wr[t - 48];
    else if (t < 80) sW[t] = bias[t - 64];
    __syncthreads();

    float a0[3] = {0.f, 0.f, 0.f};
    float a1[3] = {0.f, 0.f, 0.f};
    int e0 = off[n], e1 = off[n + 1];
    for (int base = e0; base < e1; base += 64) {
        int cnt = min(64, e1 - base);
        __syncthreads();
        if (t < cnt) {
            int e = perm[base + t];
            sSrc[t] = srcArr[e];
            float u0 = ea[e * 3 + 0], u1 = ea[e * 3 + 1], u2 = ea[e * 3 + 2];
            float w0 = u0 * sA[0] + u1 * sA[3] + u2 * sA[6];
            float w1 = u0 * sA[1] + u1 * sA[4] + u2 * sA[7];
            float w2 = u0 * sA[2] + u1 * sA[5] + u2 * sA[8];
            float m = fmaxf(w0, fmaxf(w1, w2));
            float q0 = __expf(w0 - m), q1 = __expf(w1 - m), q2 = __expf(w2 - m);
            float qi = 1.0f / (q0 + q1 + q2);
            sEw[t * 3 + 0] = q0 * qi;
            sEw[t * 3 + 1] = q1 * qi;
            sEw[t * 3 + 2] = q2 * qi;
        }
        __syncthreads();
        if (t < TT) {
            for (int j = 0; j < cnt; j++) {
                int src = sSrc[j];
                float w0 = sEw[j * 3 + 0], w1 = sEw[j * 3 + 1], w2 = sEw[j * 3 + 2];
                float va = x[src * TT + t];
                float vb = x[(N0 + src) * TT + t];
                a0[0] += w0 * va; a0[1] += w1 * va; a0[2] += w2 * va;
                a1[0] += w0 * vb; a1[1] += w1 * vb; a1[2] += w2 * vb;
            }
        }
    }
    if (t >= TT) return;
    float inv = inv_cnt[n];
#pragma unroll
    for (int k = 0; k < 3; k++) { a0[k] *= inv; a1[k] *= inv; }
    float xo0 = x[n * TT + t];
    float xo1 = x[(N0 + n) * TT + t];
    long base0 = ((long)n * 16) * TT + t;
    long base1 = ((long)(N0 + n) * 16) * TT + t;
#pragma unroll
    for (int o = 0; o < 16; o++) {
        float v = a0[0] * sW[o] + a0[1] * sW[16 + o] + a0[2] * sW[32 + o] +
                  xo0 * sW[48 + o] + sW[64 + o];
        v = v > 0.0f ? v : expm1f(v);
        __nv_bfloat16 hi = __float2bfloat16(v);
        Bh[base0 + (long)o * TT] = hi;
        Bl[base0 + (long)o * TT] = __float2bfloat16(v - __bfloat162float(hi));
        v = a1[0] * sW[o] + a1[1] * sW[16 + o] + a1[2] * sW[32 + o] +
            xo1 * sW[48 + o] + sW[64 + o];
        v = v > 0.0f ? v : expm1f(v);
        hi = __float2bfloat16(v);
        Bh[base1 + (long)o * TT] = hi;
        Bl[base1 + (long)o * TT] = __float2bfloat16(v - __bfloat162float(hi));
    }
}

// -------- fused GCN level (gather in smem + combine), bf16 hi/lo out --------
template <int CIN, int COUT>
__global__ __launch_bounds__(256)
void gcnf_kernel(const float* __restrict__ xin, const float* __restrict__ ea,
                 const float* __restrict__ Amat,
                 const float* __restrict__ Wk, const float* __restrict__ Wr,
                 const float* __restrict__ bias,
                 const int* __restrict__ srcArr, const int* __restrict__ off,
                 const int* __restrict__ perm, const float* __restrict__ inv_cnt,
                 __nv_bfloat16* __restrict__ Bh, __nv_bfloat16* __restrict__ Bl, int Nn) {
    constexpr int CC = CIN * COUT;
    extern __shared__ float dsm[];
    float* sW = dsm;
    float* sb = sW + 4 * CC;
    float* sG = sb + COUT;
    __shared__ float sA[9];
    __shared__ int sSrc[64];
    __shared__ float sEw[64 * 3];

    int n = blockIdx.x, b = blockIdx.y;
    int tid = threadIdx.x, tx = tid & 31, ty = tid >> 5;
    if (tid < 9) sA[tid] = Amat[tid];
    for (int q = tid; q < 3 * CC; q += 256) sW[q] = Wk[q];
    for (int q = tid; q < CC; q += 256) sW[3 * CC + q] = Wr[q];
    if (tid < COUT) sb[tid] = bias[tid];
    __syncthreads();

    constexpr int U = CIN / 8;
    float acc[3][U][7];
#pragma unroll
    for (int k = 0; k < 3; k++)
#pragma unroll
        for (int u = 0; u < U; u++)
#pragma unroll
            for (int s = 0; s < 7; s++) acc[k][u][s] = 0.0f;

    int e0 = off[n], e1 = off[n + 1];
    for (int base = e0; base < e1; base += 64) {
        int cnt = min(64, e1 - base);
        __syncthreads();
        if (tid < cnt) {
            int e = perm[base + tid];
            sSrc[tid] = srcArr[e];
            float u0 = ea[e * 3 + 0], u1 = ea[e * 3 + 1], u2 = ea[e * 3 + 2];
            float w0 = u0 * sA[0] + u1 * sA[3] + u2 * sA[6];
            float w1 = u0 * sA[1] + u1 * sA[4] + u2 * sA[7];
            float w2 = u0 * sA[2] + u1 * sA[5] + u2 * sA[8];
            float m = fmaxf(w0, fmaxf(w1, w2));
            float q0 = __expf(w0 - m), q1 = __expf(w1 - m), q2 = __expf(w2 - m);
            float qi = 1.0f / (q0 + q1 + q2);
            sEw[tid * 3 + 0] = q0 * qi;
            sEw[tid * 3 + 1] = q1 * qi;
            sEw[tid * 3 + 2] = q2 * qi;
        }
        __syncthreads();
        for (int j = 0; j < cnt; j++) {
            float q0 = sEw[j * 3 + 0], q1 = sEw[j * 3 + 1], q2 = sEw[j * 3 + 2];
            const float* xp = xin + (long)(b * Nn + sSrc[j]) * (CIN * TT);
#pragma unroll
            for (int u = 0; u < U; u++) {
#pragma unroll
                for (int s = 0; s < 7; s++) {
                    int t = tx + 32 * s;
                    float v = xp[(ty + 8 * u) * TT + (t < TT ? t : 0)];
                    acc[0][u][s] += q0 * v;
                    acc[1][u][s] += q1 * v;
                    acc[2][u][s] += q2 * v;
                }
            }
        }
    }
    float inv = inv_cnt[n];
    __syncthreads();
#pragma unroll
    for (int k = 0; k < 3; k++)
#pragma unroll
        for (int u = 0; u < U; u++)
#pragma unroll
            for (int s = 0; s < 7; s++) {
                int t = tx + 32 * s;
                if (t < TT) sG[(k * CIN + ty + 8 * u) * TT + t] = acc[k][u][s] * inv;
            }
    __syncthreads();

    constexpr int U2 = COUT / 8;
    float a2r[U2][7];
#pragma unroll
    for (int u = 0; u < U2; u++)
#pragma unroll
        for (int s = 0; s < 7; s++) a2r[u][s] = 0.0f;

#pragma unroll 4
    for (int j = 0; j < 3 * CIN; j++) {
        float xr[7];
#pragma unroll
        for (int s = 0; s < 7; s++) {
            int t = tx + 32 * s;
            xr[s] = sG[j * TT + (t < TT ? t : 0)];
        }
#pragma unroll
        for (int u = 0; u < U2; u++) {
            float w = sW[j * COUT + ty + 8 * u];
#pragma unroll
            for (int s = 0; s < 7; s++) a2r[u][s] += w * xr[s];
        }
    }
    const float* xp = xin + (long)(b * Nn + n) * (CIN * TT);
#pragma unroll 4
    for (int j = 0; j < CIN; j++) {
        float xr[7];
#pragma unroll
        for (int s = 0; s < 7; s++) {
            int t = tx + 32 * s;
            xr[s] = xp[j * TT + (t < TT ? t : 0)];
        }
#pragma unroll
        for (int u = 0; u < U2; u++) {
            float w = sW[(3 * CIN + j) * COUT + ty + 8 * u];
#pragma unroll
            for (int s = 0; s < 7; s++) a2r[u][s] += w * xr[s];
        }
    }

    long obase = (long)(b * Nn + n) * (COUT * TT);
#pragma unroll
    for (int u = 0; u < U2; u++) {
        int o = ty + 8 * u;
        float bb = sb[o];
#pragma unroll
        for (int s = 0; s < 7; s++) {
            int t = tx + 32 * s;
            if (t < TT) {
                float v = a2r[u][s] + bb;
                v = v > 0.0f ? v : expm1f(v);
                __nv_bfloat16 hi = __float2bfloat16(v);
                Bh[obase + o * TT + t] = hi;
                Bl[obase + o * TT + t] = __float2bfloat16(v - __bfloat162float(hi));
            }
        }
    }
}

// ------- bf16x3 GEMM, cp.async double-buffered, B read via trans-ldmatrix ----
__global__ __launch_bounds__(256)
void mma_gemm_kernel(const __nv_bfloat16* __restrict__ Ahi, const __nv_bfloat16* __restrict__ Alo,
                     const __nv_bfloat16* __restrict__ Bhi, const __nv_bfloat16* __restrict__ Blo,
                     float* __restrict__ C, int Mout, int K, int F) {
    extern __shared__ char smem[];
    const int BUF = 49152;
    const int OFF_AH = 0, OFF_AL = 16384, OFF_BH = 32768, OFF_BL = 40960;
    uint32_t sbase = smem_u32(smem);
    int tid = threadIdx.x, lane = tid & 31, w = tid >> 5;
    int mw = w & 1, fw = w >> 1;
    int f0 = blockIdx.x * 64, row0 = blockIdx.y * 128, b = blockIdx.z;

    const __nv_bfloat16* BhB = Bhi + (long)b * K * F;
    const __nv_bfloat16* BlB = Blo + (long)b * K * F;

    float acc[4][2][4];
#pragma unroll
    for (int mt = 0; mt < 4; mt++)
#pragma unroll
        for (int nt = 0; nt < 2; nt++)
#pragma unroll
            for (int q = 0; q < 4; q++) acc[mt][nt][q] = 0.0f;

    int r = tid >> 3, cb = (tid & 7) * 16;
    int nchunk = K >> 6;

#define STAGE(bo, k0)                                                              \
    do {                                                                           \
        _Pragma("unroll")                                                          \
        for (int i = 0; i < 4; i++) {                                              \
            int rr = r + i * 32;                                                   \
            uint32_t so = SW128(rr * 128 + cb);                                    \
            CP16(sbase + (bo) + OFF_AH + so,                                       \
                 (const char*)&Ahi[(long)(row0 + rr) * K + (k0) + (cb >> 1)]);     \
            CP16(sbase + (bo) + OFF_AL + so,                                       \
                 (const char*)&Alo[(long)(row0 + rr) * K + (k0) + (cb >> 1)]);     \
        }                                                                          \
        _Pragma("unroll")                                                          \
        for (int i = 0; i < 2; i++) {                                              \
            int rr = r + i * 32;                                                   \
            uint32_t so = SW128(rr * 128 + cb);                                    \
            long gi = (long)((k0) + rr) * F + f0 + (cb >> 1);                      \
            CP16(sbase + (bo) + OFF_BH + so, (const char*)&BhB[gi]);               \
            CP16(sbase + (bo) + OFF_BL + so, (const char*)&BlB[gi]);               \
        }                                                                          \
    } while (0)

    STAGE(0, 0);
    CP_COMMIT;

    int buf = 0;
    for (int kc = 0; kc < nchunk; kc++) {
        CP_WAIT0;
        __syncthreads();
        if (kc + 1 < nchunk) {
            STAGE((buf ^ 1) * BUF, (kc + 1) << 6);
            CP_COMMIT;
        }
        int bo = buf * BUF;
#pragma unroll
        for (int ks = 0; ks < 4; ks++) {
            uint32_t ah[4][4], al[4][4], bh[2][2], bl[2][2];
#pragma unroll
            for (int mt = 0; mt < 4; mt++) {
                uint32_t off = SW128((mw * 64 + mt * 16 + (lane & 15)) * 128 +
                                     ks * 32 + (lane >> 4) * 16);
                LDM4(ah[mt], sbase + bo + OFF_AH + off);
                LDM4(al[mt], sbase + bo + OFF_AL + off);
            }
#pragma unroll
            for (int nt = 0; nt < 2; nt++) {
                uint32_t off = SW128((ks * 16 + (lane & 15)) * 128 + fw * 32 + nt * 16);
                LDM2T(bh[nt], sbase + bo + OFF_BH + off);
                LDM2T(bl[nt], sbase + bo + OFF_BL + off);
            }
#pragma unroll
            for (int mt = 0; mt < 4; mt++) {
#pragma unroll
                for (int nt = 0; nt < 2; nt++) {
                    MMA_BF16(acc[mt][nt], ah[mt], bh[nt]);
                    MMA_BF16(acc[mt][nt], ah[mt], bl[nt]);
                    MMA_BF16(acc[mt][nt], al[mt], bh[nt]);
                }
            }
        }
        __syncthreads();
        buf ^= 1;
    }
#undef STAGE

#pragma unroll
    for (int mt = 0; mt < 4; mt++) {
        int gr = row0 + mw * 64 + mt * 16 + (lane >> 2);
#pragma unroll
        for (int nt = 0; nt < 2; nt++) {
            int gc = f0 + fw * 16 + nt * 8 + (lane & 3) * 2;
            if (gr < Mout)
                *(float2*)&C[((long)b * Mout + gr) * F + gc] =
                    make_float2(acc[mt][nt][0], acc[mt][nt][1]);
            if (gr + 8 < Mout)
                *(float2*)&C[((long)b * Mout + gr + 8) * F + gc] =
                    make_float2(acc[mt][nt][2], acc[mt][nt][3]);
        }
    }
}

// ------------ fused head: elu(p3@W1+b1) -> tanh(.@W2+b2), smem hm -----------
// dyn smem: w1[64*128] | w2[128*64] | b1[128] | b2[64] | hmS[128*100]
__global__ __launch_bounds__(256)
void head_kernel(const float* __restrict__ p3,
                 const float* __restrict__ f1w, const float* __restrict__ f1b,
                 const float* __restrict__ f2w, const float* __restrict__ f2b,
                 float* __restrict__ out, int Nn) {
    extern __shared__ float ds[];
    float* w1 = ds;                // 8192
    float* w2 = w1 + 8192;         // 8192
    float* b1s = w2 + 8192;        // 128
    float* b2s = b1s + 128;        // 64
    float* hmS = b2s + 64;         // 12800
    int n = blockIdx.x, b = blockIdx.y;
    int tid = threadIdx.x, tx = tid & 31, ty = tid >> 5;
    for (int q = tid; q < 8192; q += 256) { w1[q] = f1w[q]; w2[q] = f2w[q]; }
    if (tid < 128) b1s[tid] = f1b[tid];
    if (tid < 64) b2s[tid] = f2b[tid];
    __syncthreads();

    const float* xp = p3 + (long)(b * Nn + n) * (64 * TT);
    float* op = out + (long)(b * Nn + n) * (64 * TT);

    for (int tz = 0; tz < 2; tz++) {
        int toff = tz * 100;
        // phase 1: hm[o1=128][t=100] = elu(x @ W1 + b1)
        float acc1[16][4];
#pragma unroll
        for (int u = 0; u < 16; u++)
#pragma unroll
            for (int s = 0; s < 4; s++) acc1[u][s] = 0.0f;
#pragma unroll 4
        for (int j = 0; j < 64; j++) {
            float xr[4];
#pragma unroll
            for (int s = 0; s < 4; s++) {
                int t = tx + 32 * s;
                xr[s] = xp[j * TT + toff + (t < 100 ? t : 0)];
            }
#pragma unroll
            for (int u = 0; u < 16; u++) {
                float w = w1[j * 128 + ty + 8 * u];
#pragma unroll
                for (int s = 0; s < 4; s++) acc1[u][s] += w * xr[s];
            }
        }
        __syncthreads();
#pragma unroll
        for (int u = 0; u < 16; u++) {
            int o = ty + 8 * u;
            float bb = b1s[o];
#pragma unroll
            for (int s = 0; s < 4; s++) {
                int t = tx + 32 * s;
                if (t < 100) {
                    float v = acc1[u][s] + bb;
                    v = v > 0.0f ? v : expm1f(v);
                    hmS[o * 100 + t] = v;
                }
            }
        }
        __syncthreads();
        // phase 2: out[o2=64][t=100] = tanh(hm @ W2 + b2)
        float acc2[8][4];
#pragma unroll
        for (int u = 0; u < 8; u++)
#pragma unroll
            for (int s = 0; s < 4; s++) acc2[u][s] = 0.0f;
#pragma unroll 4
        for (int j = 0; j < 128; j++) {
            float xr[4];
#pragma unroll
            for (int s = 0; s < 4; s++) {
                int t = tx + 32 * s;
                xr[s] = hmS[j * 100 + (t < 100 ? t : 0)];
            }
#pragma unroll
            for (int u = 0; u < 8; u++) {
                float w = w2[j * 64 + ty + 8 * u];
#pragma unroll
                for (int s = 0; s < 4; s++) acc2[u][s] += w * xr[s];
            }
        }
#pragma unroll
        for (int u = 0; u < 8; u++) {
            int o = ty + 8 * u;
            float bb = b2s[o];
#pragma unroll
            for (int s = 0; s < 4; s++) {
                int t = tx + 32 * s;
                if (t < 100) op[o * TT + toff + t] = tanhf(acc2[u][s] + bb);
            }
        }
        __syncthreads();
    }
}

// -------------------------------- launch ------------------------------------
#define GETSYM(var, sym)                                       \
    do {                                                       \
        void* _p = nullptr;                                    \
        cudaGetSymbolAddress(&_p, sym);                        \
        var = (decltype(var))_p;                               \
    } while (0)

extern "C" void kernel_launch(void* const* d_in, const int* in_sizes, int n_in,
                              void* d_out, int out_size) {
    (void)in_sizes; (void)n_in; (void)out_size;
    const float* x   = (const float*)d_in[0];
    const int*   ei0 = (const int*)d_in[1];
    const float* ea0 = (const float*)d_in[2];
    const int*   ei1 = (const int*)d_in[3];
    const float* ea1 = (const float*)d_in[4];
    const int*   ei2 = (const int*)d_in[5];
    const float* ea2 = (const float*)d_in[6];
    const float* A1  = (const float*)d_in[7];
    const float* Wk1 = (const float*)d_in[8];
    const float* Wr1 = (const float*)d_in[9];
    const float* b1  = (const float*)d_in[10];
    const float* A2  = (const float*)d_in[11];
    const float* Wk2 = (const float*)d_in[12];
    const float* Wr2 = (const float*)d_in[13];
    const float* b2  = (const float*)d_in[14];
    const float* A3  = (const float*)d_in[15];
    const float* Wk3 = (const float*)d_in[16];
    const float* Wr3 = (const float*)d_in[17];
    const float* b3  = (const float*)d_in[18];
    const float* P01 = (const float*)d_in[19];
    const float* P12 = (const float*)d_in[20];
    const float* P23 = (const float*)d_in[21];
    const float* f1w = (const float*)d_in[22];
    const float* f1b = (const float*)d_in[23];
    const float* f2w = (const float*)d_in[24];
    const float* f2b = (const float*)d_in[25];

    const int N0 = 2048, N1 = 512, N2 = 128, N3 = 64;

    float *p1, *p2, *p3;
    __nv_bfloat16 *A1h, *A1l, *A2h, *A2l, *A3h, *A3l, *Bh, *Bl;
    int *off0, *perm0, *off1, *perm1, *off2, *perm2;
    float *inv0, *inv1, *inv2;
    GETSYM(p1, g_p1); GETSYM(p2, g_p2); GETSYM(p3, g_p3);
    GETSYM(A1h, g_A1h); GETSYM(A1l, g_A1l);
    GETSYM(A2h, g_A2h); GETSYM(A2l, g_A2l);
    GETSYM(A3h, g_A3h); GETSYM(A3l, g_A3l);
    GETSYM(Bh, g_Bh); GETSYM(Bl, g_Bl);
    GETSYM(off0, g_off0); GETSYM(perm0, g_perm0);
    GETSYM(off1, g_off1); GETSYM(perm1, g_perm1);
    GETSYM(off2, g_off2); GETSYM(perm2, g_perm2);
    GETSYM(inv0, g_inv0); GETSYM(inv1, g_inv1); GETSYM(inv2, g_inv2);

    const int SMEM_GEMM = 98304;
    cudaFuncSetAttribute(mma_gemm_kernel, cudaFuncAttributeMaxDynamicSharedMemorySize,
                         SMEM_GEMM);
    const int SMEM_F1 = (4 * 16 * 32 + 32 + 3 * 16 * TT) * 4;
    const int SMEM_F2 = (4 * 32 * 64 + 64 + 3 * 32 * TT) * 4;
    cudaFuncSetAttribute((const void*)gcnf_kernel<16, 32>,
                         cudaFuncAttributeMaxDynamicSharedMemorySize, SMEM_F1);
    cudaFuncSetAttribute((const void*)gcnf_kernel<32, 64>,
                         cudaFuncAttributeMaxDynamicSharedMemorySize, SMEM_F2);
    const int SMEM_HEAD = (8192 + 8192 + 128 + 64 + 12800) * 4;  // ~117KB
    cudaFuncSetAttribute(head_kernel, cudaFuncAttributeMaxDynamicSharedMemorySize,
                         SMEM_HEAD);

    // ---- setup: CSR (3 blocks) + splitA (rest), one launch ----
    const int SPLIT_ELEMS = 512 * 2048 + 128 * 512 + 128 * 128;
    setup_kernel<<<3 + (SPLIT_ELEMS + 1023) / 1024, 1024>>>(
        ei0, ei1, ei2, off0, perm0, inv0, off1, perm1, inv1, off2, perm2, inv2,
        P01, P12, P23, A1h, A1l, A2h, A2l, A3h, A3l);

    // ---- level 0->1 GCN : x -> B operand (bf16 hi/lo), both batches ----
    gcn1_kernel<<<N0, 256>>>(x, ea0, A1, Wk1, Wr1, b1, ei0, off0, perm0, inv0, Bh, Bl);

    // ---- pool1: p1 = P01 @ h1 ; M=512, K=2048, F=3200 ----
    mma_gemm_kernel<<<dim3(3200 / 64, 512 / 128, 2), 256, SMEM_GEMM>>>(
        A1h, A1l, Bh, Bl, p1, 512, 2048, 3200);

    // ---- level 1->2 GCN (fused) ----
    gcnf_kernel<16, 32><<<dim3(N1, 2), 256, SMEM_F1>>>(
        p1, ea1, A2, Wk2, Wr2, b2, ei1, off1, perm1, inv1, Bh, Bl, N1);

    // ---- pool2: M=128, K=512, F=6400 ----
    mma_gemm_kernel<<<dim3(6400 / 64, 1, 2), 256, SMEM_GEMM>>>(
        A2h, A2l, Bh, Bl, p2, 128, 512, 6400);

    // ---- level 2->3 GCN (fused) ----
    gcnf_kernel<32, 64><<<dim3(N2, 2), 256, SMEM_F2>>>(
        p2, ea2, A3, Wk3, Wr3, b3, ei2, off2, perm2, inv2, Bh, Bl, N2);

    // ---- pool3: M=64 (padded 128), K=128, F=12800 ----
    mma_gemm_kernel<<<dim3(12800 / 64, 1, 2), 256, SMEM_GEMM>>>(
        A3h, A3l, Bh, Bl, p3, 64, 128, 12800);

    // ---- fused head ----
    head_kernel<<<dim3(N3, 2), 256, SMEM_HEAD>>>(
        p3, f1w, f1b, f2w, f2b, (float*)d_out, N3);
}

// round 8
// speedup vs baseline: 3.3656x; 1.0495x over previous
#include <cuda_runtime.h>
#include <cuda_bf16.h>
#include <cstdint>

// ============================================================================
// Graph_ODE_RNN — 8-launch pipeline; GCN combine now on tensor cores:
//  [csr+splitA+Wt] -> gcn1 -> pool1 -> gcnf1 -> pool2 -> gcnf2 -> pool3 -> head
// ============================================================================

#define TT 200

// ---------------- static scratch (no allocation allowed) -------------------
__device__ float g_p1[2 * 512 * 16 * TT];
__device__ float g_p2[2 * 128 * 32 * TT];
__device__ float g_p3[2 * 64 * 64 * TT];

__device__ __nv_bfloat16 g_A1h[512 * 2048], g_A1l[512 * 2048];
__device__ __nv_bfloat16 g_A2h[128 * 512],  g_A2l[128 * 512];
__device__ __nv_bfloat16 g_A3h[128 * 128],  g_A3l[128 * 128];  // M padded 64->128
__device__ __nv_bfloat16 g_Bh[2 * 2048 * 3200], g_Bl[2 * 2048 * 3200];

// combine weights W^T, bf16 hi/lo, chunk layout [kc][m][64]
__device__ __nv_bfloat16 g_Wt1h[32 * 64],  g_Wt1l[32 * 64];      // level2: COUT=32,K=64
__device__ __nv_bfloat16 g_Wt2h[2 * 64 * 64], g_Wt2l[2 * 64 * 64];  // level3: COUT=64,K=128

__device__ int g_off0[2049], g_perm0[16384];
__device__ int g_off1[513],  g_perm1[8192];
__device__ int g_off2[129],  g_perm2[2048];
__device__ float g_inv0[2048], g_inv1[512], g_inv2[128];

// ---------------------------- helpers ---------------------------------------
__device__ __forceinline__ uint32_t smem_u32(const void* p) {
    uint32_t a;
    asm("{ .reg .u64 t; cvta.to.shared.u64 t, %1; cvt.u32.u64 %0, t; }"
        : "=r"(a) : "l"(p));
    return a;
}

#define SW128(x) ((x) ^ (((x) >> 3) & 0x70))

#define LDM4(r, addr)                                                            \
    asm volatile("ldmatrix.sync.aligned.m8n8.x4.shared.b16 {%0,%1,%2,%3}, [%4];" \
                 : "=r"((r)[0]), "=r"((r)[1]), "=r"((r)[2]), "=r"((r)[3])        \
                 : "r"(addr))

#define LDM2T(r, addr)                                                           \
    asm volatile("ldmatrix.sync.aligned.m8n8.x2.trans.shared.b16 {%0,%1}, [%2];" \
                 : "=r"((r)[0]), "=r"((r)[1]) : "r"(addr))

#define MMA_BF16(c, a, bb)                                                       \
    asm volatile("mma.sync.aligned.m16n8k16.row.col.f32.bf16.bf16.f32 "          \
                 "{%0,%1,%2,%3}, {%4,%5,%6,%7}, {%8,%9}, {%0,%1,%2,%3};"         \
                 : "+f"((c)[0]), "+f"((c)[1]), "+f"((c)[2]), "+f"((c)[3])        \
                 : "r"((a)[0]), "r"((a)[1]), "r"((a)[2]), "r"((a)[3]),           \
                   "r"((bb)[0]), "r"((bb)[1]))

#define CP16(dst, src)                                                           \
    asm volatile("cp.async.cg.shared.global [%0], [%1], 16;" :: "r"(dst), "l"(src))
#define CP_COMMIT asm volatile("cp.async.commit_group;" ::: "memory")
#define CP_WAIT0  asm volatile("cp.async.wait_group 0;" ::: "memory")

// -------------- merged setup: 3 CSR blocks + split/Wt blocks ----------------
__global__ __launch_bounds__(1024)
void setup_kernel(const int* e0, const int* e1, const int* e2,
                  int* o0, int* p0, float* v0,
                  int* o1, int* p1, float* v1,
                  int* o2, int* p2, float* v2,
                  const float* __restrict__ P01, const float* __restrict__ P12,
                  const float* __restrict__ P23,
                  __nv_bfloat16* A1h, __nv_bfloat16* A1l,
                  __nv_bfloat16* A2h, __nv_bfloat16* A2l,
                  __nv_bfloat16* A3h, __nv_bfloat16* A3l,
                  const float* __restrict__ Wk2, const float* __restrict__ Wr2,
                  const float* __restrict__ Wk3, const float* __restrict__ Wr3,
                  __nv_bfloat16* Wt1h, __nv_bfloat16* Wt1l,
                  __nv_bfloat16* Wt2h, __nv_bfloat16* Wt2l) {
    int tid = threadIdx.x;
    if (blockIdx.x >= 3) {
        const long S1 = 512 * 2048, S2 = 128 * 512, S3 = 128 * 128;
        const long W1 = 32 * 64, W2 = 2 * 64 * 64;
        long i = (long)(blockIdx.x - 3) * 1024 + tid;
        float v; __nv_bfloat16 *H, *L; long o;
        if (i < S1) { o = i; v = P01[o]; H = A1h; L = A1l; }
        else if (i < S1 + S2) { o = i - S1; v = P12[o]; H = A2h; L = A2l; }
        else if (i < S1 + S2 + S3) {
            o = i - S1 - S2;
            v = ((o >> 7) < 64) ? P23[o] : 0.0f;
            H = A3h; L = A3l;
        } else if (i < S1 + S2 + S3 + W1) {
            o = i - S1 - S2 - S3;
            int m = (int)(o >> 6), kk = (int)(o & 63);
            v = (kk < 48) ? Wk2[kk * 32 + m] : Wr2[(kk - 48) * 32 + m];
            H = Wt1h; L = Wt1l;
        } else if (i < S1 + S2 + S3 + W1 + W2) {
            o = i - S1 - S2 - S3 - W1;
            int kc = (int)(o >> 12), rem = (int)(o & 4095);
            int m = rem >> 6, kk = rem & 63;
            int j = kc * 64 + kk;
            v = (j < 96) ? Wk3[j * 64 + m] : Wr3[(j - 96) * 64 + m];
            H = Wt2h; L = Wt2l;
        } else return;
        __nv_bfloat16 hi = __float2bfloat16(v);
        H[o] = hi;
        L[o] = __float2bfloat16(v - __bfloat162float(hi));
        return;
    }
    // ---- CSR part: one block per level ----
    __shared__ int sa[2048];
    __shared__ int sb[2048];
    __shared__ int scur[2048];
    int lvl = blockIdx.x;
    const int* dst = lvl == 0 ? e0 + 16384 : (lvl == 1 ? e1 + 8192 : e2 + 2048);
    int E = lvl == 0 ? 16384 : (lvl == 1 ? 8192 : 2048);
    int N = lvl == 0 ? 2048 : (lvl == 1 ? 512 : 128);
    int* off = lvl == 0 ? o0 : (lvl == 1 ? o1 : o2);
    int* perm = lvl == 0 ? p0 : (lvl == 1 ? p1 : p2);
    float* inv = lvl == 0 ? v0 : (lvl == 1 ? v1 : v2);

    for (int q = tid; q < 2048; q += 1024) sa[q] = 0;
    __syncthreads();
    for (int i = tid; i < E; i += 1024) atomicAdd(&sa[dst[i]], 1);
    __syncthreads();
    for (int q = tid; q < 2048; q += 1024) {
        int dg = sa[q];
        sb[q] = dg;
        if (q < N) inv[q] = 1.0f / (float)(dg > 0 ? dg : 1);
    }
    __syncthreads();
    int* pc = sa;
    int* pn = scur;
    for (int d = 1; d < 2048; d <<= 1) {
        for (int q = tid; q < 2048; q += 1024) {
            int v = pc[q];
            if (q >= d) v += pc[q - d];
            pn[q] = v;
        }
        __syncthreads();
        int* t = pc; pc = pn; pn = t;
    }
    for (int q = tid; q < N; q += 1024) {
        int o = (q == 0) ? 0 : pc[q - 1];
        off[q] = o;
        pn[q] = o;
    }
    if (tid == 0) off[N] = pc[N - 1];
    __syncthreads();
    for (int i = tid; i < E; i += 1024) {
        int p = atomicAdd(&pn[dst[i]], 1);
        perm[p] = i;
    }
    __syncthreads();
    for (int n = tid; n < N; n += 1024) {
        int a = (n == 0) ? 0 : pc[n - 1];
        int b = pc[n];
        for (int k = a + 1; k < b; k++) {
            int v = perm[k];
            int j = k - 1;
            while (j >= a && perm[j] > v) { perm[j + 1] = perm[j]; j--; }
            perm[j + 1] = v;
        }
    }
}

// ------- level-1 GCN (both batches per block, staged edge weights) ----------
__global__ __launch_bounds__(256)
void gcn1_kernel(const float* __restrict__ x, const float* __restrict__ ea,
                 const float* __restrict__ Amat,
                 const float* __restrict__ Wk, const float* __restrict__ Wr,
                 const float* __restrict__ bias,
                 const int* __restrict__ srcArr, const int* __restrict__ off,
                 const int* __restrict__ perm, const float* __restrict__ inv_cnt,
                 __nv_bfloat16* __restrict__ Bh, __nv_bfloat16* __restrict__ Bl) {
    __shared__ float sA[9];
    __shared__ float sW[80];
    __shared__ int sSrc[64];
    __shared__ float sEw[64 * 3];
    const int N0 = 2048;
    int n = blockIdx.x;
    int t = threadIdx.x;
    if (t < 9) sA[t] = Amat[t];
    if (t < 48) sW[t] = Wk[t];
    else if (t < 64) sW[t] = Wr[t - 48];
    else if (t < 80) sW[t] = bias[t - 64];
    __syncthreads();

    float a0[3] = {0.f, 0.f, 0.f};
    float a1[3] = {0.f, 0.f, 0.f};
    int e0 = off[n], e1 = off[n + 1];
    for (int base = e0; base < e1; base += 64) {
        int cnt = min(64, e1 - base);
        __syncthreads();
        if (t < cnt) {
            int e = perm[base + t];
            sSrc[t] = srcArr[e];
            float u0 = ea[e * 3 + 0], u1 = ea[e * 3 + 1], u2 = ea[e * 3 + 2];
            float w0 = u0 * sA[0] + u1 * sA[3] + u2 * sA[6];
            float w1 = u0 * sA[1] + u1 * sA[4] + u2 * sA[7];
            float w2 = u0 * sA[2] + u1 * sA[5] + u2 * sA[8];
            float m = fmaxf(w0, fmaxf(w1, w2));
            float q0 = __expf(w0 - m), q1 = __expf(w1 - m), q2 = __expf(w2 - m);
            float qi = 1.0f / (q0 + q1 + q2);
            sEw[t * 3 + 0] = q0 * qi;
            sEw[t * 3 + 1] = q1 * qi;
            sEw[t * 3 + 2] = q2 * qi;
        }
        __syncthreads();
        if (t < TT) {
            for (int j = 0; j < cnt; j++) {
                int src = sSrc[j];
                float w0 = sEw[j * 3 + 0], w1 = sEw[j * 3 + 1], w2 = sEw[j * 3 + 2];
                float va = x[src * TT + t];
                float vb = x[(N0 + src) * TT + t];
                a0[0] += w0 * va; a0[1] += w1 * va; a0[2] += w2 * va;
                a1[0] += w0 * vb; a1[1] += w1 * vb; a1[2] += w2 * vb;
            }
        }
    }
    if (t >= TT) return;
    float inv = inv_cnt[n];
#pragma unroll
    for (int k = 0; k < 3; k++) { a0[k] *= inv; a1[k] *= inv; }
    float xo0 = x[n * TT + t];
    float xo1 = x[(N0 + n) * TT + t];
    long base0 = ((long)n * 16) * TT + t;
    long base1 = ((long)(N0 + n) * 16) * TT + t;
#pragma unroll
    for (int o = 0; o < 16; o++) {
        float v = a0[0] * sW[o] + a0[1] * sW[16 + o] + a0[2] * sW[32 + o] +
                  xo0 * sW[48 + o] + sW[64 + o];
        v = v > 0.0f ? v : expm1f(v);
        __nv_bfloat16 hi = __float2bfloat16(v);
        Bh[base0 + (long)o * TT] = hi;
        Bl[base0 + (long)o * TT] = __float2bfloat16(v - __bfloat162float(hi));
        v = a1[0] * sW[o] + a1[1] * sW[16 + o] + a1[2] * sW[32 + o] +
            xo1 * sW[48 + o] + sW[64 + o];
        v = v > 0.0f ? v : expm1f(v);
        hi = __float2bfloat16(v);
        Bh[base1 + (long)o * TT] = hi;
        Bl[base1 + (long)o * TT] = __float2bfloat16(v - __bfloat162float(hi));
    }
}

// ----- fused GCN level: smem gather + TENSOR-CORE combine, bf16 hi/lo out ----
// dyn smem: sWh[KCH*COUT*128B] | sWl[same] | chi[K4*400B] | clo[K4*400B] | sbias
template <int CIN, int COUT>
__global__ __launch_bounds__(256)
void gcnf_kernel(const float* __restrict__ xin, const float* __restrict__ ea,
                 const float* __restrict__ Amat,
                 const __nv_bfloat16* __restrict__ Wth,
                 const __nv_bfloat16* __restrict__ Wtl,
                 const float* __restrict__ bias,
                 const int* __restrict__ srcArr, const int* __restrict__ off,
                 const int* __restrict__ perm, const float* __restrict__ inv_cnt,
                 __nv_bfloat16* __restrict__ Bh, __nv_bfloat16* __restrict__ Bl, int Nn) {
    constexpr int K4 = 4 * CIN;       // cat rows
    constexpr int KCH = K4 / 64;      // 64-wide k chunks for W layout
    constexpr int MT = COUT / 16;     // m-tiles
    constexpr int KQ = K4 / 16;       // k16 steps
    extern __shared__ char dsm[];
    const uint32_t sWh_o = 0;
    const uint32_t sWl_o = KCH * COUT * 128;
    const uint32_t chi_o = 2 * KCH * COUT * 128;
    const uint32_t clo_o = chi_o + K4 * 400;
    float* sbias = (float*)(dsm + clo_o + K4 * 400);
    uint32_t sb = smem_u32(dsm);
    __shared__ float sA[9];
    __shared__ int sSrc[64];
    __shared__ float sEw[64 * 3];

    int n = blockIdx.x, b = blockIdx.y;
    int tid = threadIdx.x, lane = tid & 31, w = tid >> 5;
    int tx = lane, ty = w;
    if (tid < 9) sA[tid] = Amat[tid];
    if (tid < COUT) sbias[tid] = bias[tid];
    // load W^T into smem, swizzled per 128B row
    {
        const uint4* WhG = (const uint4*)Wth;
        const uint4* WlG = (const uint4*)Wtl;
        for (int q = tid; q < KCH * COUT * 8; q += 256) {
            int kc = q / (COUT * 8);
            int rem = q - kc * (COUT * 8);
            int m = rem >> 3, seg = rem & 7;
            uint32_t d = kc * COUT * 128 + SW128(m * 128 + seg * 16);
            *(uint4*)(dsm + sWh_o + d) = WhG[q];
            *(uint4*)(dsm + sWl_o + d) = WlG[q];
        }
    }
    __syncthreads();

    // ---- gather: acc[k][u][s], element (ch = ty+8u, t = tx+32s) ----
    constexpr int U = CIN / 8;
    float acc[3][U][7];
#pragma unroll
    for (int k = 0; k < 3; k++)
#pragma unroll
        for (int u = 0; u < U; u++)
#pragma unroll
            for (int s = 0; s < 7; s++) acc[k][u][s] = 0.0f;

    int e0 = off[n], e1 = off[n + 1];
    for (int base = e0; base < e1; base += 64) {
        int cnt = min(64, e1 - base);
        __syncthreads();
        if (tid < cnt) {
            int e = perm[base + tid];
            sSrc[tid] = srcArr[e];
            float u0 = ea[e * 3 + 0], u1 = ea[e * 3 + 1], u2 = ea[e * 3 + 2];
            float w0 = u0 * sA[0] + u1 * sA[3] + u2 * sA[6];
            float w1 = u0 * sA[1] + u1 * sA[4] + u2 * sA[7];
            float w2 = u0 * sA[2] + u1 * sA[5] + u2 * sA[8];
            float m = fmaxf(w0, fmaxf(w1, w2));
            float q0 = __expf(w0 - m), q1 = __expf(w1 - m), q2 = __expf(w2 - m);
            float qi = 1.0f / (q0 + q1 + q2);
            sEw[tid * 3 + 0] = q0 * qi;
            sEw[tid * 3 + 1] = q1 * qi;
            sEw[tid * 3 + 2] = q2 * qi;
        }
        __syncthreads();
        for (int j = 0; j < cnt; j++) {
            float q0 = sEw[j * 3 + 0], q1 = sEw[j * 3 + 1], q2 = sEw[j * 3 + 2];
            const float* xp = xin + (long)(b * Nn + sSrc[j]) * (CIN * TT);
#pragma unroll
            for (int u = 0; u < U; u++) {
#pragma unroll
                for (int s = 0; s < 7; s++) {
                    int t = tx + 32 * s;
                    float v = xp[(ty + 8 * u) * TT + (t < TT ? t : 0)];
                    acc[0][u][s] += q0 * v;
                    acc[1][u][s] += q1 * v;
                    acc[2][u][s] += q2 * v;
                }
            }
        }
    }

    // ---- build cat = [G | x] in bf16 hi/lo smem ----
    float inv = inv_cnt[n];
    __syncthreads();
    __nv_bfloat16* chi = (__nv_bfloat16*)(dsm + chi_o);
    __nv_bfloat16* clo = (__nv_bfloat16*)(dsm + clo_o);
#pragma unroll
    for (int k = 0; k < 3; k++)
#pragma unroll
        for (int u = 0; u < U; u++)
#pragma unroll
            for (int s = 0; s < 7; s++) {
                int t = tx + 32 * s;
                if (t < TT) {
                    int row = k * CIN + ty + 8 * u;
                    float v = acc[k][u][s] * inv;
                    __nv_bfloat16 hi = __float2bfloat16(v);
                    chi[row * TT + t] = hi;
                    clo[row * TT + t] = __float2bfloat16(v - __bfloat162float(hi));
                }
            }
    {
        const float* xp = xin + (long)(b * Nn + n) * (CIN * TT);
#pragma unroll
        for (int u = 0; u < U; u++)
#pragma unroll
            for (int s = 0; s < 7; s++) {
                int t = tx + 32 * s;
                if (t < TT) {
                    int c = ty + 8 * u;
                    float v = xp[c * TT + t];
                    int row = 3 * CIN + c;
                    __nv_bfloat16 hi = __float2bfloat16(v);
                    chi[row * TT + t] = hi;
                    clo[row * TT + t] = __float2bfloat16(v - __bfloat162float(hi));
                }
            }
    }
    __syncthreads();

    // ---- combine on tensor cores: out[COUT x 200] = Wt @ cat, bf16x3 ----
    int mt = w % MT;
    int ntStart = w / MT;
    constexpr int NTSTRIDE = 8 / MT;

    uint32_t ah[KQ][4], al[KQ][4];
#pragma unroll
    for (int kq = 0; kq < KQ; kq++) {
        int kc = kq >> 2, ks = kq & 3;
        uint32_t offA = kc * COUT * 128 +
                        SW128((mt * 16 + (lane & 15)) * 128 + ks * 32 + (lane >> 4) * 16);
        LDM4(ah[kq], sb + sWh_o + offA);
        LDM4(al[kq], sb + sWl_o + offA);
    }

    long obase = (long)(b * Nn + n) * (COUT * TT);
    int o0 = mt * 16 + (lane >> 2);
    float bb0 = sbias[o0], bb1 = sbias[o0 + 8];
    for (int nt = ntStart; nt < 25; nt += NTSTRIDE) {
        float c[4] = {0.f, 0.f, 0.f, 0.f};
#pragma unroll
        for (int kq = 0; kq < KQ; kq++) {
            uint32_t offB = (uint32_t)(kq * 16 + (lane & 15)) * 400 + nt * 16;
            uint32_t bh[2], bl[2];
            LDM2T(bh, sb + chi_o + offB);
            LDM2T(bl, sb + clo_o + offB);
            MMA_BF16(c, ah[kq], bh);
            MMA_BF16(c, ah[kq], bl);
            MMA_BF16(c, al[kq], bh);
        }
        int t0 = nt * 8 + (lane & 3) * 2;
        // row o0
        float v0 = c[0] + bb0; v0 = v0 > 0.f ? v0 : expm1f(v0);
        float v1 = c[1] + bb0; v1 = v1 > 0.f ? v1 : expm1f(v1);
        __nv_bfloat16 h0 = __float2bfloat16(v0), h1 = __float2bfloat16(v1);
        __nv_bfloat16 l0 = __float2bfloat16(v0 - __bfloat162float(h0));
        __nv_bfloat16 l1 = __float2bfloat16(v1 - __bfloat162float(h1));
        *(uint32_t*)&Bh[obase + (long)o0 * TT + t0] =
            (uint32_t)__bfloat16_as_ushort(h0) | ((uint32_t)__bfloat16_as_ushort(h1) << 16);
        *(uint32_t*)&Bl[obase + (long)o0 * TT + t0] =
            (uint32_t)__bfloat16_as_ushort(l0) | ((uint32_t)__bfloat16_as_ushort(l1) << 16);
        // row o0 + 8
        float v2 = c[2] + bb1; v2 = v2 > 0.f ? v2 : expm1f(v2);
        float v3 = c[3] + bb1; v3 = v3 > 0.f ? v3 : expm1f(v3);
        __nv_bfloat16 h2 = __float2bfloat16(v2), h3 = __float2bfloat16(v3);
        __nv_bfloat16 l2 = __float2bfloat16(v2 - __bfloat162float(h2));
        __nv_bfloat16 l3 = __float2bfloat16(v3 - __bfloat162float(h3));
        *(uint32_t*)&Bh[obase + (long)(o0 + 8) * TT + t0] =
            (uint32_t)__bfloat16_as_ushort(h2) | ((uint32_t)__bfloat16_as_ushort(h3) << 16);
        *(uint32_t*)&Bl[obase + (long)(o0 + 8) * TT + t0] =
            (uint32_t)__bfloat16_as_ushort(l2) | ((uint32_t)__bfloat16_as_ushort(l3) << 16);
    }
}

// ------- bf16x3 GEMM, cp.async double-buffered, B read via trans-ldmatrix ----
__global__ __launch_bounds__(256)
void mma_gemm_kernel(const __nv_bfloat16* __restrict__ Ahi, const __nv_bfloat16* __restrict__ Alo,
                     const __nv_bfloat16* __restrict__ Bhi, const __nv_bfloat16* __restrict__ Blo,
                     float* __restrict__ C, int Mout, int K, int F) {
    extern __shared__ char smem[];
    const int BUF = 49152;
    const int OFF_AH = 0, OFF_AL = 16384, OFF_BH = 32768, OFF_BL = 40960;
    uint32_t sbase = smem_u32(smem);
    int tid = threadIdx.x, lane = tid & 31, w = tid >> 5;
    int mw = w & 1, fw = w >> 1;
    int f0 = blockIdx.x * 64, row0 = blockIdx.y * 128, b = blockIdx.z;

    const __nv_bfloat16* BhB = Bhi + (long)b * K * F;
    const __nv_bfloat16* BlB = Blo + (long)b * K * F;

    float acc[4][2][4];
#pragma unroll
    for (int mt = 0; mt < 4; mt++)
#pragma unroll
        for (int nt = 0; nt < 2; nt++)
#pragma unroll
            for (int q = 0; q < 4; q++) acc[mt][nt][q] = 0.0f;

    int r = tid >> 3, cb = (tid & 7) * 16;
    int nchunk = K >> 6;

#define STAGE(bo, k0)                                                              \
    do {                                                                           \
        _Pragma("unroll")                                                          \
        for (int i = 0; i < 4; i++) {                                              \
            int rr = r + i * 32;                                                   \
            uint32_t so = SW128(rr * 128 + cb);                                    \
            CP16(sbase + (bo) + OFF_AH + so,                                       \
                 (const char*)&Ahi[(long)(row0 + rr) * K + (k0) + (cb >> 1)]);     \
            CP16(sbase + (bo) + OFF_AL + so,                                       \
                 (const char*)&Alo[(long)(row0 + rr) * K + (k0) + (cb >> 1)]);     \
        }                                                                          \
        _Pragma("unroll")                                                          \
        for (int i = 0; i < 2; i++) {                                              \
            int rr = r + i * 32;                                                   \
            uint32_t so = SW128(rr * 128 + cb);                                    \
            long gi = (long)((k0) + rr) * F + f0 + (cb >> 1);                      \
            CP16(sbase + (bo) + OFF_BH + so, (const char*)&BhB[gi]);               \
            CP16(sbase + (bo) + OFF_BL + so, (const char*)&BlB[gi]);               \
        }                                                                          \
    } while (0)

    STAGE(0, 0);
    CP_COMMIT;

    int buf = 0;
    for (int kc = 0; kc < nchunk; kc++) {
        CP_WAIT0;
        __syncthreads();
        if (kc + 1 < nchunk) {
            STAGE((buf ^ 1) * BUF, (kc + 1) << 6);
            CP_COMMIT;
        }
        int bo = buf * BUF;
#pragma unroll
        for (int ks = 0; ks < 4; ks++) {
            uint32_t ah[4][4], al[4][4], bh[2][2], bl[2][2];
#pragma unroll
            for (int mt = 0; mt < 4; mt++) {
                uint32_t off = SW128((mw * 64 + mt * 16 + (lane & 15)) * 128 +
                                     ks * 32 + (lane >> 4) * 16);
                LDM4(ah[mt], sbase + bo + OFF_AH + off);
                LDM4(al[mt], sbase + bo + OFF_AL + off);
            }
#pragma unroll
            for (int nt = 0; nt < 2; nt++) {
                uint32_t off = SW128((ks * 16 + (lane & 15)) * 128 + fw * 32 + nt * 16);
                LDM2T(bh[nt], sbase + bo + OFF_BH + off);
                LDM2T(bl[nt], sbase + bo + OFF_BL + off);
            }
#pragma unroll
            for (int mt = 0; mt < 4; mt++) {
#pragma unroll
                for (int nt = 0; nt < 2; nt++) {
                    MMA_BF16(acc[mt][nt], ah[mt], bh[nt]);
                    MMA_BF16(acc[mt][nt], ah[mt], bl[nt]);
                    MMA_BF16(acc[mt][nt], al[mt], bh[nt]);
                }
            }
        }
        __syncthreads();
        buf ^= 1;
    }
#undef STAGE

#pragma unroll
    for (int mt = 0; mt < 4; mt++) {
        int gr = row0 + mw * 64 + mt * 16 + (lane >> 2);
#pragma unroll
        for (int nt = 0; nt < 2; nt++) {
            int gc = f0 + fw * 16 + nt * 8 + (lane & 3) * 2;
            if (gr < Mout)
                *(float2*)&C[((long)b * Mout + gr) * F + gc] =
                    make_float2(acc[mt][nt][0], acc[mt][nt][1]);
            if (gr + 8 < Mout)
                *(float2*)&C[((long)b * Mout + gr + 8) * F + gc] =
                    make_float2(acc[mt][nt][2], acc[mt][nt][3]);
        }
    }
}

// ------------ fused head: elu(p3@W1+b1) -> tanh(.@W2+b2), smem hm -----------
__global__ __launch_bounds__(256)
void head_kernel(const float* __restrict__ p3,
                 const float* __restrict__ f1w, const float* __restrict__ f1b,
                 const float* __restrict__ f2w, const float* __restrict__ f2b,
                 float* __restrict__ out, int Nn) {
    extern __shared__ float ds[];
    float* w1 = ds;
    float* w2 = w1 + 8192;
    float* b1s = w2 + 8192;
    float* b2s = b1s + 128;
    float* hmS = b2s + 64;
    int n = blockIdx.x, b = blockIdx.y;
    int tid = threadIdx.x, tx = tid & 31, ty = tid >> 5;
    for (int q = tid; q < 8192; q += 256) { w1[q] = f1w[q]; w2[q] = f2w[q]; }
    if (tid < 128) b1s[tid] = f1b[tid];
    if (tid < 64) b2s[tid] = f2b[tid];
    __syncthreads();

    const float* xp = p3 + (long)(b * Nn + n) * (64 * TT);
    float* op = out + (long)(b * Nn + n) * (64 * TT);

    for (int tz = 0; tz < 2; tz++) {
        int toff = tz * 100;
        float acc1[16][4];
#pragma unroll
        for (int u = 0; u < 16; u++)
#pragma unroll
            for (int s = 0; s < 4; s++) acc1[u][s] = 0.0f;
#pragma unroll 4
        for (int j = 0; j < 64; j++) {
            float xr[4];
#pragma unroll
            for (int s = 0; s < 4; s++) {
                int t = tx + 32 * s;
                xr[s] = xp[j * TT + toff + (t < 100 ? t : 0)];
            }
#pragma unroll
            for (int u = 0; u < 16; u++) {
                float w = w1[j * 128 + ty + 8 * u];
#pragma unroll
                for (int s = 0; s < 4; s++) acc1[u][s] += w * xr[s];
            }
        }
        __syncthreads();
#pragma unroll
        for (int u = 0; u < 16; u++) {
            int o = ty + 8 * u;
            float bb = b1s[o];
#pragma unroll
            for (int s = 0; s < 4; s++) {
                int t = tx + 32 * s;
                if (t < 100) {
                    float v = acc1[u][s] + bb;
                    v = v > 0.0f ? v : expm1f(v);
                    hmS[o * 100 + t] = v;
                }
            }
        }
        __syncthreads();
        float acc2[8][4];
#pragma unroll
        for (int u = 0; u < 8; u++)
#pragma unroll
            for (int s = 0; s < 4; s++) acc2[u][s] = 0.0f;
#pragma unroll 4
        for (int j = 0; j < 128; j++) {
            float xr[4];
#pragma unroll
            for (int s = 0; s < 4; s++) {
                int t = tx + 32 * s;
                xr[s] = hmS[j * 100 + (t < 100 ? t : 0)];
            }
#pragma unroll
            for (int u = 0; u < 8; u++) {
                float w = w2[j * 64 + ty + 8 * u];
#pragma unroll
                for (int s = 0; s < 4; s++) acc2[u][s] += w * xr[s];
            }
        }
#pragma unroll
        for (int u = 0; u < 8; u++) {
            int o = ty + 8 * u;
            float bb = b2s[o];
#pragma unroll
            for (int s = 0; s < 4; s++) {
                int t = tx + 32 * s;
                if (t < 100) op[o * TT + toff + t] = tanhf(acc2[u][s] + bb);
            }
        }
        __syncthreads();
    }
}

// -------------------------------- launch ------------------------------------
#define GETSYM(var, sym)                                       \
    do {                                                       \
        void* _p = nullptr;                                    \
        cudaGetSymbolAddress(&_p, sym);                        \
        var = (decltype(var))_p;                               \
    } while (0)

extern "C" void kernel_launch(void* const* d_in, const int* in_sizes, int n_in,
                              void* d_out, int out_size) {
    (void)in_sizes; (void)n_in; (void)out_size;
    const float* x   = (const float*)d_in[0];
    const int*   ei0 = (const int*)d_in[1];
    const float* ea0 = (const float*)d_in[2];
    const int*   ei1 = (const int*)d_in[3];
    const float* ea1 = (const float*)d_in[4];
    const int*   ei2 = (const int*)d_in[5];
    const float* ea2 = (const float*)d_in[6];
    const float* A1  = (const float*)d_in[7];
    const float* Wk1 = (const float*)d_in[8];
    const float* Wr1 = (const float*)d_in[9];
    const float* b1  = (const float*)d_in[10];
    const float* A2  = (const float*)d_in[11];
    const float* Wk2 = (const float*)d_in[12];
    const float* Wr2 = (const float*)d_in[13];
    const float* b2  = (const float*)d_in[14];
    const float* A3  = (const float*)d_in[15];
    const float* Wk3 = (const float*)d_in[16];
    const float* Wr3 = (const float*)d_in[17];
    const float* b3  = (const float*)d_in[18];
    const float* P01 = (const float*)d_in[19];
    const float* P12 = (const float*)d_in[20];
    const float* P23 = (const float*)d_in[21];
    const float* f1w = (const float*)d_in[22];
    const float* f1b = (const float*)d_in[23];
    const float* f2w = (const float*)d_in[24];
    const float* f2b = (const float*)d_in[25];

    const int N0 = 2048, N1 = 512, N2 = 128, N3 = 64;

    float *p1, *p2, *p3;
    __nv_bfloat16 *A1h, *A1l, *A2h, *A2l, *A3h, *A3l, *Bh, *Bl;
    __nv_bfloat16 *Wt1h, *Wt1l, *Wt2h, *Wt2l;
    int *off0, *perm0, *off1, *perm1, *off2, *perm2;
    float *inv0, *inv1, *inv2;
    GETSYM(p1, g_p1); GETSYM(p2, g_p2); GETSYM(p3, g_p3);
    GETSYM(A1h, g_A1h); GETSYM(A1l, g_A1l);
    GETSYM(A2h, g_A2h); GETSYM(A2l, g_A2l);
    GETSYM(A3h, g_A3h); GETSYM(A3l, g_A3l);
    GETSYM(Bh, g_Bh); GETSYM(Bl, g_Bl);
    GETSYM(Wt1h, g_Wt1h); GETSYM(Wt1l, g_Wt1l);
    GETSYM(Wt2h, g_Wt2h); GETSYM(Wt2l, g_Wt2l);
    GETSYM(off0, g_off0); GETSYM(perm0, g_perm0);
    GETSYM(off1, g_off1); GETSYM(perm1, g_perm1);
    GETSYM(off2, g_off2); GETSYM(perm2, g_perm2);
    GETSYM(inv0, g_inv0); GETSYM(inv1, g_inv1); GETSYM(inv2, g_inv2);

    const int SMEM_GEMM = 98304;
    cudaFuncSetAttribute(mma_gemm_kernel, cudaFuncAttributeMaxDynamicSharedMemorySize,
                         SMEM_GEMM);
    // gcnf1: W 2*1*32*128 + cat 2*64*400 + bias = 59520
    const int SMEM_F1 = 2 * 1 * 32 * 128 + 2 * 64 * 400 + 32 * 4;
    // gcnf2: W 2*2*64*128 + cat 2*128*400 + bias = 135424
    const int SMEM_F2 = 2 * 2 * 64 * 128 + 2 * 128 * 400 + 64 * 4;
    cudaFuncSetAttribute((const void*)gcnf_kernel<16, 32>,
                         cudaFuncAttributeMaxDynamicSharedMemorySize, SMEM_F1);
    cudaFuncSetAttribute((const void*)gcnf_kernel<32, 64>,
                         cudaFuncAttributeMaxDynamicSharedMemorySize, SMEM_F2);
    const int SMEM_HEAD = (8192 + 8192 + 128 + 64 + 12800) * 4;
    cudaFuncSetAttribute(head_kernel, cudaFuncAttributeMaxDynamicSharedMemorySize,
                         SMEM_HEAD);

    // ---- setup: CSR (3 blocks) + splitA + Wt, one launch ----
    const long SPLIT_TOT = 512L * 2048 + 128 * 512 + 128 * 128 + 32 * 64 + 2 * 64 * 64;
    setup_kernel<<<3 + (int)((SPLIT_TOT + 1023) / 1024), 1024>>>(
        ei0, ei1, ei2, off0, perm0, inv0, off1, perm1, inv1, off2, perm2, inv2,
        P01, P12, P23, A1h, A1l, A2h, A2l, A3h, A3l,
        Wk2, Wr2, Wk3, Wr3, Wt1h, Wt1l, Wt2h, Wt2l);

    // ---- level 0->1 GCN ----
    gcn1_kernel<<<N0, 256>>>(x, ea0, A1, Wk1, Wr1, b1, ei0, off0, perm0, inv0, Bh, Bl);

    // ---- pool1: M=512, K=2048, F=3200 ----
    mma_gemm_kernel<<<dim3(3200 / 64, 512 / 128, 2), 256, SMEM_GEMM>>>(
        A1h, A1l, Bh, Bl, p1, 512, 2048, 3200);

    // ---- level 1->2 GCN (tensor-core combine) ----
    gcnf_kernel<16, 32><<<dim3(N1, 2), 256, SMEM_F1>>>(
        p1, ea1, A2, Wt1h, Wt1l, b2, ei1, off1, perm1, inv1, Bh, Bl, N1);

    // ---- pool2: M=128, K=512, F=6400 ----
    mma_gemm_kernel<<<dim3(6400 / 64, 1, 2), 256, SMEM_GEMM>>>(
        A2h, A2l, Bh, Bl, p2, 128, 512, 6400);

    // ---- level 2->3 GCN (tensor-core combine) ----
    gcnf_kernel<32, 64><<<dim3(N2, 2), 256, SMEM_F2>>>(
        p2, ea2, A3, Wt2h, Wt2l, b3, ei2, off2, perm2, inv2, Bh, Bl, N2);

    // ---- pool3: M=64 (padded 128), K=128, F=12800 ----
    mma_gemm_kernel<<<dim3(12800 / 64, 1, 2), 256, SMEM_GEMM>>>(
        A3h, A3l, Bh, Bl, p3, 64, 128, 12800);

    // ---- fused head ----
    head_kernel<<<dim3(N3, 2), 256, SMEM_HEAD>>>(
        p3, f1w, f1b, f2w, f2b, (float*)d_out, N3);
}